// round 8
// baseline (speedup 1.0000x reference)
#include <cuda_runtime.h>
#include <math.h>
#include <stdint.h>

// ---------------------------------------------------------------------------
// LorentzTransformerEncoder  (B=8, N=1024, D=769, H=12, hd=64, M=3072)
// R8 = R7 resubmit (broker infra failure, kernel never ran):
// warp tile 64x64 (CTA 128x128, 128 thr), softmax max-pass removed,
// vtime folded into head_time.
// ---------------------------------------------------------------------------

constexpr int B  = 8;
constexpr int N  = 1024;
constexpr int DS = 768;
constexpr int H  = 12;
constexpr int HD = 64;
constexpr int M_ = 3072;
constexpr int BN = B * N;   // 8192
constexpr int BH = B * H;   // 96

// ------------------------------- scratch -----------------------------------
__device__ float g_h1s [(size_t)BN * DS];
__device__ float g_h1t [BN];
__device__ float g_qs  [(size_t)BN * DS];
__device__ float g_ksp [(size_t)BN * DS];
__device__ float g_vsp [(size_t)BN * DS];
__device__ float g_qt  [BH * N];
__device__ float g_kt  [BH * N];
__device__ float g_vT  [(size_t)BH * 80 * N];   // row 0 time, rows 1..64 space^T
__device__ float g_lt  [(size_t)BH * N * N];
__device__ float g_s   [(size_t)BH * N * 80];
__device__ float g_atns[(size_t)BN * DS];
__device__ float g_atnt[BN];
__device__ float g_out1[(size_t)BN * DS];
__device__ float g_zs  [(size_t)BN * DS];
__device__ float g_zt  [BN];
__device__ float g_hid [(size_t)BN * M_];       // col 3071 stays 0
__device__ float g_hidt[BN];
// tf32 weights (space part, k-major, aligned) + time columns
__device__ float g_wqs [768 * 768];  __device__ float g_wqt [768];
__device__ float g_wks [768 * 768];  __device__ float g_wkt [768];
__device__ float g_wvs [768 * 768];  __device__ float g_wvt [768];
__device__ float g_wos [768 * 768];  __device__ float g_wot [768];
__device__ float g_w1s [3071 * 768]; __device__ float g_w1t [3071];
__device__ float g_w2s [768 * 3072]; __device__ float g_w2t [768];

// ----------------------------- helpers --------------------------------------
__device__ __forceinline__ uint32_t cvt_tf32(float x) {
    uint32_t r;
    asm("cvt.rna.tf32.f32 %0, %1;" : "=r"(r) : "f"(x));
    return r;
}
__device__ __forceinline__ float rnd_tf32(float x) { return __uint_as_float(cvt_tf32(x)); }

__device__ __forceinline__ void ldsm4(uint32_t& r0, uint32_t& r1, uint32_t& r2,
                                      uint32_t& r3, uint32_t addr) {
    asm volatile("ldmatrix.sync.aligned.m8n8.x4.shared.b16 {%0,%1,%2,%3},[%4];"
                 : "=r"(r0), "=r"(r1), "=r"(r2), "=r"(r3) : "r"(addr));
}
__device__ __forceinline__ void mma_tf32(float* c, const uint32_t* a, const uint32_t* b) {
    asm volatile("mma.sync.aligned.m16n8k8.row.col.f32.tf32.tf32.f32 "
                 "{%0,%1,%2,%3},{%4,%5,%6,%7},{%8,%9},{%0,%1,%2,%3};"
                 : "+f"(c[0]), "+f"(c[1]), "+f"(c[2]), "+f"(c[3])
                 : "r"(a[0]), "r"(a[1]), "r"(a[2]), "r"(a[3]), "r"(b[0]), "r"(b[1]));
}
#define CP16(d, s) \
    asm volatile("cp.async.cg.shared.global [%0],[%1],16;" :: "r"(d), "l"(s))
#define CP_COMMIT() asm volatile("cp.async.commit_group;" ::: "memory")
#define CP_WAIT1()  asm volatile("cp.async.wait_group 1;" ::: "memory")

// one pipeline stage: A rows bm..bm+127 (8KB @0), B rows (8KB @8192)
#define ISSUE_STAGE(slot, k0)                                    \
    do {                                                         \
        uint32_t base_ = sbase + (slot) * 16384;                 \
        CP16(base_ + dO[0],        aSrc + (k0));                 \
        CP16(base_ + dO[1],        aSrc + (k0) + 4);             \
        CP16(base_ + dO[2],        aSrc + (k0) + 8);             \
        CP16(base_ + dO[3],        aSrc + (k0) + 12);            \
        CP16(base_ + 8192 + dO[0], bSrc + (k0));                 \
        CP16(base_ + 8192 + dO[1], bSrc + (k0) + 4);             \
        CP16(base_ + 8192 + dO[2], bSrc + (k0) + 8);             \
        CP16(base_ + 8192 + dO[3], bSrc + (k0) + 12);            \
        CP_COMMIT();                                             \
    } while (0)

__device__ __forceinline__ float block_reduce_sum(float v, float* sh) {
    int tid = threadIdx.x, lane = tid & 31, wid = tid >> 5;
    #pragma unroll
    for (int o = 16; o > 0; o >>= 1) v += __shfl_down_sync(0xffffffffu, v, o);
    __syncthreads();
    if (lane == 0) sh[wid] = v;
    __syncthreads();
    if (tid == 0) {
        float s = 0.f;
        #pragma unroll
        for (int w = 0; w < 8; w++) s += sh[w];
        sh[32] = s;
    }
    __syncthreads();
    return sh[32];
}

// ------------------------ weight prep (tf32 + split time) -------------------
__global__ void prep_w(const float* __restrict__ W, float* __restrict__ Ws,
                       float* __restrict__ Wt, int rows, int cols, int kcols, int sld) {
    int idx = blockIdx.x * 256 + threadIdx.x;
    if (idx >= rows * cols) return;
    int n = idx / cols, k = idx - n * cols;
    float v = (k < kcols) ? W[(size_t)(n + 1) * sld + k + 1] : 0.f;
    Ws[idx] = rnd_tf32(v);
    if (k == 0) Wt[n] = W[(size_t)(n + 1) * sld];
}

// ------------------------- Lorentz layernorm --------------------------------
__global__ void ln_kernel(const float* __restrict__ X, int ldx, int xofs,
                          const float* __restrict__ gamma,
                          const float* __restrict__ beta,
                          float* __restrict__ Ys, float* __restrict__ Yt) {
    __shared__ float sh[33];
    int bn = blockIdx.x, tid = threadIdx.x;
    const float* x = X + (size_t)bn * ldx + xofs;
    float v[3], s = 0.f;
    #pragma unroll
    for (int i = 0; i < 3; i++) { v[i] = x[tid + i * 256]; s += v[i]; }
    s = block_reduce_sum(s, sh);
    float mu = s * (1.f / 768.f);
    float s2 = 0.f;
    #pragma unroll
    for (int i = 0; i < 3; i++) { float dd = v[i] - mu; s2 += dd * dd; }
    s2 = block_reduce_sum(s2, sh);
    float rstd = rsqrtf(s2 * (1.f / 768.f) + 1e-5f);
    float t2 = 0.f;
    float* ys = Ys + (size_t)bn * DS;
    #pragma unroll
    for (int i = 0; i < 3; i++) {
        int d = tid + i * 256;
        float yy = gamma[d] * (v[i] - mu) * rstd + beta[d];
        ys[d] = rnd_tf32(yy);
        t2 += yy * yy;
    }
    t2 = block_reduce_sum(t2, sh);
    if (tid == 0) Yt[bn] = sqrtf(1.f + t2);
}

// ------------------------------- tf32 GEMM ----------------------------------
// C[m][n] = sum_k A[m][k] * Bw[n][k]  (+ rank1 tA[m]*tB[n] if RK1)
// EPI: 0 none, 1 gelu, 2 +R, 3 lorentz-logit.  BM: 0 none, 1 head-slice, 2 flat
// CTA 128x128, 128 threads, 4 warps (2m x 2n), warp tile 64x64.
// K%16==0, 3-stage cp.async.
template<int EPI, int BM, bool RK1, bool RND, bool TAILN>
__global__ void __launch_bounds__(128, 2)
mma_gemm(const float* __restrict__ A, int lda, size_t aBatch,
         const float* __restrict__ Bw, int ldb, size_t bBatch,
         float* __restrict__ C, int ldc, int cofs, size_t cBatch,
         const float* __restrict__ R, int ldr, int rofs,
         const float* __restrict__ tA, const float* __restrict__ tB,
         int Nn, int Kk) {
    extern __shared__ float dsm[];
    uint32_t sbase = (uint32_t)__cvta_generic_to_shared(dsm);

    int tid = threadIdx.x;
    int lane = tid & 31, wid = tid >> 5;
    int warpm = wid >> 1, warpn = wid & 1;
    int bm = blockIdx.y << 7, bnb = blockIdx.x << 7;

    const float* Ab = A;
    const float* Bb = Bw;
    const float* tAp = tA;
    const float* tBp = tB;
    float* Cp = C;
    if (BM == 1) {
        int bz = blockIdx.z;
        int b = bz / H, h = bz % H;
        Ab += (size_t)b * N * lda + h * HD;
        Bb += (size_t)b * N * ldb + h * HD;
        tAp = tA + (size_t)bz * N;
        tBp = tB + (size_t)bz * N;
        Cp += (size_t)bz * cBatch;
    }
    if (BM == 2) {
        int bz = blockIdx.z;
        Ab += (size_t)bz * aBatch;
        Bb += (size_t)bz * bBatch;
        Cp += (size_t)bz * cBatch;
    }

    // ---- loader: each thread owns one row (A and B), 4 swizzled 16B chunks --
    int lrow = tid;                       // 0..127
    int xr = (lrow >> 1) & 3;
    uint32_t dO[4];
    #pragma unroll
    for (int c = 0; c < 4; c++) dO[c] = lrow * 64 + ((c ^ xr) << 4);
    const float* aSrc = Ab + (size_t)(bm + lrow) * lda;
    int brow = bnb + lrow;
    int cb = (TAILN && brow >= Nn) ? (Nn - 1) : brow;
    const float* bSrc = Bb + (size_t)cb * ldb;

    // ---- ldmatrix lane addressing ----
    int lrowA = (lane & 7) + ((lane >> 3) & 1) * 8;   // 0..15
    int hiA   = lane >> 4;
    int swA   = (lrowA >> 1) & 3;
    int lrowB = (lane & 7) + ((lane >> 4) & 1) * 8;
    int hiB   = (lane >> 3) & 1;
    int swB   = (lrowB >> 1) & 3;
    uint32_t aOff[2], bOff[2];
    #pragma unroll
    for (int ks = 0; ks < 2; ks++) {
        aOff[ks] = (warpm * 64 + lrowA) * 64 + (((2 * ks + hiA) ^ swA) << 4);
        bOff[ks] = 8192 + (warpn * 64 + lrowB) * 64 + (((2 * ks + hiB) ^ swB) << 4);
    }

    float acc[4][8][4];
    #pragma unroll
    for (int i = 0; i < 4; i++)
        #pragma unroll
        for (int j = 0; j < 8; j++)
            #pragma unroll
            for (int r = 0; r < 4; r++) acc[i][j][r] = 0.f;

    int KT = Kk >> 4;

    ISSUE_STAGE(0, 0);
    ISSUE_STAGE(1, 16);

    for (int kt = 0; kt < KT; kt++) {
        CP_WAIT1();
        __syncthreads();
        int st = kt % 3;
        uint32_t sb = sbase + st * 16384;
        #pragma unroll
        for (int ks = 0; ks < 2; ks++) {
            uint32_t af[4][4];
            uint32_t bf[8][2];
            #pragma unroll
            for (int mt = 0; mt < 4; mt++)
                ldsm4(af[mt][0], af[mt][1], af[mt][2], af[mt][3],
                      sb + aOff[ks] + mt * 1024);
            #pragma unroll
            for (int np = 0; np < 4; np++)
                ldsm4(bf[2 * np][0], bf[2 * np][1], bf[2 * np + 1][0], bf[2 * np + 1][1],
                      sb + bOff[ks] + np * 1024);
            #pragma unroll
            for (int mt = 0; mt < 4; mt++)
                #pragma unroll
                for (int nt = 0; nt < 8; nt++)
                    mma_tf32(acc[mt][nt], af[mt], bf[nt]);
        }
        int nk = kt + 2;
        if (nk < KT) { ISSUE_STAGE(nk % 3, nk << 4); }
        else CP_COMMIT();
    }

    // ------------------------------ epilogue --------------------------------
    int er = bm + warpm * 64 + (lane >> 2);
    int ec0 = bnb + warpn * 64 + 2 * (lane & 3);
    #pragma unroll
    for (int mt = 0; mt < 4; mt++) {
        #pragma unroll
        for (int nt = 0; nt < 8; nt++) {
            #pragma unroll
            for (int half = 0; half < 2; half++) {
                int r = er + mt * 16 + half * 8;
                int c = ec0 + nt * 8;
                bool ok0 = !TAILN || c < Nn;
                bool ok1 = !TAILN || (c + 1) < Nn;
                float v0 = acc[mt][nt][2 * half];
                float v1 = acc[mt][nt][2 * half + 1];
                if (RK1) {
                    float ta = tAp[r];
                    if (ok0) v0 += ta * tBp[c];
                    if (ok1) v1 += ta * tBp[c + 1];
                }
                if (EPI == 1) {
                    float t0 = tanhf(0.7978845608028654f * (v0 + 0.044715f * v0 * v0 * v0));
                    v0 = 0.5f * v0 * (1.f + t0);
                    float t1 = tanhf(0.7978845608028654f * (v1 + 0.044715f * v1 * v1 * v1));
                    v1 = 0.5f * v1 * (1.f + t1);
                }
                if (EPI == 2) {
                    const float* rp = R + (size_t)r * ldr + rofs;
                    if (ok0) v0 += rp[c];
                    if (ok1) v1 += rp[c + 1];
                }
                if (EPI == 3) {
                    float kt_ = tAp[r];
                    float d20 = fmaxf(2.f * (kt_ * tBp[c] - v0 - 1.f), 1e-8f);
                    float d21 = fmaxf(2.f * (kt_ * tBp[ok1 ? c + 1 : c] - v1 - 1.f), 1e-8f);
                    v0 = 1.f / (1.f + log1pf(d20));
                    v1 = 1.f / (1.f + log1pf(d21));
                }
                if (RND) { v0 = rnd_tf32(v0); v1 = rnd_tf32(v1); }
                float* cp = Cp + (size_t)r * ldc + cofs;
                if (ok0) cp[c] = v0;
                if (ok1) cp[c + 1] = v1;
            }
        }
    }
}

// --------- per-head time for Q, K, V (V time -> row 0 of g_vT, tf32) --------
__global__ void head_time_kernel() {
    int idx = blockIdx.x * 256 + threadIdx.x;
    if (idx >= BH * N) return;
    int which = blockIdx.y;
    int i = idx & (N - 1);
    int bh = idx >> 10;
    int h = bh % H, b = bh / H;
    const float* S = (which == 0) ? g_qs : (which == 1) ? g_ksp : g_vsp;
    const float* p = S + (size_t)(b * N + i) * DS + h * HD;
    float s = 1.f;
    #pragma unroll 16
    for (int d = 0; d < HD; d++) s = fmaf(p[d], p[d], s);
    float t = sqrtf(s);
    if (which == 0)      g_qt[idx] = t;
    else if (which == 1) g_kt[idx] = t;
    else                 g_vT[(size_t)bh * 80 * N + i] = rnd_tf32(t);
}

// ------------------ V transpose to [bh][80][N] (rows 1..64) -----------------
__global__ void vT_kernel() {
    __shared__ float tile[32][33];
    int i0 = blockIdx.x << 5, d0 = blockIdx.y << 5, b = blockIdx.z;
    int tx = threadIdx.x, ty = threadIdx.y;
    #pragma unroll
    for (int r = 0; r < 4; r++)
        tile[ty + 8 * r][tx] = g_vsp[(size_t)(b * N + i0 + ty + 8 * r) * DS + d0 + tx];
    __syncthreads();
    #pragma unroll
    for (int r = 0; r < 4; r++) {
        int dg = d0 + ty + 8 * r;
        int h = dg >> 6, dd = dg & 63;
        g_vT[((size_t)(b * H + h) * 80 + 1 + dd) * N + i0 + tx] = tile[tx][ty + 8 * r];
    }
}

// -------------- softmax (no max pass: logits bounded in (0,1]) --------------
__global__ void softmax_kernel() {
    __shared__ float sh[33];
    size_t row = blockIdx.x;
    float* p = g_lt + row * N;
    int tid = threadIdx.x;
    float v[4], s = 0.f;
    #pragma unroll
    for (int i = 0; i < 4; i++) { v[i] = expf(p[tid + i * 256]); s += v[i]; }
    s = block_reduce_sum(s, sh);
    float inv = 1.f / s;
    #pragma unroll
    for (int i = 0; i < 4; i++) p[tid + i * 256] = rnd_tf32(v[i] * inv);
}

// --------- per-head hyperboloid normalize + head-concat + new time ----------
__global__ void assemble_kernel() {
    __shared__ float hsum[12];
    __shared__ float hinv[12];
    __shared__ float cts;
    int bn = blockIdx.x;
    int b = bn >> 10, j = bn & (N - 1);
    int tid = threadIdx.x;
    if (tid < 12) hsum[tid] = 0.f;
    if (tid == 0) cts = 0.f;
    __syncthreads();
    float sv[3];
    #pragma unroll
    for (int r = 0; r < 3; r++) {
        int e = tid + r * 256;
        int h = e >> 6, d = e & 63;
        sv[r] = g_s[((size_t)(b * H + h) * N + j) * 80 + 1 + d];
        atomicAdd(&hsum[h], sv[r] * sv[r]);
    }
    __syncthreads();
    if (tid < 12) {
        float st = g_s[((size_t)(b * H + tid) * N + j) * 80];
        float li = st * st - hsum[tid];
        float inv = rsqrtf(fmaxf(li, 1e-8f));
        hinv[tid] = inv;
        float ct = st * inv;
        atomicAdd(&cts, ct * ct);
    }
    __syncthreads();
    float* os = g_atns + (size_t)bn * DS;
    #pragma unroll
    for (int r = 0; r < 3; r++) {
        int e = tid + r * 256;
        int h = e >> 6;
        os[e] = rnd_tf32(sv[r] * hinv[h]);
    }
    if (tid == 0) g_atnt[bn] = sqrtf(cts - 11.f);
}

// --------------------- FFN hidden time --------------------------------------
__global__ void hid_time_kernel() {
    __shared__ float sh[33];
    int bn = blockIdx.x, tid = threadIdx.x;
    const float* p = g_hid + (size_t)bn * M_;
    float s = 0.f;
    for (int d = tid; d < 3071; d += 256) s = fmaf(p[d], p[d], s);
    s = block_reduce_sum(s, sh);
    if (tid == 0) g_hidt[bn] = sqrtf(1.f + s);
}

// --------------------------- final add_time ---------------------------------
__global__ void final_time_kernel(float* __restrict__ out) {
    __shared__ float sh[33];
    int bn = blockIdx.x, tid = threadIdx.x;
    float* p = out + (size_t)bn * 769;
    float s = 0.f;
    #pragma unroll
    for (int r = 0; r < 3; r++) {
        float v = p[1 + tid + r * 256];
        s = fmaf(v, v, s);
    }
    s = block_reduce_sum(s, sh);
    if (tid == 0) p[0] = sqrtf(1.f + s);
}

// ----------------------------------------------------------------------------
extern "C" void kernel_launch(void* const* d_in, const int* in_sizes, int n_in,
                              void* d_out, int out_size) {
    const float* x      = (const float*)d_in[0];
    const float* gamma1 = (const float*)d_in[1];
    const float* beta1  = (const float*)d_in[2];
    const float* Wq     = (const float*)d_in[3];
    const float* Wk     = (const float*)d_in[4];
    const float* Wv     = (const float*)d_in[5];
    const float* Wo     = (const float*)d_in[6];
    const float* gamma2 = (const float*)d_in[7];
    const float* beta2  = (const float*)d_in[8];
    const float* W1     = (const float*)d_in[9];
    const float* W2     = (const float*)d_in[10];
    float* out = (float*)d_out;

    float *h1s, *h1t, *qs, *ksp, *vsp, *qt, *kt, *vT, *lt, *s_, *atns, *atnt;
    float *out1, *zs, *zt, *hid, *hidt;
    float *wqs, *wqt, *wks, *wkt, *wvs, *wvt, *wos, *wot, *w1s, *w1t, *w2s, *w2t;
    cudaGetSymbolAddress((void**)&h1s,  g_h1s);  cudaGetSymbolAddress((void**)&h1t,  g_h1t);
    cudaGetSymbolAddress((void**)&qs,   g_qs);   cudaGetSymbolAddress((void**)&ksp,  g_ksp);
    cudaGetSymbolAddress((void**)&vsp,  g_vsp);
    cudaGetSymbolAddress((void**)&qt,   g_qt);   cudaGetSymbolAddress((void**)&kt,   g_kt);
    cudaGetSymbolAddress((void**)&vT,   g_vT);   cudaGetSymbolAddress((void**)&lt,   g_lt);
    cudaGetSymbolAddress((void**)&s_,   g_s);
    cudaGetSymbolAddress((void**)&atns, g_atns); cudaGetSymbolAddress((void**)&atnt, g_atnt);
    cudaGetSymbolAddress((void**)&out1, g_out1);
    cudaGetSymbolAddress((void**)&zs,   g_zs);   cudaGetSymbolAddress((void**)&zt,   g_zt);
    cudaGetSymbolAddress((void**)&hid,  g_hid);  cudaGetSymbolAddress((void**)&hidt, g_hidt);
    cudaGetSymbolAddress((void**)&wqs,  g_wqs);  cudaGetSymbolAddress((void**)&wqt,  g_wqt);
    cudaGetSymbolAddress((void**)&wks,  g_wks);  cudaGetSymbolAddress((void**)&wkt,  g_wkt);
    cudaGetSymbolAddress((void**)&wvs,  g_wvs);  cudaGetSymbolAddress((void**)&wvt,  g_wvt);
    cudaGetSymbolAddress((void**)&wos,  g_wos);  cudaGetSymbolAddress((void**)&wot,  g_wot);
    cudaGetSymbolAddress((void**)&w1s,  g_w1s);  cudaGetSymbolAddress((void**)&w1t,  g_w1t);
    cudaGetSymbolAddress((void**)&w2s,  g_w2s);  cudaGetSymbolAddress((void**)&w2t,  g_w2t);

    constexpr int SMB = 49152;   // 3 stages * 16KB
    cudaFuncSetAttribute(mma_gemm<0, 0, true,  true,  false>, cudaFuncAttributeMaxDynamicSharedMemorySize, SMB);
    cudaFuncSetAttribute(mma_gemm<3, 1, false, false, false>, cudaFuncAttributeMaxDynamicSharedMemorySize, SMB);
    cudaFuncSetAttribute(mma_gemm<0, 2, false, false, true>,  cudaFuncAttributeMaxDynamicSharedMemorySize, SMB);
    cudaFuncSetAttribute(mma_gemm<2, 0, true,  false, false>, cudaFuncAttributeMaxDynamicSharedMemorySize, SMB);
    cudaFuncSetAttribute(mma_gemm<1, 0, true,  true,  true>,  cudaFuncAttributeMaxDynamicSharedMemorySize, SMB);

    dim3 t1(256);
    dim3 tg(128);

    // 0) weight prep (tf32-rounded, aligned, time split)
    prep_w<<<(768 * 768 + 255) / 256, t1>>>(Wq, wqs, wqt, 768, 768, 768, 769);
    prep_w<<<(768 * 768 + 255) / 256, t1>>>(Wk, wks, wkt, 768, 768, 768, 769);
    prep_w<<<(768 * 768 + 255) / 256, t1>>>(Wv, wvs, wvt, 768, 768, 768, 769);
    prep_w<<<(768 * 768 + 255) / 256, t1>>>(Wo, wos, wot, 768, 768, 768, 769);
    prep_w<<<(3071 * 768 + 255) / 256, t1>>>(W1, w1s, w1t, 3071, 768, 768, 769);
    prep_w<<<(768 * 3072 + 255) / 256, t1>>>(W2, w2s, w2t, 768, 3072, 3071, 3072);

    // 1) LN1
    ln_kernel<<<BN, t1>>>(x, 769, 1, gamma1, beta1, h1s, h1t);

    // 2) QKV (rank-1 time col, rounded output)
    mma_gemm<0, 0, true, true, false><<<dim3(6, 64), tg, SMB>>>(
        h1s, 768, 0, wqs, 768, 0, qs, 768, 0, 0, nullptr, 0, 0, h1t, wqt, 768, 768);
    mma_gemm<0, 0, true, true, false><<<dim3(6, 64), tg, SMB>>>(
        h1s, 768, 0, wks, 768, 0, ksp, 768, 0, 0, nullptr, 0, 0, h1t, wkt, 768, 768);
    mma_gemm<0, 0, true, true, false><<<dim3(6, 64), tg, SMB>>>(
        h1s, 768, 0, wvs, 768, 0, vsp, 768, 0, 0, nullptr, 0, 0, h1t, wvt, 768, 768);
    head_time_kernel<<<dim3((BH * N + 255) / 256, 3), t1>>>();
    vT_kernel<<<dim3(32, 24, 8), dim3(32, 8)>>>();

    // 3) logits (transposed), softmax, P @ V_cat
    mma_gemm<3, 1, false, false, false><<<dim3(8, 8, BH), tg, SMB>>>(
        ksp, 768, 0, qs, 768, 0, lt, N, 0, (size_t)N * N, nullptr, 0, 0, kt, qt, N, HD);
    softmax_kernel<<<BH * N, t1>>>();
    mma_gemm<0, 2, false, false, true><<<dim3(1, 8, BH), tg, SMB>>>(
        lt, N, (size_t)N * N, vT, N, (size_t)80 * N, s_, 80, 0, (size_t)N * 80,
        nullptr, 0, 0, nullptr, nullptr, 65, N);

    // 4) normalize + concat heads
    assemble_kernel<<<BN, t1>>>();

    // 5) Wo + residual(x)
    mma_gemm<2, 0, true, false, false><<<dim3(6, 64), tg, SMB>>>(
        atns, 768, 0, wos, 768, 0, out1, 768, 0, 0, x, 769, 1, atnt, wot, 768, 768);

    // 6) LN2
    ln_kernel<<<BN, t1>>>(out1, 768, 0, gamma2, beta2, zs, zt);

    // 7) FFN up (gelu, rounded)
    mma_gemm<1, 0, true, true, true><<<dim3(24, 64), tg, SMB>>>(
        zs, 768, 0, w1s, 768, 0, hid, M_, 0, 0, nullptr, 0, 0, zt, w1t, 3071, 768);
    hid_time_kernel<<<BN, t1>>>();

    // 8) FFN down + residual(out1) -> d_out space cols
    mma_gemm<2, 0, true, false, false><<<dim3(6, 64), tg, SMB>>>(
        hid, M_, 0, w2s, M_, 0, out, 769, 1, 0, out1, 768, 0, hidt, w2t, 768, M_);

    // 9) final add_time
    final_time_kernel<<<BN, t1>>>(out);
}

// round 9
// speedup vs baseline: 1.6118x; 1.6118x over previous
#include <cuda_runtime.h>
#include <math.h>
#include <stdint.h>

// ---------------------------------------------------------------------------
// LorentzTransformerEncoder  (B=8, N=1024, D=769, H=12, hd=64, M=3072)
// R9: revert to R6-proven 64x32-warp mainloop; 4-stage cp.async; QKV fused
//     into one batched launch; softmax replaced by exp-in-logits-epilogue +
//     rowsum-reciprocal folded into the av epilogue.
// ---------------------------------------------------------------------------

constexpr int B  = 8;
constexpr int N  = 1024;
constexpr int DS = 768;
constexpr int H  = 12;
constexpr int HD = 64;
constexpr int M_ = 3072;
constexpr int BN = B * N;   // 8192
constexpr int BH = B * H;   // 96

// ------------------------------- scratch -----------------------------------
__device__ float g_h1s [(size_t)BN * DS];
__device__ float g_h1t [BN];
__device__ float g_qkv [(size_t)3 * BN * DS];   // [q|k|v] space, contiguous
__device__ float g_qt  [BH * N];
__device__ float g_kt  [BH * N];
__device__ float g_vT  [(size_t)BH * 80 * N];   // row 0 time, rows 1..64 space^T
__device__ float g_lt  [(size_t)BH * N * N];    // E = exp(logit)
__device__ float g_rs  [BH * N];                // 1 / row-sum of E
__device__ float g_s   [(size_t)BH * N * 80];
__device__ float g_atns[(size_t)BN * DS];
__device__ float g_atnt[BN];
__device__ float g_out1[(size_t)BN * DS];
__device__ float g_zs  [(size_t)BN * DS];
__device__ float g_zt  [BN];
__device__ float g_hid [(size_t)BN * M_];       // col 3071 stays 0
__device__ float g_hidt[BN];
// tf32 weights (space part, k-major, aligned) + time columns
__device__ float g_wqkv [(size_t)3 * 768 * 768];
__device__ float g_wqkvt[3 * 768];
__device__ float g_wos [768 * 768];  __device__ float g_wot [768];
__device__ float g_w1s [3071 * 768]; __device__ float g_w1t [3071];
__device__ float g_w2s [768 * 3072]; __device__ float g_w2t [768];

// ----------------------------- helpers --------------------------------------
__device__ __forceinline__ uint32_t cvt_tf32(float x) {
    uint32_t r;
    asm("cvt.rna.tf32.f32 %0, %1;" : "=r"(r) : "f"(x));
    return r;
}
__device__ __forceinline__ float rnd_tf32(float x) { return __uint_as_float(cvt_tf32(x)); }

__device__ __forceinline__ void ldsm4(uint32_t& r0, uint32_t& r1, uint32_t& r2,
                                      uint32_t& r3, uint32_t addr) {
    asm volatile("ldmatrix.sync.aligned.m8n8.x4.shared.b16 {%0,%1,%2,%3},[%4];"
                 : "=r"(r0), "=r"(r1), "=r"(r2), "=r"(r3) : "r"(addr));
}
__device__ __forceinline__ void mma_tf32(float* c, const uint32_t* a, const uint32_t* b) {
    asm volatile("mma.sync.aligned.m16n8k8.row.col.f32.tf32.tf32.f32 "
                 "{%0,%1,%2,%3},{%4,%5,%6,%7},{%8,%9},{%0,%1,%2,%3};"
                 : "+f"(c[0]), "+f"(c[1]), "+f"(c[2]), "+f"(c[3])
                 : "r"(a[0]), "r"(a[1]), "r"(a[2]), "r"(a[3]), "r"(b[0]), "r"(b[1]));
}
#define CP16(d, s) \
    asm volatile("cp.async.cg.shared.global [%0],[%1],16;" :: "r"(d), "l"(s))
#define CP_COMMIT() asm volatile("cp.async.commit_group;" ::: "memory")
#define CP_WAIT2()  asm volatile("cp.async.wait_group 2;" ::: "memory")

// one pipeline stage: A rows bm..bm+127 (8KB @0), B rows (8KB @8192)
#define ISSUE_STAGE(slot, k0)                                    \
    do {                                                         \
        uint32_t sa_ = sbase + (slot) * 16384 + dOff;            \
        CP16(sa_,         aSrc  + (k0));                         \
        CP16(sa_ + 4096,  aSrc2 + (k0));                         \
        CP16(sa_ + 8192,  bSrc1 + (k0));                         \
        CP16(sa_ + 12288, bSrc2 + (k0));                         \
        CP_COMMIT();                                             \
    } while (0)

__device__ __forceinline__ float block_reduce_sum(float v, float* sh) {
    int tid = threadIdx.x, lane = tid & 31, wid = tid >> 5;
    #pragma unroll
    for (int o = 16; o > 0; o >>= 1) v += __shfl_down_sync(0xffffffffu, v, o);
    __syncthreads();
    if (lane == 0) sh[wid] = v;
    __syncthreads();
    if (tid == 0) {
        float s = 0.f;
        #pragma unroll
        for (int w = 0; w < 8; w++) s += sh[w];
        sh[32] = s;
    }
    __syncthreads();
    return sh[32];
}

// ------------------------ weight prep (tf32 + split time) -------------------
__global__ void prep_w(const float* __restrict__ W, float* __restrict__ Ws,
                       float* __restrict__ Wt, int rows, int cols, int kcols, int sld) {
    int idx = blockIdx.x * 256 + threadIdx.x;
    if (idx >= rows * cols) return;
    int n = idx / cols, k = idx - n * cols;
    float v = (k < kcols) ? W[(size_t)(n + 1) * sld + k + 1] : 0.f;
    Ws[idx] = rnd_tf32(v);
    if (k == 0) Wt[n] = W[(size_t)(n + 1) * sld];
}

// ------------------------- Lorentz layernorm --------------------------------
__global__ void ln_kernel(const float* __restrict__ X, int ldx, int xofs,
                          const float* __restrict__ gamma,
                          const float* __restrict__ beta,
                          float* __restrict__ Ys, float* __restrict__ Yt) {
    __shared__ float sh[33];
    int bn = blockIdx.x, tid = threadIdx.x;
    const float* x = X + (size_t)bn * ldx + xofs;
    float v[3], s = 0.f;
    #pragma unroll
    for (int i = 0; i < 3; i++) { v[i] = x[tid + i * 256]; s += v[i]; }
    s = block_reduce_sum(s, sh);
    float mu = s * (1.f / 768.f);
    float s2 = 0.f;
    #pragma unroll
    for (int i = 0; i < 3; i++) { float dd = v[i] - mu; s2 += dd * dd; }
    s2 = block_reduce_sum(s2, sh);
    float rstd = rsqrtf(s2 * (1.f / 768.f) + 1e-5f);
    float t2 = 0.f;
    float* ys = Ys + (size_t)bn * DS;
    #pragma unroll
    for (int i = 0; i < 3; i++) {
        int d = tid + i * 256;
        float yy = gamma[d] * (v[i] - mu) * rstd + beta[d];
        ys[d] = rnd_tf32(yy);
        t2 += yy * yy;
    }
    t2 = block_reduce_sum(t2, sh);
    if (tid == 0) Yt[bn] = sqrtf(1.f + t2);
}

// ------------------------------- tf32 GEMM ----------------------------------
// C[m][n] = sum_k A[m][k] * Bw[n][k]  (+ rank1 tA[m]*tB[n] if RK1)
// EPI: 0 none, 1 gelu, 2 +R, 3 exp(lorentz-logit), 4 row-scale by tA[m]
// BM : 0 none, 1 head-slice, 2 flat batch (A/B/C/tA/tB strides)
// 128x128 tile, K%16==0 (KT>=3), 4-stage cp.async, 256 thr, 8 warps (2m x 4n).
template<int EPI, int BM, bool RK1, bool RND>
__global__ void __launch_bounds__(256, 2)
mma_gemm(const float* __restrict__ A, int lda, size_t aBatch,
         const float* __restrict__ Bw, int ldb, size_t bBatch,
         float* __restrict__ C, int ldc, int cofs, size_t cBatch,
         const float* __restrict__ R, int ldr, int rofs,
         const float* __restrict__ tA, size_t tABat,
         const float* __restrict__ tB, size_t tBBat,
         int Nn, int Kk) {
    extern __shared__ float dsm[];
    uint32_t sbase = (uint32_t)__cvta_generic_to_shared(dsm);

    int tid = threadIdx.x;
    int lane = tid & 31, wid = tid >> 5;
    int warpm = wid >> 2, warpn = wid & 3;
    int bm = blockIdx.y << 7, bnb = blockIdx.x << 7;

    const float* Ab = A;
    const float* Bb = Bw;
    const float* tAp = tA;
    const float* tBp = tB;
    float* Cp = C;
    if (BM == 1) {
        int bz = blockIdx.z;
        int b = bz / H, h = bz % H;
        Ab += (size_t)b * N * lda + h * HD;
        Bb += (size_t)b * N * ldb + h * HD;
        tAp = tA + (size_t)bz * N;
        tBp = tB + (size_t)bz * N;
        Cp += (size_t)bz * cBatch;
    }
    if (BM == 2) {
        int bz = blockIdx.z;
        Ab += (size_t)bz * aBatch;
        Bb += (size_t)bz * bBatch;
        Cp += (size_t)bz * cBatch;
        tAp = tA + (size_t)bz * tABat;
        tBp = tB + (size_t)bz * tBBat;
    }

    // ---- loader constants: thread -> (row, chunk) pair, rows r and r+64 ----
    int lrow = tid >> 2, lch = tid & 3;
    uint32_t dOff = lrow * 64 + ((lch ^ ((lrow >> 1) & 3)) << 4);  // bytes
    const float* aSrc  = Ab + (size_t)(bm + lrow) * lda + lch * 4;
    const float* aSrc2 = aSrc + (size_t)64 * lda;
    int brow1 = bnb + lrow, brow2 = brow1 + 64;
    bool bok1 = brow1 < Nn, bok2 = brow2 < Nn;
    int cb1 = bok1 ? brow1 : Nn - 1;
    int cb2 = bok2 ? brow2 : Nn - 1;
    const float* bSrc1 = Bb + (size_t)cb1 * ldb + lch * 4;
    const float* bSrc2 = Bb + (size_t)cb2 * ldb + lch * 4;

    // ---- ldmatrix lane addressing ----
    int lrowA = (lane & 7) + ((lane >> 3) & 1) * 8;   // 0..15
    int hiA   = lane >> 4;
    int swA   = (lrowA >> 1) & 3;
    int lrowB = (lane & 7) + ((lane >> 4) & 1) * 8;
    int hiB   = (lane >> 3) & 1;
    int swB   = (lrowB >> 1) & 3;
    uint32_t aOff[2], bOff[2];
    #pragma unroll
    for (int ks = 0; ks < 2; ks++) {
        aOff[ks] = (warpm * 64 + lrowA) * 64 + (((2 * ks + hiA) ^ swA) << 4);
        bOff[ks] = 8192 + (warpn * 32 + lrowB) * 64 + (((2 * ks + hiB) ^ swB) << 4);
    }

    float acc[4][4][4];
    #pragma unroll
    for (int i = 0; i < 4; i++)
        #pragma unroll
        for (int j = 0; j < 4; j++)
            #pragma unroll
            for (int r = 0; r < 4; r++) acc[i][j][r] = 0.f;

    int KT = Kk >> 4;

    ISSUE_STAGE(0, 0);
    ISSUE_STAGE(1, 16);
    ISSUE_STAGE(2, 32);

    for (int kt = 0; kt < KT; kt++) {
        CP_WAIT2();
        __syncthreads();
        int st = kt & 3;
        uint32_t sb = sbase + st * 16384;
        #pragma unroll
        for (int ks = 0; ks < 2; ks++) {
            uint32_t af[4][4];
            uint32_t bf[4][2];
            #pragma unroll
            for (int mt = 0; mt < 4; mt++)
                ldsm4(af[mt][0], af[mt][1], af[mt][2], af[mt][3],
                      sb + aOff[ks] + mt * 1024);
            #pragma unroll
            for (int np = 0; np < 2; np++)
                ldsm4(bf[2 * np][0], bf[2 * np][1], bf[2 * np + 1][0], bf[2 * np + 1][1],
                      sb + bOff[ks] + np * 1024);
            #pragma unroll
            for (int mt = 0; mt < 4; mt++)
                #pragma unroll
                for (int nt = 0; nt < 4; nt++)
                    mma_tf32(acc[mt][nt], af[mt], bf[nt]);
        }
        int nk = kt + 3;
        if (nk < KT) { ISSUE_STAGE(nk & 3, nk << 4); }
        else CP_COMMIT();
    }

    // ------------------------------ epilogue --------------------------------
    int er = bm + warpm * 64 + (lane >> 2);
    int ec0 = bnb + warpn * 32 + 2 * (lane & 3);
    #pragma unroll
    for (int mt = 0; mt < 4; mt++) {
        #pragma unroll
        for (int nt = 0; nt < 4; nt++) {
            #pragma unroll
            for (int half = 0; half < 2; half++) {
                int r = er + mt * 16 + half * 8;
                int c = ec0 + nt * 8;
                bool ok0 = c < Nn, ok1 = (c + 1) < Nn;
                float v0 = acc[mt][nt][2 * half];
                float v1 = acc[mt][nt][2 * half + 1];
                if (RK1) {
                    float ta = tAp[r];
                    if (ok0) v0 += ta * tBp[c];
                    if (ok1) v1 += ta * tBp[c + 1];
                }
                if (EPI == 1) {
                    float t0 = tanhf(0.7978845608028654f * (v0 + 0.044715f * v0 * v0 * v0));
                    v0 = 0.5f * v0 * (1.f + t0);
                    float t1 = tanhf(0.7978845608028654f * (v1 + 0.044715f * v1 * v1 * v1));
                    v1 = 0.5f * v1 * (1.f + t1);
                }
                if (EPI == 2) {
                    const float* rp = R + (size_t)r * ldr + rofs;
                    if (ok0) v0 += rp[c];
                    if (ok1) v1 += rp[c + 1];
                }
                if (EPI == 3) {   // E = exp(1/(1+log1p(d2))), bounded in (1,e]
                    float kt_ = tAp[r];
                    float d20 = fmaxf(2.f * (kt_ * tBp[c] - v0 - 1.f), 1e-8f);
                    float d21 = fmaxf(2.f * (kt_ * tBp[ok1 ? c + 1 : c] - v1 - 1.f), 1e-8f);
                    v0 = expf(1.f / (1.f + log1pf(d20)));
                    v1 = expf(1.f / (1.f + log1pf(d21)));
                }
                if (EPI == 4) {   // row scale (softmax denominator)
                    float sc = tAp[r];
                    v0 *= sc;
                    v1 *= sc;
                }
                if (RND) { v0 = rnd_tf32(v0); v1 = rnd_tf32(v1); }
                float* cp = Cp + (size_t)r * ldc + cofs;
                if (ok0) cp[c] = v0;
                if (ok1) cp[c + 1] = v1;
            }
        }
    }
}

// --------- per-head time for Q, K, V (V time -> row 0 of g_vT, tf32) --------
__global__ void head_time_kernel() {
    int idx = blockIdx.x * 256 + threadIdx.x;
    if (idx >= BH * N) return;
    int which = blockIdx.y;
    int i = idx & (N - 1);
    int bh = idx >> 10;
    int h = bh % H, b = bh / H;
    const float* p = g_qkv + (size_t)which * BN * DS + (size_t)(b * N + i) * DS + h * HD;
    float s = 1.f;
    #pragma unroll 16
    for (int d = 0; d < HD; d++) s = fmaf(p[d], p[d], s);
    float t = sqrtf(s);
    if (which == 0)      g_qt[idx] = t;
    else if (which == 1) g_kt[idx] = t;
    else                 g_vT[(size_t)bh * 80 * N + i] = rnd_tf32(t);
}

// ------------------ V transpose to [bh][80][N] (rows 1..64) -----------------
__global__ void vT_kernel() {
    __shared__ float tile[32][33];
    int i0 = blockIdx.x << 5, d0 = blockIdx.y << 5, b = blockIdx.z;
    int tx = threadIdx.x, ty = threadIdx.y;
    const float* vsp = g_qkv + (size_t)2 * BN * DS;
    #pragma unroll
    for (int r = 0; r < 4; r++)
        tile[ty + 8 * r][tx] = vsp[(size_t)(b * N + i0 + ty + 8 * r) * DS + d0 + tx];
    __syncthreads();
    #pragma unroll
    for (int r = 0; r < 4; r++) {
        int dg = d0 + ty + 8 * r;
        int h = dg >> 6, dd = dg & 63;
        g_vT[((size_t)(b * H + h) * 80 + 1 + dd) * N + i0 + tx] = tile[tx][ty + 8 * r];
    }
}

// -------------- row-sum reciprocal of E (softmax denominator) ---------------
__global__ void rowsum_kernel() {
    __shared__ float sh[33];
    size_t row = blockIdx.x;
    const float* p = g_lt + row * N;
    int tid = threadIdx.x;
    float s = 0.f;
    #pragma unroll
    for (int i = 0; i < 4; i++) s += p[tid + i * 256];
    s = block_reduce_sum(s, sh);
    if (tid == 0) g_rs[row] = 1.f / s;
}

// --------- per-head hyperboloid normalize + head-concat + new time ----------
__global__ void assemble_kernel() {
    __shared__ float hsum[12];
    __shared__ float hinv[12];
    __shared__ float cts;
    int bn = blockIdx.x;
    int b = bn >> 10, j = bn & (N - 1);
    int tid = threadIdx.x;
    if (tid < 12) hsum[tid] = 0.f;
    if (tid == 0) cts = 0.f;
    __syncthreads();
    float sv[3];
    #pragma unroll
    for (int r = 0; r < 3; r++) {
        int e = tid + r * 256;
        int h = e >> 6, d = e & 63;
        sv[r] = g_s[((size_t)(b * H + h) * N + j) * 80 + 1 + d];
        atomicAdd(&hsum[h], sv[r] * sv[r]);
    }
    __syncthreads();
    if (tid < 12) {
        float st = g_s[((size_t)(b * H + tid) * N + j) * 80];
        float li = st * st - hsum[tid];
        float inv = rsqrtf(fmaxf(li, 1e-8f));
        hinv[tid] = inv;
        float ct = st * inv;
        atomicAdd(&cts, ct * ct);
    }
    __syncthreads();
    float* os = g_atns + (size_t)bn * DS;
    #pragma unroll
    for (int r = 0; r < 3; r++) {
        int e = tid + r * 256;
        int h = e >> 6;
        os[e] = rnd_tf32(sv[r] * hinv[h]);
    }
    if (tid == 0) g_atnt[bn] = sqrtf(cts - 11.f);
}

// --------------------- FFN hidden time --------------------------------------
__global__ void hid_time_kernel() {
    __shared__ float sh[33];
    int bn = blockIdx.x, tid = threadIdx.x;
    const float* p = g_hid + (size_t)bn * M_;
    float s = 0.f;
    for (int d = tid; d < 3071; d += 256) s = fmaf(p[d], p[d], s);
    s = block_reduce_sum(s, sh);
    if (tid == 0) g_hidt[bn] = sqrtf(1.f + s);
}

// --------------------------- final add_time ---------------------------------
__global__ void final_time_kernel(float* __restrict__ out) {
    __shared__ float sh[33];
    int bn = blockIdx.x, tid = threadIdx.x;
    float* p = out + (size_t)bn * 769;
    float s = 0.f;
    #pragma unroll
    for (int r = 0; r < 3; r++) {
        float v = p[1 + tid + r * 256];
        s = fmaf(v, v, s);
    }
    s = block_reduce_sum(s, sh);
    if (tid == 0) p[0] = sqrtf(1.f + s);
}

// ----------------------------------------------------------------------------
extern "C" void kernel_launch(void* const* d_in, const int* in_sizes, int n_in,
                              void* d_out, int out_size) {
    const float* x      = (const float*)d_in[0];
    const float* gamma1 = (const float*)d_in[1];
    const float* beta1  = (const float*)d_in[2];
    const float* Wq     = (const float*)d_in[3];
    const float* Wk     = (const float*)d_in[4];
    const float* Wv     = (const float*)d_in[5];
    const float* Wo     = (const float*)d_in[6];
    const float* gamma2 = (const float*)d_in[7];
    const float* beta2  = (const float*)d_in[8];
    const float* W1     = (const float*)d_in[9];
    const float* W2     = (const float*)d_in[10];
    float* out = (float*)d_out;

    float *h1s, *h1t, *qkv, *qt, *kt, *vT, *lt, *rs, *s_, *atns, *atnt;
    float *out1, *zs, *zt, *hid, *hidt;
    float *wqkv, *wqkvt, *wos, *wot, *w1s, *w1t, *w2s, *w2t;
    cudaGetSymbolAddress((void**)&h1s,  g_h1s);  cudaGetSymbolAddress((void**)&h1t,  g_h1t);
    cudaGetSymbolAddress((void**)&qkv,  g_qkv);
    cudaGetSymbolAddress((void**)&qt,   g_qt);   cudaGetSymbolAddress((void**)&kt,   g_kt);
    cudaGetSymbolAddress((void**)&vT,   g_vT);   cudaGetSymbolAddress((void**)&lt,   g_lt);
    cudaGetSymbolAddress((void**)&rs,   g_rs);   cudaGetSymbolAddress((void**)&s_,   g_s);
    cudaGetSymbolAddress((void**)&atns, g_atns); cudaGetSymbolAddress((void**)&atnt, g_atnt);
    cudaGetSymbolAddress((void**)&out1, g_out1);
    cudaGetSymbolAddress((void**)&zs,   g_zs);   cudaGetSymbolAddress((void**)&zt,   g_zt);
    cudaGetSymbolAddress((void**)&hid,  g_hid);  cudaGetSymbolAddress((void**)&hidt, g_hidt);
    cudaGetSymbolAddress((void**)&wqkv, g_wqkv); cudaGetSymbolAddress((void**)&wqkvt, g_wqkvt);
    cudaGetSymbolAddress((void**)&wos,  g_wos);  cudaGetSymbolAddress((void**)&wot,  g_wot);
    cudaGetSymbolAddress((void**)&w1s,  g_w1s);  cudaGetSymbolAddress((void**)&w1t,  g_w1t);
    cudaGetSymbolAddress((void**)&w2s,  g_w2s);  cudaGetSymbolAddress((void**)&w2t,  g_w2t);

    constexpr int SMB = 65536;   // 4 stages * 16KB (opt-in)
    cudaFuncSetAttribute(mma_gemm<0, 2, true,  true>,  cudaFuncAttributeMaxDynamicSharedMemorySize, SMB);
    cudaFuncSetAttribute(mma_gemm<3, 1, false, true>,  cudaFuncAttributeMaxDynamicSharedMemorySize, SMB);
    cudaFuncSetAttribute(mma_gemm<4, 2, false, false>, cudaFuncAttributeMaxDynamicSharedMemorySize, SMB);
    cudaFuncSetAttribute(mma_gemm<2, 0, true,  false>, cudaFuncAttributeMaxDynamicSharedMemorySize, SMB);
    cudaFuncSetAttribute(mma_gemm<1, 0, true,  true>,  cudaFuncAttributeMaxDynamicSharedMemorySize, SMB);

    dim3 t1(256);
    const float* qs  = qkv;
    const float* ksp = qkv + (size_t)BN * DS;

    // 0) weight prep (tf32-rounded, aligned, time split; QKV combined)
    prep_w<<<(768 * 768 + 255) / 256, t1>>>(Wq, wqkv,                 wqkvt,        768, 768, 768, 769);
    prep_w<<<(768 * 768 + 255) / 256, t1>>>(Wk, wqkv + 768 * 768,     wqkvt + 768,  768, 768, 768, 769);
    prep_w<<<(768 * 768 + 255) / 256, t1>>>(Wv, wqkv + 2 * 768 * 768, wqkvt + 1536, 768, 768, 768, 769);
    prep_w<<<(768 * 768 + 255) / 256, t1>>>(Wo, wos, wot, 768, 768, 768, 769);
    prep_w<<<(3071 * 768 + 255) / 256, t1>>>(W1, w1s, w1t, 3071, 768, 768, 769);
    prep_w<<<(768 * 3072 + 255) / 256, t1>>>(W2, w2s, w2t, 768, 3072, 3071, 3072);

    // 1) LN1
    ln_kernel<<<BN, t1>>>(x, 769, 1, gamma1, beta1, h1s, h1t);

    // 2) QKV — single batched launch (grid.z = 3)
    mma_gemm<0, 2, true, true><<<dim3(6, 64, 3), t1, SMB>>>(
        h1s, 768, 0, wqkv, 768, (size_t)768 * 768, qkv, 768, 0, (size_t)BN * DS,
        nullptr, 0, 0, h1t, 0, wqkvt, 768, 768, 768);
    head_time_kernel<<<dim3((BH * N + 255) / 256, 3), t1>>>();
    vT_kernel<<<dim3(32, 24, 8), dim3(32, 8)>>>();

    // 3) E = exp(logits) (per-head), rowsum recip, av with row-scale epilogue
    mma_gemm<3, 1, false, true><<<dim3(8, 8, BH), t1, SMB>>>(
        ksp, 768, 0, qs, 768, 0, lt, N, 0, (size_t)N * N,
        nullptr, 0, 0, kt, 0, qt, 0, N, HD);
    rowsum_kernel<<<BH * N, t1>>>();
    mma_gemm<4, 2, false, false><<<dim3(1, 8, BH), t1, SMB>>>(
        lt, N, (size_t)N * N, vT, N, (size_t)80 * N, s_, 80, 0, (size_t)N * 80,
        nullptr, 0, 0, rs, N, nullptr, 0, 65, N);

    // 4) normalize + concat heads
    assemble_kernel<<<BN, t1>>>();

    // 5) Wo + residual(x)
    mma_gemm<2, 0, true, false><<<dim3(6, 64), t1, SMB>>>(
        atns, 768, 0, wos, 768, 0, out1, 768, 0, 0,
        x, 769, 1, atnt, 0, wot, 0, 768, 768);

    // 6) LN2
    ln_kernel<<<BN, t1>>>(out1, 768, 0, gamma2, beta2, zs, zt);

    // 7) FFN up (gelu, rounded)
    mma_gemm<1, 0, true, true><<<dim3(24, 64), t1, SMB>>>(
        zs, 768, 0, w1s, 768, 0, hid, M_, 0, 0,
        nullptr, 0, 0, zt, 0, w1t, 0, 3071, 768);
    hid_time_kernel<<<BN, t1>>>();

    // 8) FFN down + residual(out1) -> d_out space cols
    mma_gemm<2, 0, true, false><<<dim3(6, 64), t1, SMB>>>(
        hid, M_, 0, w2s, M_, 0, out, 769, 1, 0,
        out1, 768, 0, hidt, 0, w2t, 0, 768, M_);

    // 9) final add_time
    final_time_kernel<<<BN, t1>>>(out);
}

// round 11
// speedup vs baseline: 1.7685x; 1.0972x over previous
#include <cuda_runtime.h>
#include <math.h>
#include <stdint.h>

// ---------------------------------------------------------------------------
// LorentzTransformerEncoder  (B=8, N=1024, D=769, H=12, hd=64, M=3072)
// R11 = R10 with the B-fragment warp offset fixed (warpn*(NT/4), was NT/8):
// fused rowsum/time-dot in logits epilogue, fused |v|^2 in FF1 epilogue,
// 64-wide av tile.
// ---------------------------------------------------------------------------

constexpr int B  = 8;
constexpr int N  = 1024;
constexpr int DS = 768;
constexpr int H  = 12;
constexpr int HD = 64;
constexpr int M_ = 3072;
constexpr int BN = B * N;   // 8192
constexpr int BH = B * H;   // 96

// ------------------------------- scratch -----------------------------------
__device__ float g_h1s [(size_t)BN * DS];
__device__ float g_h1t [BN];
__device__ float g_qkv [(size_t)3 * BN * DS];   // [q|k|v] space, contiguous
__device__ float g_qt  [BH * N];
__device__ float g_kt  [BH * N];
__device__ float g_vT  [(size_t)BH * 80 * N];   // row 0 time, rows 1..64 space^T
__device__ float g_lt  [(size_t)BH * N * N];    // E = exp(logit)
__device__ float g_rsE [BH * N];                // row-sum of E (accumulated)
__device__ float g_rs  [BH * N];                // 1 / row-sum
__device__ float g_st  [BH * N];                // sum E * vt (accumulated)
__device__ float g_s   [(size_t)BH * N * 80];   // space at 1..64 (0 unused)
__device__ float g_atns[(size_t)BN * DS];
__device__ float g_atnt[BN];
__device__ float g_out1[(size_t)BN * DS];
__device__ float g_zs  [(size_t)BN * DS];
__device__ float g_zt  [BN];
__device__ float g_hid [(size_t)BN * M_];       // col 3071 stays 0
__device__ float g_hsq [BN];                    // sum v^2 (accumulated)
__device__ float g_hidt[BN];
// tf32 weights (space part, k-major, aligned) + time columns
__device__ float g_wqkv [(size_t)3 * 768 * 768];
__device__ float g_wqkvt[3 * 768];
__device__ float g_wos [768 * 768];  __device__ float g_wot [768];
__device__ float g_w1s [3071 * 768]; __device__ float g_w1t [3071];
__device__ float g_w2s [768 * 3072]; __device__ float g_w2t [768];

// ----------------------------- helpers --------------------------------------
__device__ __forceinline__ uint32_t cvt_tf32(float x) {
    uint32_t r;
    asm("cvt.rna.tf32.f32 %0, %1;" : "=r"(r) : "f"(x));
    return r;
}
__device__ __forceinline__ float rnd_tf32(float x) { return __uint_as_float(cvt_tf32(x)); }

__device__ __forceinline__ void ldsm4(uint32_t& r0, uint32_t& r1, uint32_t& r2,
                                      uint32_t& r3, uint32_t addr) {
    asm volatile("ldmatrix.sync.aligned.m8n8.x4.shared.b16 {%0,%1,%2,%3},[%4];"
                 : "=r"(r0), "=r"(r1), "=r"(r2), "=r"(r3) : "r"(addr));
}
__device__ __forceinline__ void mma_tf32(float* c, const uint32_t* a, const uint32_t* b) {
    asm volatile("mma.sync.aligned.m16n8k8.row.col.f32.tf32.tf32.f32 "
                 "{%0,%1,%2,%3},{%4,%5,%6,%7},{%8,%9},{%0,%1,%2,%3};"
                 : "+f"(c[0]), "+f"(c[1]), "+f"(c[2]), "+f"(c[3])
                 : "r"(a[0]), "r"(a[1]), "r"(a[2]), "r"(a[3]), "r"(b[0]), "r"(b[1]));
}
#define CP16(d, s) \
    asm volatile("cp.async.cg.shared.global [%0],[%1],16;" :: "r"(d), "l"(s))
#define CP_COMMIT() asm volatile("cp.async.commit_group;" ::: "memory")
#define CP_WAIT2()  asm volatile("cp.async.wait_group 2;" ::: "memory")

// one pipeline stage; NT==64 drops the second B row batch (B is 64 rows)
#define ISSUE_STAGE(slot, k0)                                    \
    do {                                                         \
        uint32_t sa_ = sbase + (slot) * STG + dOff;              \
        CP16(sa_,         aSrc  + (k0));                         \
        CP16(sa_ + 4096,  aSrc2 + (k0));                         \
        CP16(sa_ + 8192,  bSrc1 + (k0));                         \
        if (NT == 128) { CP16(sa_ + 12288, bSrc2 + (k0)); }      \
        CP_COMMIT();                                             \
    } while (0)

__device__ __forceinline__ float block_reduce_sum(float v, float* sh) {
    int tid = threadIdx.x, lane = tid & 31, wid = tid >> 5;
    #pragma unroll
    for (int o = 16; o > 0; o >>= 1) v += __shfl_down_sync(0xffffffffu, v, o);
    __syncthreads();
    if (lane == 0) sh[wid] = v;
    __syncthreads();
    if (tid == 0) {
        float s = 0.f;
        #pragma unroll
        for (int w = 0; w < 8; w++) s += sh[w];
        sh[32] = s;
    }
    __syncthreads();
    return sh[32];
}

// ------------------------ weight prep (tf32 + split time) -------------------
__global__ void prep_w(const float* __restrict__ W, float* __restrict__ Ws,
                       float* __restrict__ Wt, int rows, int cols, int kcols, int sld) {
    int idx = blockIdx.x * 256 + threadIdx.x;
    if (idx >= rows * cols) return;
    int n = idx / cols, k = idx - n * cols;
    float v = (k < kcols) ? W[(size_t)(n + 1) * sld + k + 1] : 0.f;
    Ws[idx] = rnd_tf32(v);
    if (k == 0) Wt[n] = W[(size_t)(n + 1) * sld];
}

// ------------------ zero the atomic accumulators (per launch) ---------------
__global__ void zero_acc() {
    int idx = blockIdx.x * 256 + threadIdx.x;
    if (idx < BH * N) { g_rsE[idx] = 0.f; g_st[idx] = 0.f; }
    else if (idx < BH * N + BN) g_hsq[idx - BH * N] = 0.f;
}

// ------------------------- Lorentz layernorm --------------------------------
__global__ void ln_kernel(const float* __restrict__ X, int ldx, int xofs,
                          const float* __restrict__ gamma,
                          const float* __restrict__ beta,
                          float* __restrict__ Ys, float* __restrict__ Yt) {
    __shared__ float sh[33];
    int bn = blockIdx.x, tid = threadIdx.x;
    const float* x = X + (size_t)bn * ldx + xofs;
    float v[3], s = 0.f;
    #pragma unroll
    for (int i = 0; i < 3; i++) { v[i] = x[tid + i * 256]; s += v[i]; }
    s = block_reduce_sum(s, sh);
    float mu = s * (1.f / 768.f);
    float s2 = 0.f;
    #pragma unroll
    for (int i = 0; i < 3; i++) { float dd = v[i] - mu; s2 += dd * dd; }
    s2 = block_reduce_sum(s2, sh);
    float rstd = rsqrtf(s2 * (1.f / 768.f) + 1e-5f);
    float t2 = 0.f;
    float* ys = Ys + (size_t)bn * DS;
    #pragma unroll
    for (int i = 0; i < 3; i++) {
        int d = tid + i * 256;
        float yy = gamma[d] * (v[i] - mu) * rstd + beta[d];
        ys[d] = rnd_tf32(yy);
        t2 += yy * yy;
    }
    t2 = block_reduce_sum(t2, sh);
    if (tid == 0) Yt[bn] = sqrtf(1.f + t2);
}

// ------------------------------- tf32 GEMM ----------------------------------
// C[m][n] = sum_k A[m][k] * Bw[n][k]  (+ rank1 tA[m]*tB[n] if RK1)
// EPI: 0 none, 1 gelu(+hsq atomics), 2 +R, 3 exp(logit)(+rowsum/time atomics),
//      4 row-scale by tA[m]
// BM : 0 none, 1 head-slice, 2 flat batch.  NT: n-tile width 128 or 64.
// 128xNT tile, K%16==0 (KT>=3), 4-stage cp.async, 256 thr, 8 warps (2m x 4n).
template<int EPI, int BM, bool RK1, bool RND, int NT>
__global__ void __launch_bounds__(256, 2)
mma_gemm(const float* __restrict__ A, int lda, size_t aBatch,
         const float* __restrict__ Bw, int ldb, size_t bBatch,
         float* __restrict__ C, int ldc, int cofs, size_t cBatch,
         const float* __restrict__ R, int ldr, int rofs,
         const float* __restrict__ tA, size_t tABat,
         const float* __restrict__ tB, size_t tBBat,
         float* __restrict__ pS1, float* __restrict__ pS2,
         int Nn, int Kk) {
    constexpr int STG = (NT == 128) ? 16384 : 12288;
    constexpr int NTILES = NT / 32;          // n8-tile pairs per warp
    extern __shared__ float dsm[];
    uint32_t sbase = (uint32_t)__cvta_generic_to_shared(dsm);

    int tid = threadIdx.x;
    int lane = tid & 31, wid = tid >> 5;
    int warpm = wid >> 2, warpn = wid & 3;
    int bm = blockIdx.y << 7, bnb = blockIdx.x * NT;

    const float* Ab = A;
    const float* Bb = Bw;
    const float* tAp = tA;
    const float* tBp = tB;
    const float* Rp = R;
    float* pS1p = pS1;
    float* pS2p = pS2;
    float* Cp = C;
    if (BM == 1) {
        int bz = blockIdx.z;
        int b = bz / H, h = bz % H;
        Ab += (size_t)b * N * lda + h * HD;
        Bb += (size_t)b * N * ldb + h * HD;
        tAp = tA + (size_t)bz * N;
        tBp = tB + (size_t)bz * N;
        Cp += (size_t)bz * cBatch;
        if (EPI == 3) {
            Rp = R + (size_t)bz * ldr;       // vt row (ldr = 80*N)
            pS1p = pS1 + (size_t)bz * N;
            pS2p = pS2 + (size_t)bz * N;
        }
    }
    if (BM == 2) {
        int bz = blockIdx.z;
        Ab += (size_t)bz * aBatch;
        Bb += (size_t)bz * bBatch;
        Cp += (size_t)bz * cBatch;
        tAp = tA + (size_t)bz * tABat;
        tBp = tB + (size_t)bz * tBBat;
    }

    // ---- loader constants ----
    int lrow = tid >> 2, lch = tid & 3;
    uint32_t dOff = lrow * 64 + ((lch ^ ((lrow >> 1) & 3)) << 4);  // bytes
    const float* aSrc  = Ab + (size_t)(bm + lrow) * lda + lch * 4;
    const float* aSrc2 = aSrc + (size_t)64 * lda;
    int brow1 = bnb + lrow, brow2 = brow1 + 64;
    int cb1 = (brow1 < Nn) ? brow1 : Nn - 1;
    int cb2 = (brow2 < Nn) ? brow2 : Nn - 1;
    const float* bSrc1 = Bb + (size_t)cb1 * ldb + lch * 4;
    const float* bSrc2 = Bb + (size_t)cb2 * ldb + lch * 4;

    // ---- ldmatrix lane addressing ----
    int lrowA = (lane & 7) + ((lane >> 3) & 1) * 8;
    int hiA   = lane >> 4;
    int swA   = (lrowA >> 1) & 3;
    int lrowB = (lane & 7) + ((lane >> 4) & 1) * 8;
    int hiB   = (lane >> 3) & 1;
    int swB   = (lrowB >> 1) & 3;
    uint32_t aOff[2], bOff[2];
    #pragma unroll
    for (int ks = 0; ks < 2; ks++) {
        aOff[ks] = (warpm * 64 + lrowA) * 64 + (((2 * ks + hiA) ^ swA) << 4);
        bOff[ks] = 8192 + (warpn * (NT / 4) + lrowB) * 64 + (((2 * ks + hiB) ^ swB) << 4);
    }

    float acc[4][NTILES][4];
    #pragma unroll
    for (int i = 0; i < 4; i++)
        #pragma unroll
        for (int j = 0; j < NTILES; j++)
            #pragma unroll
            for (int r = 0; r < 4; r++) acc[i][j][r] = 0.f;

    int KT = Kk >> 4;

    ISSUE_STAGE(0, 0);
    ISSUE_STAGE(1, 16);
    ISSUE_STAGE(2, 32);

    for (int kt = 0; kt < KT; kt++) {
        CP_WAIT2();
        __syncthreads();
        int st = kt & 3;
        uint32_t sb = sbase + st * STG;
        #pragma unroll
        for (int ks = 0; ks < 2; ks++) {
            uint32_t af[4][4];
            uint32_t bf[NTILES][2];
            #pragma unroll
            for (int mt = 0; mt < 4; mt++)
                ldsm4(af[mt][0], af[mt][1], af[mt][2], af[mt][3],
                      sb + aOff[ks] + mt * 1024);
            #pragma unroll
            for (int np = 0; np < NTILES / 2; np++)
                ldsm4(bf[2 * np][0], bf[2 * np][1], bf[2 * np + 1][0], bf[2 * np + 1][1],
                      sb + bOff[ks] + np * 1024);
            #pragma unroll
            for (int mt = 0; mt < 4; mt++)
                #pragma unroll
                for (int nt = 0; nt < NTILES; nt++)
                    mma_tf32(acc[mt][nt], af[mt], bf[nt]);
        }
        int nk = kt + 3;
        if (nk < KT) { ISSUE_STAGE(nk & 3, nk << 4); }
        else CP_COMMIT();
    }

    // ------------------------------ epilogue --------------------------------
    int er = bm + warpm * 64 + (lane >> 2);
    int ec0 = bnb + warpn * (NT / 4) + 2 * (lane & 3);
    float sumE[4][2], sumT[4][2], sumQ[4][2];
    if (EPI == 3 || EPI == 1) {
        #pragma unroll
        for (int i = 0; i < 4; i++)
            #pragma unroll
            for (int j = 0; j < 2; j++) { sumE[i][j] = 0.f; sumT[i][j] = 0.f; sumQ[i][j] = 0.f; }
    }
    #pragma unroll
    for (int mt = 0; mt < 4; mt++) {
        #pragma unroll
        for (int nt = 0; nt < NTILES; nt++) {
            #pragma unroll
            for (int half = 0; half < 2; half++) {
                int r = er + mt * 16 + half * 8;
                int c = ec0 + nt * 8;
                bool ok0 = c < Nn, ok1 = (c + 1) < Nn;
                float v0 = acc[mt][nt][2 * half];
                float v1 = acc[mt][nt][2 * half + 1];
                if (RK1) {
                    float ta = tAp[r];
                    if (ok0) v0 += ta * tBp[c];
                    if (ok1) v1 += ta * tBp[c + 1];
                }
                if (EPI == 1) {
                    float t0 = tanhf(0.7978845608028654f * (v0 + 0.044715f * v0 * v0 * v0));
                    v0 = 0.5f * v0 * (1.f + t0);
                    float t1 = tanhf(0.7978845608028654f * (v1 + 0.044715f * v1 * v1 * v1));
                    v1 = 0.5f * v1 * (1.f + t1);
                    if (ok0) sumQ[mt][half] = fmaf(v0, v0, sumQ[mt][half]);
                    if (ok1) sumQ[mt][half] = fmaf(v1, v1, sumQ[mt][half]);
                }
                if (EPI == 2) {
                    const float* rp = R + (size_t)r * ldr + rofs;
                    if (ok0) v0 += rp[c];
                    if (ok1) v1 += rp[c + 1];
                }
                if (EPI == 3) {   // E = exp(1/(1+log1p(d2))) in (1,e]
                    float kt_ = tAp[r];
                    float d20 = fmaxf(2.f * (kt_ * tBp[c] - v0 - 1.f), 1e-8f);
                    float d21 = fmaxf(2.f * (kt_ * tBp[c + 1] - v1 - 1.f), 1e-8f);
                    v0 = rnd_tf32(expf(1.f / (1.f + log1pf(d20))));
                    v1 = rnd_tf32(expf(1.f / (1.f + log1pf(d21))));
                    sumE[mt][half] += v0 + v1;
                    sumT[mt][half] = fmaf(v0, Rp[c], sumT[mt][half]);
                    sumT[mt][half] = fmaf(v1, Rp[c + 1], sumT[mt][half]);
                }
                if (EPI == 4) {
                    float sc = tAp[r];
                    v0 *= sc;
                    v1 *= sc;
                }
                if (RND && EPI != 3) { v0 = rnd_tf32(v0); v1 = rnd_tf32(v1); }
                float* cp = Cp + (size_t)r * ldc + cofs;
                if (ok0) cp[c] = v0;
                if (ok1) cp[c + 1] = v1;
            }
        }
    }
    if (EPI == 3) {
        #pragma unroll
        for (int mt = 0; mt < 4; mt++)
            #pragma unroll
            for (int half = 0; half < 2; half++) {
                float vE = sumE[mt][half], vT = sumT[mt][half];
                vE += __shfl_down_sync(0xffffffffu, vE, 1, 4);
                vE += __shfl_down_sync(0xffffffffu, vE, 2, 4);
                vT += __shfl_down_sync(0xffffffffu, vT, 1, 4);
                vT += __shfl_down_sync(0xffffffffu, vT, 2, 4);
                if ((lane & 3) == 0) {
                    int r = er + mt * 16 + half * 8;
                    atomicAdd(&pS1p[r], vE);
                    atomicAdd(&pS2p[r], vT);
                }
            }
    }
    if (EPI == 1) {
        #pragma unroll
        for (int mt = 0; mt < 4; mt++)
            #pragma unroll
            for (int half = 0; half < 2; half++) {
                float vQ = sumQ[mt][half];
                vQ += __shfl_down_sync(0xffffffffu, vQ, 1, 4);
                vQ += __shfl_down_sync(0xffffffffu, vQ, 2, 4);
                if ((lane & 3) == 0) {
                    int r = er + mt * 16 + half * 8;
                    atomicAdd(&pS1p[r], vQ);
                }
            }
    }
}

// --------- per-head time for Q, K, V (V time -> row 0 of g_vT, tf32) --------
__global__ void head_time_kernel() {
    int idx = blockIdx.x * 256 + threadIdx.x;
    if (idx >= BH * N) return;
    int which = blockIdx.y;
    int i = idx & (N - 1);
    int bh = idx >> 10;
    int h = bh % H, b = bh / H;
    const float* p = g_qkv + (size_t)which * BN * DS + (size_t)(b * N + i) * DS + h * HD;
    float s = 1.f;
    #pragma unroll 16
    for (int d = 0; d < HD; d++) s = fmaf(p[d], p[d], s);
    float t = sqrtf(s);
    if (which == 0)      g_qt[idx] = t;
    else if (which == 1) g_kt[idx] = t;
    else                 g_vT[(size_t)bh * 80 * N + i] = rnd_tf32(t);
}

// ------------------ V transpose to [bh][80][N] (rows 1..64) -----------------
__global__ void vT_kernel() {
    __shared__ float tile[32][33];
    int i0 = blockIdx.x << 5, d0 = blockIdx.y << 5, b = blockIdx.z;
    int tx = threadIdx.x, ty = threadIdx.y;
    const float* vsp = g_qkv + (size_t)2 * BN * DS;
    #pragma unroll
    for (int r = 0; r < 4; r++)
        tile[ty + 8 * r][tx] = vsp[(size_t)(b * N + i0 + ty + 8 * r) * DS + d0 + tx];
    __syncthreads();
    #pragma unroll
    for (int r = 0; r < 4; r++) {
        int dg = d0 + ty + 8 * r;
        int h = dg >> 6, dd = dg & 63;
        g_vT[((size_t)(b * H + h) * 80 + 1 + dd) * N + i0 + tx] = tile[tx][ty + 8 * r];
    }
}

// -------------------- reciprocal of accumulated row sums --------------------
__global__ void recip_kernel() {
    int idx = blockIdx.x * 256 + threadIdx.x;
    if (idx < BH * N) g_rs[idx] = 1.f / g_rsE[idx];
}

// ----------------------- hidt = sqrt(1 + sum v^2) ---------------------------
__global__ void hidt_kernel() {
    int idx = blockIdx.x * 256 + threadIdx.x;
    if (idx < BN) g_hidt[idx] = sqrtf(1.f + g_hsq[idx]);
}

// --------- per-head hyperboloid normalize + head-concat + new time ----------
__global__ void assemble_kernel() {
    __shared__ float hsum[12];
    __shared__ float hinv[12];
    __shared__ float cts;
    int bn = blockIdx.x;
    int b = bn >> 10, j = bn & (N - 1);
    int tid = threadIdx.x;
    if (tid < 12) hsum[tid] = 0.f;
    if (tid == 0) cts = 0.f;
    __syncthreads();
    float sv[3];
    #pragma unroll
    for (int r = 0; r < 3; r++) {
        int e = tid + r * 256;
        int h = e >> 6, d = e & 63;
        sv[r] = g_s[((size_t)(b * H + h) * N + j) * 80 + 1 + d];
        atomicAdd(&hsum[h], sv[r] * sv[r]);
    }
    __syncthreads();
    if (tid < 12) {
        int row = (b * H + tid) * N + j;
        float st = g_st[row] * g_rs[row];
        float li = st * st - hsum[tid];
        float inv = rsqrtf(fmaxf(li, 1e-8f));
        hinv[tid] = inv;
        float ct = st * inv;
        atomicAdd(&cts, ct * ct);
    }
    __syncthreads();
    float* os = g_atns + (size_t)bn * DS;
    #pragma unroll
    for (int r = 0; r < 3; r++) {
        int e = tid + r * 256;
        int h = e >> 6;
        os[e] = rnd_tf32(sv[r] * hinv[h]);
    }
    if (tid == 0) g_atnt[bn] = sqrtf(cts - 11.f);
}

// --------------------------- final add_time ---------------------------------
__global__ void final_time_kernel(float* __restrict__ out) {
    __shared__ float sh[33];
    int bn = blockIdx.x, tid = threadIdx.x;
    float* p = out + (size_t)bn * 769;
    float s = 0.f;
    #pragma unroll
    for (int r = 0; r < 3; r++) {
        float v = p[1 + tid + r * 256];
        s = fmaf(v, v, s);
    }
    s = block_reduce_sum(s, sh);
    if (tid == 0) p[0] = sqrtf(1.f + s);
}

// ----------------------------------------------------------------------------
extern "C" void kernel_launch(void* const* d_in, const int* in_sizes, int n_in,
                              void* d_out, int out_size) {
    const float* x      = (const float*)d_in[0];
    const float* gamma1 = (const float*)d_in[1];
    const float* beta1  = (const float*)d_in[2];
    const float* Wq     = (const float*)d_in[3];
    const float* Wk     = (const float*)d_in[4];
    const float* Wv     = (const float*)d_in[5];
    const float* Wo     = (const float*)d_in[6];
    const float* gamma2 = (const float*)d_in[7];
    const float* beta2  = (const float*)d_in[8];
    const float* W1     = (const float*)d_in[9];
    const float* W2     = (const float*)d_in[10];
    float* out = (float*)d_out;

    float *h1s, *h1t, *qkv, *qt, *kt, *vT, *lt, *rsE, *rs, *st, *s_;
    float *atns, *atnt, *out1, *zs, *zt, *hid, *hsq, *hidt;
    float *wqkv, *wqkvt, *wos, *wot, *w1s, *w1t, *w2s, *w2t;
    cudaGetSymbolAddress((void**)&h1s,  g_h1s);  cudaGetSymbolAddress((void**)&h1t,  g_h1t);
    cudaGetSymbolAddress((void**)&qkv,  g_qkv);
    cudaGetSymbolAddress((void**)&qt,   g_qt);   cudaGetSymbolAddress((void**)&kt,   g_kt);
    cudaGetSymbolAddress((void**)&vT,   g_vT);   cudaGetSymbolAddress((void**)&lt,   g_lt);
    cudaGetSymbolAddress((void**)&rsE,  g_rsE);  cudaGetSymbolAddress((void**)&rs,   g_rs);
    cudaGetSymbolAddress((void**)&st,   g_st);   cudaGetSymbolAddress((void**)&s_,   g_s);
    cudaGetSymbolAddress((void**)&atns, g_atns); cudaGetSymbolAddress((void**)&atnt, g_atnt);
    cudaGetSymbolAddress((void**)&out1, g_out1);
    cudaGetSymbolAddress((void**)&zs,   g_zs);   cudaGetSymbolAddress((void**)&zt,   g_zt);
    cudaGetSymbolAddress((void**)&hid,  g_hid);  cudaGetSymbolAddress((void**)&hsq,  g_hsq);
    cudaGetSymbolAddress((void**)&hidt, g_hidt);
    cudaGetSymbolAddress((void**)&wqkv, g_wqkv); cudaGetSymbolAddress((void**)&wqkvt, g_wqkvt);
    cudaGetSymbolAddress((void**)&wos,  g_wos);  cudaGetSymbolAddress((void**)&wot,  g_wot);
    cudaGetSymbolAddress((void**)&w1s,  g_w1s);  cudaGetSymbolAddress((void**)&w1t,  g_w1t);
    cudaGetSymbolAddress((void**)&w2s,  g_w2s);  cudaGetSymbolAddress((void**)&w2t,  g_w2t);

    constexpr int SMB128 = 65536;   // 4 stages * 16KB
    constexpr int SMB64  = 49152;   // 4 stages * 12KB
    cudaFuncSetAttribute(mma_gemm<0, 2, true,  true,  128>, cudaFuncAttributeMaxDynamicSharedMemorySize, SMB128);
    cudaFuncSetAttribute(mma_gemm<3, 1, false, true,  128>, cudaFuncAttributeMaxDynamicSharedMemorySize, SMB128);
    cudaFuncSetAttribute(mma_gemm<4, 2, false, false, 64>,  cudaFuncAttributeMaxDynamicSharedMemorySize, SMB64);
    cudaFuncSetAttribute(mma_gemm<2, 0, true,  false, 128>, cudaFuncAttributeMaxDynamicSharedMemorySize, SMB128);
    cudaFuncSetAttribute(mma_gemm<1, 0, true,  true,  128>, cudaFuncAttributeMaxDynamicSharedMemorySize, SMB128);

    dim3 t1(256);
    const float* qs  = qkv;
    const float* ksp = qkv + (size_t)BN * DS;

    // 0) weight prep + accumulator zero
    prep_w<<<(768 * 768 + 255) / 256, t1>>>(Wq, wqkv,                 wqkvt,        768, 768, 768, 769);
    prep_w<<<(768 * 768 + 255) / 256, t1>>>(Wk, wqkv + 768 * 768,     wqkvt + 768,  768, 768, 768, 769);
    prep_w<<<(768 * 768 + 255) / 256, t1>>>(Wv, wqkv + 2 * 768 * 768, wqkvt + 1536, 768, 768, 768, 769);
    prep_w<<<(768 * 768 + 255) / 256, t1>>>(Wo, wos, wot, 768, 768, 768, 769);
    prep_w<<<(3071 * 768 + 255) / 256, t1>>>(W1, w1s, w1t, 3071, 768, 768, 769);
    prep_w<<<(768 * 3072 + 255) / 256, t1>>>(W2, w2s, w2t, 768, 3072, 3071, 3072);
    zero_acc<<<(BH * N + BN + 255) / 256, t1>>>();

    // 1) LN1
    ln_kernel<<<BN, t1>>>(x, 769, 1, gamma1, beta1, h1s, h1t);

    // 2) QKV — single batched launch (grid.z = 3)
    mma_gemm<0, 2, true, true, 128><<<dim3(6, 64, 3), t1, SMB128>>>(
        h1s, 768, 0, wqkv, 768, (size_t)768 * 768, qkv, 768, 0, (size_t)BN * DS,
        nullptr, 0, 0, h1t, 0, wqkvt, 768, nullptr, nullptr, 768, 768);
    head_time_kernel<<<dim3((BH * N + 255) / 256, 3), t1>>>();
    vT_kernel<<<dim3(32, 24, 8), dim3(32, 8)>>>();

    // 3) E=exp(logits) + fused rowsum/time-dot; recip; av (64-wide, row-scaled)
    mma_gemm<3, 1, false, true, 128><<<dim3(8, 8, BH), t1, SMB128>>>(
        ksp, 768, 0, qs, 768, 0, lt, N, 0, (size_t)N * N,
        vT, 80 * N, 0, kt, 0, qt, 0, rsE, st, N, HD);
    recip_kernel<<<(BH * N + 255) / 256, t1>>>();
    mma_gemm<4, 2, false, false, 64><<<dim3(1, 8, BH), t1, SMB64>>>(
        lt, N, (size_t)N * N, vT + N, N, (size_t)80 * N, s_, 80, 1, (size_t)N * 80,
        nullptr, 0, 0, rs, N, nullptr, 0, nullptr, nullptr, 64, N);

    // 4) normalize + concat heads (time from st*rs)
    assemble_kernel<<<BN, t1>>>();

    // 5) Wo + residual(x)
    mma_gemm<2, 0, true, false, 128><<<dim3(6, 64), t1, SMB128>>>(
        atns, 768, 0, wos, 768, 0, out1, 768, 0, 0,
        x, 769, 1, atnt, 0, wot, 0, nullptr, nullptr, 768, 768);

    // 6) LN2
    ln_kernel<<<BN, t1>>>(out1, 768, 0, gamma2, beta2, zs, zt);

    // 7) FFN up (gelu + fused |v|^2 atomics), then hidt
    mma_gemm<1, 0, true, true, 128><<<dim3(24, 64), t1, SMB128>>>(
        zs, 768, 0, w1s, 768, 0, hid, M_, 0, 0,
        nullptr, 0, 0, zt, 0, w1t, 0, hsq, nullptr, 3071, 768);
    hidt_kernel<<<(BN + 255) / 256, t1>>>();

    // 8) FFN down + residual(out1) -> d_out space cols
    mma_gemm<2, 0, true, false, 128><<<dim3(6, 64), t1, SMB128>>>(
        hid, M_, 0, w2s, M_, 0, out, 769, 1, 0,
        out1, 768, 0, hidt, 0, w2t, 0, nullptr, nullptr, 768, M_);

    // 9) final add_time
    final_time_kernel<<<BN, t1>>>(out);
}

// round 12
// speedup vs baseline: 1.8710x; 1.0580x over previous
#include <cuda_runtime.h>
#include <math.h>
#include <stdint.h>

// ---------------------------------------------------------------------------
// LorentzTransformerEncoder  (B=8, N=1024, D=769, H=12, hd=64, M=3072)
// R12 = R11 + fast-math intrinsics in epilogues (__expf/__logf/__fdividef),
//       streaming stores for the E matrix, recip kernel folded into av.
// ---------------------------------------------------------------------------

constexpr int B  = 8;
constexpr int N  = 1024;
constexpr int DS = 768;
constexpr int H  = 12;
constexpr int HD = 64;
constexpr int M_ = 3072;
constexpr int BN = B * N;   // 8192
constexpr int BH = B * H;   // 96

// ------------------------------- scratch -----------------------------------
__device__ float g_h1s [(size_t)BN * DS];
__device__ float g_h1t [BN];
__device__ float g_qkv [(size_t)3 * BN * DS];   // [q|k|v] space, contiguous
__device__ float g_qt  [BH * N];
__device__ float g_kt  [BH * N];
__device__ float g_vT  [(size_t)BH * 80 * N];   // row 0 time, rows 1..64 space^T
__device__ float g_lt  [(size_t)BH * N * N];    // E = exp(logit)
__device__ float g_rsE [BH * N];                // row-sum of E (accumulated)
__device__ float g_st  [BH * N];                // sum E * vt (accumulated)
__device__ float g_s   [(size_t)BH * N * 80];   // space at 1..64 (0 unused)
__device__ float g_atns[(size_t)BN * DS];
__device__ float g_atnt[BN];
__device__ float g_out1[(size_t)BN * DS];
__device__ float g_zs  [(size_t)BN * DS];
__device__ float g_zt  [BN];
__device__ float g_hid [(size_t)BN * M_];       // col 3071 stays 0
__device__ float g_hsq [BN];                    // sum v^2 (accumulated)
__device__ float g_hidt[BN];
// tf32 weights (space part, k-major, aligned) + time columns
__device__ float g_wqkv [(size_t)3 * 768 * 768];
__device__ float g_wqkvt[3 * 768];
__device__ float g_wos [768 * 768];  __device__ float g_wot [768];
__device__ float g_w1s [3071 * 768]; __device__ float g_w1t [3071];
__device__ float g_w2s [768 * 3072]; __device__ float g_w2t [768];

// ----------------------------- helpers --------------------------------------
__device__ __forceinline__ uint32_t cvt_tf32(float x) {
    uint32_t r;
    asm("cvt.rna.tf32.f32 %0, %1;" : "=r"(r) : "f"(x));
    return r;
}
__device__ __forceinline__ float rnd_tf32(float x) { return __uint_as_float(cvt_tf32(x)); }

__device__ __forceinline__ void ldsm4(uint32_t& r0, uint32_t& r1, uint32_t& r2,
                                      uint32_t& r3, uint32_t addr) {
    asm volatile("ldmatrix.sync.aligned.m8n8.x4.shared.b16 {%0,%1,%2,%3},[%4];"
                 : "=r"(r0), "=r"(r1), "=r"(r2), "=r"(r3) : "r"(addr));
}
__device__ __forceinline__ void mma_tf32(float* c, const uint32_t* a, const uint32_t* b) {
    asm volatile("mma.sync.aligned.m16n8k8.row.col.f32.tf32.tf32.f32 "
                 "{%0,%1,%2,%3},{%4,%5,%6,%7},{%8,%9},{%0,%1,%2,%3};"
                 : "+f"(c[0]), "+f"(c[1]), "+f"(c[2]), "+f"(c[3])
                 : "r"(a[0]), "r"(a[1]), "r"(a[2]), "r"(a[3]), "r"(b[0]), "r"(b[1]));
}
#define CP16(d, s) \
    asm volatile("cp.async.cg.shared.global [%0],[%1],16;" :: "r"(d), "l"(s))
#define CP_COMMIT() asm volatile("cp.async.commit_group;" ::: "memory")
#define CP_WAIT2()  asm volatile("cp.async.wait_group 2;" ::: "memory")

// fast tanh via exp (robust at both tails)
__device__ __forceinline__ float fast_tanh(float a) {
    float e2 = __expf(2.f * a);
    return __fdividef(e2 - 1.f, e2 + 1.f);
}

// one pipeline stage; NT==64 drops the second B row batch (B is 64 rows)
#define ISSUE_STAGE(slot, k0)                                    \
    do {                                                         \
        uint32_t sa_ = sbase + (slot) * STG + dOff;              \
        CP16(sa_,         aSrc  + (k0));                         \
        CP16(sa_ + 4096,  aSrc2 + (k0));                         \
        CP16(sa_ + 8192,  bSrc1 + (k0));                         \
        if (NT == 128) { CP16(sa_ + 12288, bSrc2 + (k0)); }      \
        CP_COMMIT();                                             \
    } while (0)

__device__ __forceinline__ float block_reduce_sum(float v, float* sh) {
    int tid = threadIdx.x, lane = tid & 31, wid = tid >> 5;
    #pragma unroll
    for (int o = 16; o > 0; o >>= 1) v += __shfl_down_sync(0xffffffffu, v, o);
    __syncthreads();
    if (lane == 0) sh[wid] = v;
    __syncthreads();
    if (tid == 0) {
        float s = 0.f;
        #pragma unroll
        for (int w = 0; w < 8; w++) s += sh[w];
        sh[32] = s;
    }
    __syncthreads();
    return sh[32];
}

// ------------------------ weight prep (tf32 + split time) -------------------
__global__ void prep_w(const float* __restrict__ W, float* __restrict__ Ws,
                       float* __restrict__ Wt, int rows, int cols, int kcols, int sld) {
    int idx = blockIdx.x * 256 + threadIdx.x;
    if (idx >= rows * cols) return;
    int n = idx / cols, k = idx - n * cols;
    float v = (k < kcols) ? W[(size_t)(n + 1) * sld + k + 1] : 0.f;
    Ws[idx] = rnd_tf32(v);
    if (k == 0) Wt[n] = W[(size_t)(n + 1) * sld];
}

// ------------------ zero the atomic accumulators (per launch) ---------------
__global__ void zero_acc() {
    int idx = blockIdx.x * 256 + threadIdx.x;
    if (idx < BH * N) { g_rsE[idx] = 0.f; g_st[idx] = 0.f; }
    else if (idx < BH * N + BN) g_hsq[idx - BH * N] = 0.f;
}

// ------------------------- Lorentz layernorm --------------------------------
__global__ void ln_kernel(const float* __restrict__ X, int ldx, int xofs,
                          const float* __restrict__ gamma,
                          const float* __restrict__ beta,
                          float* __restrict__ Ys, float* __restrict__ Yt) {
    __shared__ float sh[33];
    int bn = blockIdx.x, tid = threadIdx.x;
    const float* x = X + (size_t)bn * ldx + xofs;
    float v[3], s = 0.f;
    #pragma unroll
    for (int i = 0; i < 3; i++) { v[i] = x[tid + i * 256]; s += v[i]; }
    s = block_reduce_sum(s, sh);
    float mu = s * (1.f / 768.f);
    float s2 = 0.f;
    #pragma unroll
    for (int i = 0; i < 3; i++) { float dd = v[i] - mu; s2 += dd * dd; }
    s2 = block_reduce_sum(s2, sh);
    float rstd = rsqrtf(s2 * (1.f / 768.f) + 1e-5f);
    float t2 = 0.f;
    float* ys = Ys + (size_t)bn * DS;
    #pragma unroll
    for (int i = 0; i < 3; i++) {
        int d = tid + i * 256;
        float yy = gamma[d] * (v[i] - mu) * rstd + beta[d];
        ys[d] = rnd_tf32(yy);
        t2 += yy * yy;
    }
    t2 = block_reduce_sum(t2, sh);
    if (tid == 0) Yt[bn] = sqrtf(1.f + t2);
}

// ------------------------------- tf32 GEMM ----------------------------------
// C[m][n] = sum_k A[m][k] * Bw[n][k]  (+ rank1 tA[m]*tB[n] if RK1)
// EPI: 0 none, 1 gelu(+hsq atomics), 2 +R, 3 exp(logit)(+rowsum/time atomics),
//      4 row-scale by 1/tA[m]
// BM : 0 none, 1 head-slice, 2 flat batch.  NT: n-tile width 128 or 64.
// 128xNT tile, K%16==0 (KT>=3), 4-stage cp.async, 256 thr, 8 warps (2m x 4n).
template<int EPI, int BM, bool RK1, bool RND, int NT>
__global__ void __launch_bounds__(256, 2)
mma_gemm(const float* __restrict__ A, int lda, size_t aBatch,
         const float* __restrict__ Bw, int ldb, size_t bBatch,
         float* __restrict__ C, int ldc, int cofs, size_t cBatch,
         const float* __restrict__ R, int ldr, int rofs,
         const float* __restrict__ tA, size_t tABat,
         const float* __restrict__ tB, size_t tBBat,
         float* __restrict__ pS1, float* __restrict__ pS2,
         int Nn, int Kk) {
    constexpr int STG = (NT == 128) ? 16384 : 12288;
    constexpr int NTILES = NT / 32;          // n8-tile pairs per warp
    extern __shared__ float dsm[];
    uint32_t sbase = (uint32_t)__cvta_generic_to_shared(dsm);

    int tid = threadIdx.x;
    int lane = tid & 31, wid = tid >> 5;
    int warpm = wid >> 2, warpn = wid & 3;
    int bm = blockIdx.y << 7, bnb = blockIdx.x * NT;

    const float* Ab = A;
    const float* Bb = Bw;
    const float* tAp = tA;
    const float* tBp = tB;
    const float* Rp = R;
    float* pS1p = pS1;
    float* pS2p = pS2;
    float* Cp = C;
    if (BM == 1) {
        int bz = blockIdx.z;
        int b = bz / H, h = bz % H;
        Ab += (size_t)b * N * lda + h * HD;
        Bb += (size_t)b * N * ldb + h * HD;
        tAp = tA + (size_t)bz * N;
        tBp = tB + (size_t)bz * N;
        Cp += (size_t)bz * cBatch;
        if (EPI == 3) {
            Rp = R + (size_t)bz * ldr;       // vt row (ldr = 80*N)
            pS1p = pS1 + (size_t)bz * N;
            pS2p = pS2 + (size_t)bz * N;
        }
    }
    if (BM == 2) {
        int bz = blockIdx.z;
        Ab += (size_t)bz * aBatch;
        Bb += (size_t)bz * bBatch;
        Cp += (size_t)bz * cBatch;
        tAp = tA + (size_t)bz * tABat;
        tBp = tB + (size_t)bz * tBBat;
    }

    // ---- loader constants ----
    int lrow = tid >> 2, lch = tid & 3;
    uint32_t dOff = lrow * 64 + ((lch ^ ((lrow >> 1) & 3)) << 4);  // bytes
    const float* aSrc  = Ab + (size_t)(bm + lrow) * lda + lch * 4;
    const float* aSrc2 = aSrc + (size_t)64 * lda;
    int brow1 = bnb + lrow, brow2 = brow1 + 64;
    int cb1 = (brow1 < Nn) ? brow1 : Nn - 1;
    int cb2 = (brow2 < Nn) ? brow2 : Nn - 1;
    const float* bSrc1 = Bb + (size_t)cb1 * ldb + lch * 4;
    const float* bSrc2 = Bb + (size_t)cb2 * ldb + lch * 4;

    // ---- ldmatrix lane addressing ----
    int lrowA = (lane & 7) + ((lane >> 3) & 1) * 8;
    int hiA   = lane >> 4;
    int swA   = (lrowA >> 1) & 3;
    int lrowB = (lane & 7) + ((lane >> 4) & 1) * 8;
    int hiB   = (lane >> 3) & 1;
    int swB   = (lrowB >> 1) & 3;
    uint32_t aOff[2], bOff[2];
    #pragma unroll
    for (int ks = 0; ks < 2; ks++) {
        aOff[ks] = (warpm * 64 + lrowA) * 64 + (((2 * ks + hiA) ^ swA) << 4);
        bOff[ks] = 8192 + (warpn * (NT / 4) + lrowB) * 64 + (((2 * ks + hiB) ^ swB) << 4);
    }

    float acc[4][NTILES][4];
    #pragma unroll
    for (int i = 0; i < 4; i++)
        #pragma unroll
        for (int j = 0; j < NTILES; j++)
            #pragma unroll
            for (int r = 0; r < 4; r++) acc[i][j][r] = 0.f;

    int KT = Kk >> 4;

    ISSUE_STAGE(0, 0);
    ISSUE_STAGE(1, 16);
    ISSUE_STAGE(2, 32);

    for (int kt = 0; kt < KT; kt++) {
        CP_WAIT2();
        __syncthreads();
        int st = kt & 3;
        uint32_t sb = sbase + st * STG;
        #pragma unroll
        for (int ks = 0; ks < 2; ks++) {
            uint32_t af[4][4];
            uint32_t bf[NTILES][2];
            #pragma unroll
            for (int mt = 0; mt < 4; mt++)
                ldsm4(af[mt][0], af[mt][1], af[mt][2], af[mt][3],
                      sb + aOff[ks] + mt * 1024);
            #pragma unroll
            for (int np = 0; np < NTILES / 2; np++)
                ldsm4(bf[2 * np][0], bf[2 * np][1], bf[2 * np + 1][0], bf[2 * np + 1][1],
                      sb + bOff[ks] + np * 1024);
            #pragma unroll
            for (int mt = 0; mt < 4; mt++)
                #pragma unroll
                for (int nt = 0; nt < NTILES; nt++)
                    mma_tf32(acc[mt][nt], af[mt], bf[nt]);
        }
        int nk = kt + 3;
        if (nk < KT) { ISSUE_STAGE(nk & 3, nk << 4); }
        else CP_COMMIT();
    }

    // ------------------------------ epilogue --------------------------------
    int er = bm + warpm * 64 + (lane >> 2);
    int ec0 = bnb + warpn * (NT / 4) + 2 * (lane & 3);
    float sumE[4][2], sumT[4][2], sumQ[4][2];
    if (EPI == 3 || EPI == 1) {
        #pragma unroll
        for (int i = 0; i < 4; i++)
            #pragma unroll
            for (int j = 0; j < 2; j++) { sumE[i][j] = 0.f; sumT[i][j] = 0.f; sumQ[i][j] = 0.f; }
    }
    #pragma unroll
    for (int mt = 0; mt < 4; mt++) {
        #pragma unroll
        for (int nt = 0; nt < NTILES; nt++) {
            #pragma unroll
            for (int half = 0; half < 2; half++) {
                int r = er + mt * 16 + half * 8;
                int c = ec0 + nt * 8;
                bool ok0 = c < Nn, ok1 = (c + 1) < Nn;
                float v0 = acc[mt][nt][2 * half];
                float v1 = acc[mt][nt][2 * half + 1];
                if (RK1) {
                    float ta = tAp[r];
                    if (ok0) v0 += ta * tBp[c];
                    if (ok1) v1 += ta * tBp[c + 1];
                }
                if (EPI == 1) {
                    float t0 = fast_tanh(0.7978845608028654f * (v0 + 0.044715f * v0 * v0 * v0));
                    v0 = 0.5f * v0 * (1.f + t0);
                    float t1 = fast_tanh(0.7978845608028654f * (v1 + 0.044715f * v1 * v1 * v1));
                    v1 = 0.5f * v1 * (1.f + t1);
                    if (ok0) sumQ[mt][half] = fmaf(v0, v0, sumQ[mt][half]);
                    if (ok1) sumQ[mt][half] = fmaf(v1, v1, sumQ[mt][half]);
                }
                if (EPI == 2) {
                    const float* rp = R + (size_t)r * ldr + rofs;
                    if (ok0) v0 += rp[c];
                    if (ok1) v1 += rp[c + 1];
                }
                if (EPI == 3) {   // E = exp(1/(1+log(1+d2))) in (1,e]
                    float kt_ = tAp[r];
                    float d20 = fmaxf(2.f * (kt_ * tBp[c] - v0 - 1.f), 1e-8f);
                    float d21 = fmaxf(2.f * (kt_ * tBp[c + 1] - v1 - 1.f), 1e-8f);
                    v0 = rnd_tf32(__expf(__fdividef(1.f, 1.f + __logf(1.f + d20))));
                    v1 = rnd_tf32(__expf(__fdividef(1.f, 1.f + __logf(1.f + d21))));
                    sumE[mt][half] += v0 + v1;
                    sumT[mt][half] = fmaf(v0, Rp[c], sumT[mt][half]);
                    sumT[mt][half] = fmaf(v1, Rp[c + 1], sumT[mt][half]);
                }
                if (EPI == 4) {   // row scale by reciprocal of accumulated sum
                    float sc = __fdividef(1.f, tAp[r]);
                    v0 *= sc;
                    v1 *= sc;
                }
                if (RND && EPI != 3) { v0 = rnd_tf32(v0); v1 = rnd_tf32(v1); }
                float* cp = Cp + (size_t)r * ldc + cofs;
                if (EPI == 3) {
                    // streaming store: E has no reuse before eviction
                    if (ok0) __stcs(cp + c, v0);
                    if (ok1) __stcs(cp + c + 1, v1);
                } else {
                    if (ok0) cp[c] = v0;
                    if (ok1) cp[c + 1] = v1;
                }
            }
        }
    }
    if (EPI == 3) {
        #pragma unroll
        for (int mt = 0; mt < 4; mt++)
            #pragma unroll
            for (int half = 0; half < 2; half++) {
                float vE = sumE[mt][half], vT = sumT[mt][half];
                vE += __shfl_down_sync(0xffffffffu, vE, 1, 4);
                vE += __shfl_down_sync(0xffffffffu, vE, 2, 4);
                vT += __shfl_down_sync(0xffffffffu, vT, 1, 4);
                vT += __shfl_down_sync(0xffffffffu, vT, 2, 4);
                if ((lane & 3) == 0) {
                    int r = er + mt * 16 + half * 8;
                    atomicAdd(&pS1p[r], vE);
                    atomicAdd(&pS2p[r], vT);
                }
            }
    }
    if (EPI == 1) {
        #pragma unroll
        for (int mt = 0; mt < 4; mt++)
            #pragma unroll
            for (int half = 0; half < 2; half++) {
                float vQ = sumQ[mt][half];
                vQ += __shfl_down_sync(0xffffffffu, vQ, 1, 4);
                vQ += __shfl_down_sync(0xffffffffu, vQ, 2, 4);
                if ((lane & 3) == 0) {
                    int r = er + mt * 16 + half * 8;
                    atomicAdd(&pS1p[r], vQ);
                }
            }
    }
}

// --------- per-head time for Q, K, V (V time -> row 0 of g_vT, tf32) --------
__global__ void head_time_kernel() {
    int idx = blockIdx.x * 256 + threadIdx.x;
    if (idx >= BH * N) return;
    int which = blockIdx.y;
    int i = idx & (N - 1);
    int bh = idx >> 10;
    int h = bh % H, b = bh / H;
    const float* p = g_qkv + (size_t)which * BN * DS + (size_t)(b * N + i) * DS + h * HD;
    float s = 1.f;
    #pragma unroll 16
    for (int d = 0; d < HD; d++) s = fmaf(p[d], p[d], s);
    float t = sqrtf(s);
    if (which == 0)      g_qt[idx] = t;
    else if (which == 1) g_kt[idx] = t;
    else                 g_vT[(size_t)bh * 80 * N + i] = rnd_tf32(t);
}

// ------------------ V transpose to [bh][80][N] (rows 1..64) -----------------
__global__ void vT_kernel() {
    __shared__ float tile[32][33];
    int i0 = blockIdx.x << 5, d0 = blockIdx.y << 5, b = blockIdx.z;
    int tx = threadIdx.x, ty = threadIdx.y;
    const float* vsp = g_qkv + (size_t)2 * BN * DS;
    #pragma unroll
    for (int r = 0; r < 4; r++)
        tile[ty + 8 * r][tx] = vsp[(size_t)(b * N + i0 + ty + 8 * r) * DS + d0 + tx];
    __syncthreads();
    #pragma unroll
    for (int r = 0; r < 4; r++) {
        int dg = d0 + ty + 8 * r;
        int h = dg >> 6, dd = dg & 63;
        g_vT[((size_t)(b * H + h) * 80 + 1 + dd) * N + i0 + tx] = tile[tx][ty + 8 * r];
    }
}

// ----------------------- hidt = sqrt(1 + sum v^2) ---------------------------
__global__ void hidt_kernel() {
    int idx = blockIdx.x * 256 + threadIdx.x;
    if (idx < BN) g_hidt[idx] = sqrtf(1.f + g_hsq[idx]);
}

// --------- per-head hyperboloid normalize + head-concat + new time ----------
__global__ void assemble_kernel() {
    __shared__ float hsum[12];
    __shared__ float hinv[12];
    __shared__ float cts;
    int bn = blockIdx.x;
    int b = bn >> 10, j = bn & (N - 1);
    int tid = threadIdx.x;
    if (tid < 12) hsum[tid] = 0.f;
    if (tid == 0) cts = 0.f;
    __syncthreads();
    float sv[3];
    #pragma unroll
    for (int r = 0; r < 3; r++) {
        int e = tid + r * 256;
        int h = e >> 6, d = e & 63;
        sv[r] = g_s[((size_t)(b * H + h) * N + j) * 80 + 1 + d];
        atomicAdd(&hsum[h], sv[r] * sv[r]);
    }
    __syncthreads();
    if (tid < 12) {
        int row = (b * H + tid) * N + j;
        float st = g_st[row] / g_rsE[row];
        float li = st * st - hsum[tid];
        float inv = rsqrtf(fmaxf(li, 1e-8f));
        hinv[tid] = inv;
        float ct = st * inv;
        atomicAdd(&cts, ct * ct);
    }
    __syncthreads();
    float* os = g_atns + (size_t)bn * DS;
    #pragma unroll
    for (int r = 0; r < 3; r++) {
        int e = tid + r * 256;
        int h = e >> 6;
        os[e] = rnd_tf32(sv[r] * hinv[h]);
    }
    if (tid == 0) g_atnt[bn] = sqrtf(cts - 11.f);
}

// --------------------------- final add_time ---------------------------------
__global__ void final_time_kernel(float* __restrict__ out) {
    __shared__ float sh[33];
    int bn = blockIdx.x, tid = threadIdx.x;
    float* p = out + (size_t)bn * 769;
    float s = 0.f;
    #pragma unroll
    for (int r = 0; r < 3; r++) {
        float v = p[1 + tid + r * 256];
        s = fmaf(v, v, s);
    }
    s = block_reduce_sum(s, sh);
    if (tid == 0) p[0] = sqrtf(1.f + s);
}

// ----------------------------------------------------------------------------
extern "C" void kernel_launch(void* const* d_in, const int* in_sizes, int n_in,
                              void* d_out, int out_size) {
    const float* x      = (const float*)d_in[0];
    const float* gamma1 = (const float*)d_in[1];
    const float* beta1  = (const float*)d_in[2];
    const float* Wq     = (const float*)d_in[3];
    const float* Wk     = (const float*)d_in[4];
    const float* Wv     = (const float*)d_in[5];
    const float* Wo     = (const float*)d_in[6];
    const float* gamma2 = (const float*)d_in[7];
    const float* beta2  = (const float*)d_in[8];
    const float* W1     = (const float*)d_in[9];
    const float* W2     = (const float*)d_in[10];
    float* out = (float*)d_out;

    float *h1s, *h1t, *qkv, *qt, *kt, *vT, *lt, *rsE, *st, *s_;
    float *atns, *atnt, *out1, *zs, *zt, *hid, *hsq, *hidt;
    float *wqkv, *wqkvt, *wos, *wot, *w1s, *w1t, *w2s, *w2t;
    cudaGetSymbolAddress((void**)&h1s,  g_h1s);  cudaGetSymbolAddress((void**)&h1t,  g_h1t);
    cudaGetSymbolAddress((void**)&qkv,  g_qkv);
    cudaGetSymbolAddress((void**)&qt,   g_qt);   cudaGetSymbolAddress((void**)&kt,   g_kt);
    cudaGetSymbolAddress((void**)&vT,   g_vT);   cudaGetSymbolAddress((void**)&lt,   g_lt);
    cudaGetSymbolAddress((void**)&rsE,  g_rsE);
    cudaGetSymbolAddress((void**)&st,   g_st);   cudaGetSymbolAddress((void**)&s_,   g_s);
    cudaGetSymbolAddress((void**)&atns, g_atns); cudaGetSymbolAddress((void**)&atnt, g_atnt);
    cudaGetSymbolAddress((void**)&out1, g_out1);
    cudaGetSymbolAddress((void**)&zs,   g_zs);   cudaGetSymbolAddress((void**)&zt,   g_zt);
    cudaGetSymbolAddress((void**)&hid,  g_hid);  cudaGetSymbolAddress((void**)&hsq,  g_hsq);
    cudaGetSymbolAddress((void**)&hidt, g_hidt);
    cudaGetSymbolAddress((void**)&wqkv, g_wqkv); cudaGetSymbolAddress((void**)&wqkvt, g_wqkvt);
    cudaGetSymbolAddress((void**)&wos,  g_wos);  cudaGetSymbolAddress((void**)&wot,  g_wot);
    cudaGetSymbolAddress((void**)&w1s,  g_w1s);  cudaGetSymbolAddress((void**)&w1t,  g_w1t);
    cudaGetSymbolAddress((void**)&w2s,  g_w2s);  cudaGetSymbolAddress((void**)&w2t,  g_w2t);

    constexpr int SMB128 = 65536;   // 4 stages * 16KB
    constexpr int SMB64  = 49152;   // 4 stages * 12KB
    cudaFuncSetAttribute(mma_gemm<0, 2, true,  true,  128>, cudaFuncAttributeMaxDynamicSharedMemorySize, SMB128);
    cudaFuncSetAttribute(mma_gemm<3, 1, false, true,  128>, cudaFuncAttributeMaxDynamicSharedMemorySize, SMB128);
    cudaFuncSetAttribute(mma_gemm<4, 2, false, false, 64>,  cudaFuncAttributeMaxDynamicSharedMemorySize, SMB64);
    cudaFuncSetAttribute(mma_gemm<2, 0, true,  false, 128>, cudaFuncAttributeMaxDynamicSharedMemorySize, SMB128);
    cudaFuncSetAttribute(mma_gemm<1, 0, true,  true,  128>, cudaFuncAttributeMaxDynamicSharedMemorySize, SMB128);

    dim3 t1(256);
    const float* qs  = qkv;
    const float* ksp = qkv + (size_t)BN * DS;

    // 0) weight prep + accumulator zero
    prep_w<<<(768 * 768 + 255) / 256, t1>>>(Wq, wqkv,                 wqkvt,        768, 768, 768, 769);
    prep_w<<<(768 * 768 + 255) / 256, t1>>>(Wk, wqkv + 768 * 768,     wqkvt + 768,  768, 768, 768, 769);
    prep_w<<<(768 * 768 + 255) / 256, t1>>>(Wv, wqkv + 2 * 768 * 768, wqkvt + 1536, 768, 768, 768, 769);
    prep_w<<<(768 * 768 + 255) / 256, t1>>>(Wo, wos, wot, 768, 768, 768, 769);
    prep_w<<<(3071 * 768 + 255) / 256, t1>>>(W1, w1s, w1t, 3071, 768, 768, 769);
    prep_w<<<(768 * 3072 + 255) / 256, t1>>>(W2, w2s, w2t, 768, 3072, 3071, 3072);
    zero_acc<<<(BH * N + BN + 255) / 256, t1>>>();

    // 1) LN1
    ln_kernel<<<BN, t1>>>(x, 769, 1, gamma1, beta1, h1s, h1t);

    // 2) QKV — single batched launch (grid.z = 3)
    mma_gemm<0, 2, true, true, 128><<<dim3(6, 64, 3), t1, SMB128>>>(
        h1s, 768, 0, wqkv, 768, (size_t)768 * 768, qkv, 768, 0, (size_t)BN * DS,
        nullptr, 0, 0, h1t, 0, wqkvt, 768, nullptr, nullptr, 768, 768);
    head_time_kernel<<<dim3((BH * N + 255) / 256, 3), t1>>>();
    vT_kernel<<<dim3(32, 24, 8), dim3(32, 8)>>>();

    // 3) E=exp(logits) + fused rowsum/time-dot; av (64-wide, recip in epilogue)
    mma_gemm<3, 1, false, true, 128><<<dim3(8, 8, BH), t1, SMB128>>>(
        ksp, 768, 0, qs, 768, 0, lt, N, 0, (size_t)N * N,
        vT, 80 * N, 0, kt, 0, qt, 0, rsE, st, N, HD);
    mma_gemm<4, 2, false, false, 64><<<dim3(1, 8, BH), t1, SMB64>>>(
        lt, N, (size_t)N * N, vT + N, N, (size_t)80 * N, s_, 80, 1, (size_t)N * 80,
        nullptr, 0, 0, rsE, N, nullptr, 0, nullptr, nullptr, 64, N);

    // 4) normalize + concat heads (time from st/rsE)
    assemble_kernel<<<BN, t1>>>();

    // 5) Wo + residual(x)
    mma_gemm<2, 0, true, false, 128><<<dim3(6, 64), t1, SMB128>>>(
        atns, 768, 0, wos, 768, 0, out1, 768, 0, 0,
        x, 769, 1, atnt, 0, wot, 0, nullptr, nullptr, 768, 768);

    // 6) LN2
    ln_kernel<<<BN, t1>>>(out1, 768, 0, gamma2, beta2, zs, zt);

    // 7) FFN up (fast gelu + fused |v|^2 atomics), then hidt
    mma_gemm<1, 0, true, true, 128><<<dim3(24, 64), t1, SMB128>>>(
        zs, 768, 0, w1s, 768, 0, hid, M_, 0, 0,
        nullptr, 0, 0, zt, 0, w1t, 0, hsq, nullptr, 3071, 768);
    hidt_kernel<<<(BN + 255) / 256, t1>>>();

    // 8) FFN down + residual(out1) -> d_out space cols
    mma_gemm<2, 0, true, false, 128><<<dim3(6, 64), t1, SMB128>>>(
        hid, M_, 0, w2s, M_, 0, out, 769, 1, 0,
        out1, 768, 0, hidt, 0, w2t, 0, nullptr, nullptr, 768, M_);

    // 9) final add_time
    final_time_kernel<<<BN, t1>>>(out);
}

// round 13
// speedup vs baseline: 2.1471x; 1.1476x over previous
#include <cuda_runtime.h>
#include <math.h>
#include <stdint.h>

// ---------------------------------------------------------------------------
// LorentzTransformerEncoder  (B=8, N=1024, D=769, H=12, hd=64, M=3072)
// R13 = R12 + av epilogue does hyperboloid normalize + direct concat write
//       (EPI5, removes assemble + g_s) and QKV epilogue accumulates per-head
//       |v|^2 (EPI6, removes bulk head_time reads).
// ---------------------------------------------------------------------------

constexpr int B  = 8;
constexpr int N  = 1024;
constexpr int DS = 768;
constexpr int H  = 12;
constexpr int HD = 64;
constexpr int M_ = 3072;
constexpr int BN = B * N;   // 8192
constexpr int BH = B * H;   // 96

// ------------------------------- scratch -----------------------------------
__device__ float g_h1s [(size_t)BN * DS];
__device__ float g_h1t [BN];
__device__ float g_qkv [(size_t)3 * BN * DS];   // [q|k|v] space, contiguous
__device__ float g_qt  [BH * N];
__device__ float g_kt  [BH * N];
__device__ float g_vT  [(size_t)BH * 80 * N];   // row 0 time, rows 1..64 space^T
__device__ float g_lt  [(size_t)BH * N * N];    // E = exp(logit)
__device__ float g_rsE [BH * N];                // row-sum of E (accumulated)
__device__ float g_st  [BH * N];                // sum E * vt (accumulated)
__device__ float g_hts [3 * BH * N];            // per-head |v|^2 for q,k,v
__device__ float g_cts [BN];                    // sum ct^2 per token
__device__ float g_atns[(size_t)BN * DS];
__device__ float g_atnt[BN];
__device__ float g_out1[(size_t)BN * DS];
__device__ float g_zs  [(size_t)BN * DS];
__device__ float g_zt  [BN];
__device__ float g_hid [(size_t)BN * M_];       // col 3071 stays 0
__device__ float g_hsq [BN];                    // sum v^2 (accumulated)
__device__ float g_hidt[BN];
// tf32 weights (space part, k-major, aligned) + time columns
__device__ float g_wqkv [(size_t)3 * 768 * 768];
__device__ float g_wqkvt[3 * 768];
__device__ float g_wos [768 * 768];  __device__ float g_wot [768];
__device__ float g_w1s [3071 * 768]; __device__ float g_w1t [3071];
__device__ float g_w2s [768 * 3072]; __device__ float g_w2t [768];

// ----------------------------- helpers --------------------------------------
__device__ __forceinline__ uint32_t cvt_tf32(float x) {
    uint32_t r;
    asm("cvt.rna.tf32.f32 %0, %1;" : "=r"(r) : "f"(x));
    return r;
}
__device__ __forceinline__ float rnd_tf32(float x) { return __uint_as_float(cvt_tf32(x)); }

__device__ __forceinline__ void ldsm4(uint32_t& r0, uint32_t& r1, uint32_t& r2,
                                      uint32_t& r3, uint32_t addr) {
    asm volatile("ldmatrix.sync.aligned.m8n8.x4.shared.b16 {%0,%1,%2,%3},[%4];"
                 : "=r"(r0), "=r"(r1), "=r"(r2), "=r"(r3) : "r"(addr));
}
__device__ __forceinline__ void mma_tf32(float* c, const uint32_t* a, const uint32_t* b) {
    asm volatile("mma.sync.aligned.m16n8k8.row.col.f32.tf32.tf32.f32 "
                 "{%0,%1,%2,%3},{%4,%5,%6,%7},{%8,%9},{%0,%1,%2,%3};"
                 : "+f"(c[0]), "+f"(c[1]), "+f"(c[2]), "+f"(c[3])
                 : "r"(a[0]), "r"(a[1]), "r"(a[2]), "r"(a[3]), "r"(b[0]), "r"(b[1]));
}
#define CP16(d, s) \
    asm volatile("cp.async.cg.shared.global [%0],[%1],16;" :: "r"(d), "l"(s))
#define CP_COMMIT() asm volatile("cp.async.commit_group;" ::: "memory")
#define CP_WAIT2()  asm volatile("cp.async.wait_group 2;" ::: "memory")
#define CP_WAIT0()  asm volatile("cp.async.wait_group 0;" ::: "memory")

// fast tanh via exp (robust at both tails)
__device__ __forceinline__ float fast_tanh(float a) {
    float e2 = __expf(2.f * a);
    return __fdividef(e2 - 1.f, e2 + 1.f);
}

// one pipeline stage; NT==64 drops the second B row batch (B is 64 rows)
#define ISSUE_STAGE(slot, k0)                                    \
    do {                                                         \
        uint32_t sa_ = sbase + (slot) * STG + dOff;              \
        CP16(sa_,         aSrc  + (k0));                         \
        CP16(sa_ + 4096,  aSrc2 + (k0));                         \
        CP16(sa_ + 8192,  bSrc1 + (k0));                         \
        if (NT == 128) { CP16(sa_ + 12288, bSrc2 + (k0)); }      \
        CP_COMMIT();                                             \
    } while (0)

__device__ __forceinline__ float block_reduce_sum(float v, float* sh) {
    int tid = threadIdx.x, lane = tid & 31, wid = tid >> 5;
    #pragma unroll
    for (int o = 16; o > 0; o >>= 1) v += __shfl_down_sync(0xffffffffu, v, o);
    __syncthreads();
    if (lane == 0) sh[wid] = v;
    __syncthreads();
    if (tid == 0) {
        float s = 0.f;
        #pragma unroll
        for (int w = 0; w < 8; w++) s += sh[w];
        sh[32] = s;
    }
    __syncthreads();
    return sh[32];
}

// ------------------------ weight prep (tf32 + split time) -------------------
__global__ void prep_w(const float* __restrict__ W, float* __restrict__ Ws,
                       float* __restrict__ Wt, int rows, int cols, int kcols, int sld) {
    int idx = blockIdx.x * 256 + threadIdx.x;
    if (idx >= rows * cols) return;
    int n = idx / cols, k = idx - n * cols;
    float v = (k < kcols) ? W[(size_t)(n + 1) * sld + k + 1] : 0.f;
    Ws[idx] = rnd_tf32(v);
    if (k == 0) Wt[n] = W[(size_t)(n + 1) * sld];
}

// ------------------ zero the atomic accumulators (per launch) ---------------
__global__ void zero_acc() {
    int idx = blockIdx.x * 256 + threadIdx.x;
    if (idx < BH * N) { g_rsE[idx] = 0.f; g_st[idx] = 0.f; }
    if (idx < 3 * BH * N) g_hts[idx] = 0.f;
    if (idx < BN) { g_hsq[idx] = 0.f; g_cts[idx] = 0.f; }
}

// ------------------------- Lorentz layernorm --------------------------------
__global__ void ln_kernel(const float* __restrict__ X, int ldx, int xofs,
                          const float* __restrict__ gamma,
                          const float* __restrict__ beta,
                          float* __restrict__ Ys, float* __restrict__ Yt) {
    __shared__ float sh[33];
    int bn = blockIdx.x, tid = threadIdx.x;
    const float* x = X + (size_t)bn * ldx + xofs;
    float v[3], s = 0.f;
    #pragma unroll
    for (int i = 0; i < 3; i++) { v[i] = x[tid + i * 256]; s += v[i]; }
    s = block_reduce_sum(s, sh);
    float mu = s * (1.f / 768.f);
    float s2 = 0.f;
    #pragma unroll
    for (int i = 0; i < 3; i++) { float dd = v[i] - mu; s2 += dd * dd; }
    s2 = block_reduce_sum(s2, sh);
    float rstd = rsqrtf(s2 * (1.f / 768.f) + 1e-5f);
    float t2 = 0.f;
    float* ys = Ys + (size_t)bn * DS;
    #pragma unroll
    for (int i = 0; i < 3; i++) {
        int d = tid + i * 256;
        float yy = gamma[d] * (v[i] - mu) * rstd + beta[d];
        ys[d] = rnd_tf32(yy);
        t2 += yy * yy;
    }
    t2 = block_reduce_sum(t2, sh);
    if (tid == 0) Yt[bn] = sqrtf(1.f + t2);
}

// ------------------------------- tf32 GEMM ----------------------------------
// C[m][n] = sum_k A[m][k] * Bw[n][k]  (+ rank1 tA[m]*tB[n] if RK1)
// EPI: 0 none, 1 gelu(+hsq atomics), 2 +R, 3 exp(logit)(+rowsum/time atomics),
//      5 av+normalize+concat, 6 qkv(+per-head |v|^2 atomics)
// BM : 0 none, 1 head-slice, 2 flat batch.  NT: n-tile width 128 or 64.
// 128xNT tile, K%16==0 (KT>=3), 4-stage cp.async, 256 thr, 8 warps (2m x 4n).
template<int EPI, int BM, bool RK1, bool RND, int NT>
__global__ void __launch_bounds__(256, 2)
mma_gemm(const float* __restrict__ A, int lda, size_t aBatch,
         const float* __restrict__ Bw, int ldb, size_t bBatch,
         float* __restrict__ C, int ldc, int cofs, size_t cBatch,
         const float* __restrict__ R, int ldr, int rofs,
         const float* __restrict__ tA, size_t tABat,
         const float* __restrict__ tB, size_t tBBat,
         float* __restrict__ pS1, float* __restrict__ pS2,
         int Nn, int Kk) {
    constexpr int STG = (NT == 128) ? 16384 : 12288;
    constexpr int NTILES = NT / 32;          // n8-tile pairs per warp
    extern __shared__ float dsm[];
    uint32_t sbase = (uint32_t)__cvta_generic_to_shared(dsm);

    int tid = threadIdx.x;
    int lane = tid & 31, wid = tid >> 5;
    int warpm = wid >> 2, warpn = wid & 3;
    int bm = blockIdx.y << 7, bnb = blockIdx.x * NT;

    const float* Ab = A;
    const float* Bb = Bw;
    const float* tAp = tA;
    const float* tBp = tB;
    const float* Rp = R;
    float* pS1p = pS1;
    float* pS2p = pS2;
    float* Cp = C;
    if (BM == 1) {
        int bz = blockIdx.z;
        int b = bz / H, h = bz % H;
        Ab += (size_t)b * N * lda + h * HD;
        Bb += (size_t)b * N * ldb + h * HD;
        tAp = tA + (size_t)bz * N;
        tBp = tB + (size_t)bz * N;
        Cp += (size_t)bz * cBatch;
        if (EPI == 3) {
            Rp = R + (size_t)bz * ldr;       // vt row (ldr = 80*N)
            pS1p = pS1 + (size_t)bz * N;
            pS2p = pS2 + (size_t)bz * N;
        }
    }
    if (BM == 2) {
        int bz = blockIdx.z;
        Ab += (size_t)bz * aBatch;
        Bb += (size_t)bz * bBatch;
        Cp += (size_t)bz * cBatch;
        tAp = tA + (size_t)bz * tABat;
        tBp = tB + (size_t)bz * tBBat;
    }

    // ---- loader constants ----
    int lrow = tid >> 2, lch = tid & 3;
    uint32_t dOff = lrow * 64 + ((lch ^ ((lrow >> 1) & 3)) << 4);  // bytes
    const float* aSrc  = Ab + (size_t)(bm + lrow) * lda + lch * 4;
    const float* aSrc2 = aSrc + (size_t)64 * lda;
    int brow1 = bnb + lrow, brow2 = brow1 + 64;
    int cb1 = (brow1 < Nn) ? brow1 : Nn - 1;
    int cb2 = (brow2 < Nn) ? brow2 : Nn - 1;
    const float* bSrc1 = Bb + (size_t)cb1 * ldb + lch * 4;
    const float* bSrc2 = Bb + (size_t)cb2 * ldb + lch * 4;

    // ---- ldmatrix lane addressing ----
    int lrowA = (lane & 7) + ((lane >> 3) & 1) * 8;
    int hiA   = lane >> 4;
    int swA   = (lrowA >> 1) & 3;
    int lrowB = (lane & 7) + ((lane >> 4) & 1) * 8;
    int hiB   = (lane >> 3) & 1;
    int swB   = (lrowB >> 1) & 3;
    uint32_t aOff[2], bOff[2];
    #pragma unroll
    for (int ks = 0; ks < 2; ks++) {
        aOff[ks] = (warpm * 64 + lrowA) * 64 + (((2 * ks + hiA) ^ swA) << 4);
        bOff[ks] = 8192 + (warpn * (NT / 4) + lrowB) * 64 + (((2 * ks + hiB) ^ swB) << 4);
    }

    float acc[4][NTILES][4];
    #pragma unroll
    for (int i = 0; i < 4; i++)
        #pragma unroll
        for (int j = 0; j < NTILES; j++)
            #pragma unroll
            for (int r = 0; r < 4; r++) acc[i][j][r] = 0.f;

    int KT = Kk >> 4;

    ISSUE_STAGE(0, 0);
    ISSUE_STAGE(1, 16);
    ISSUE_STAGE(2, 32);

    for (int kt = 0; kt < KT; kt++) {
        CP_WAIT2();
        __syncthreads();
        int st = kt & 3;
        uint32_t sb = sbase + st * STG;
        #pragma unroll
        for (int ks = 0; ks < 2; ks++) {
            uint32_t af[4][4];
            uint32_t bf[NTILES][2];
            #pragma unroll
            for (int mt = 0; mt < 4; mt++)
                ldsm4(af[mt][0], af[mt][1], af[mt][2], af[mt][3],
                      sb + aOff[ks] + mt * 1024);
            #pragma unroll
            for (int np = 0; np < NTILES / 2; np++)
                ldsm4(bf[2 * np][0], bf[2 * np][1], bf[2 * np + 1][0], bf[2 * np + 1][1],
                      sb + bOff[ks] + np * 1024);
            #pragma unroll
            for (int mt = 0; mt < 4; mt++)
                #pragma unroll
                for (int nt = 0; nt < NTILES; nt++)
                    mma_tf32(acc[mt][nt], af[mt], bf[nt]);
        }
        int nk = kt + 3;
        if (nk < KT) { ISSUE_STAGE(nk & 3, nk << 4); }
        else CP_COMMIT();
    }

    // ------------------------------ epilogue --------------------------------
    int er = bm + warpm * 64 + (lane >> 2);
    int ec0 = bnb + warpn * (NT / 4) + 2 * (lane & 3);

    if (EPI == 5) {
        // av + per-head hyperboloid normalize + direct concat write.
        // Rows = tokens (full head per CTA row); cols = head dims 0..63.
        CP_WAIT0();
        __syncthreads();
        float* hs = dsm;                 // reuse stage smem for per-row |v|^2
        if (tid < 128) hs[tid] = 0.f;
        __syncthreads();
        int bz = blockIdx.z;
        int b = bz / H, h = bz % H;
        #pragma unroll
        for (int mt = 0; mt < 4; mt++)
            #pragma unroll
            for (int half = 0; half < 2; half++) {
                int r = er + mt * 16 + half * 8;
                float sc = __fdividef(1.f, tAp[r]);
                float ss = 0.f;
                #pragma unroll
                for (int nt = 0; nt < NTILES; nt++) {
                    float v0 = acc[mt][nt][2 * half] * sc;
                    float v1 = acc[mt][nt][2 * half + 1] * sc;
                    acc[mt][nt][2 * half] = v0;
                    acc[mt][nt][2 * half + 1] = v1;
                    ss = fmaf(v0, v0, fmaf(v1, v1, ss));
                }
                ss += __shfl_down_sync(0xffffffffu, ss, 1, 4);
                ss += __shfl_down_sync(0xffffffffu, ss, 2, 4);
                if ((lane & 3) == 0) atomicAdd(&hs[r - bm], ss);
            }
        __syncthreads();
        #pragma unroll
        for (int mt = 0; mt < 4; mt++)
            #pragma unroll
            for (int half = 0; half < 2; half++) {
                int r = er + mt * 16 + half * 8;
                float sc = __fdividef(1.f, tAp[r]);
                float stt = pS2[(size_t)bz * N + r] * sc;
                float inv = rsqrtf(fmaxf(stt * stt - hs[r - bm], 1e-8f));
                float* op = Cp + (size_t)(b * N + r) * 768 + h * 64;
                #pragma unroll
                for (int nt = 0; nt < NTILES; nt++) {
                    int c = ec0 + nt * 8;
                    op[c]     = rnd_tf32(acc[mt][nt][2 * half] * inv);
                    op[c + 1] = rnd_tf32(acc[mt][nt][2 * half + 1] * inv);
                }
                if (warpn == 0 && (lane & 3) == 0) {
                    float ct = stt * inv;
                    atomicAdd(&pS1[b * N + r], ct * ct);
                }
            }
        return;
    }

    float sumE[4][2], sumT[4][2], sumQ[4][2];
    if (EPI == 3 || EPI == 1 || EPI == 6) {
        #pragma unroll
        for (int i = 0; i < 4; i++)
            #pragma unroll
            for (int j = 0; j < 2; j++) { sumE[i][j] = 0.f; sumT[i][j] = 0.f; sumQ[i][j] = 0.f; }
    }
    #pragma unroll
    for (int mt = 0; mt < 4; mt++) {
        #pragma unroll
        for (int nt = 0; nt < NTILES; nt++) {
            #pragma unroll
            for (int half = 0; half < 2; half++) {
                int r = er + mt * 16 + half * 8;
                int c = ec0 + nt * 8;
                bool ok0 = c < Nn, ok1 = (c + 1) < Nn;
                float v0 = acc[mt][nt][2 * half];
                float v1 = acc[mt][nt][2 * half + 1];
                if (RK1) {
                    float ta = tAp[r];
                    if (ok0) v0 += ta * tBp[c];
                    if (ok1) v1 += ta * tBp[c + 1];
                }
                if (EPI == 1) {
                    float t0 = fast_tanh(0.7978845608028654f * (v0 + 0.044715f * v0 * v0 * v0));
                    v0 = 0.5f * v0 * (1.f + t0);
                    float t1 = fast_tanh(0.7978845608028654f * (v1 + 0.044715f * v1 * v1 * v1));
                    v1 = 0.5f * v1 * (1.f + t1);
                    if (ok0) sumQ[mt][half] = fmaf(v0, v0, sumQ[mt][half]);
                    if (ok1) sumQ[mt][half] = fmaf(v1, v1, sumQ[mt][half]);
                }
                if (EPI == 2) {
                    const float* rp = R + (size_t)r * ldr + rofs;
                    if (ok0) v0 += rp[c];
                    if (ok1) v1 += rp[c + 1];
                }
                if (EPI == 3) {   // E = exp(1/(1+log(1+d2))) in (1,e]
                    float kt_ = tAp[r];
                    float d20 = fmaxf(2.f * (kt_ * tBp[c] - v0 - 1.f), 1e-8f);
                    float d21 = fmaxf(2.f * (kt_ * tBp[c + 1] - v1 - 1.f), 1e-8f);
                    v0 = rnd_tf32(__expf(__fdividef(1.f, 1.f + __logf(1.f + d20))));
                    v1 = rnd_tf32(__expf(__fdividef(1.f, 1.f + __logf(1.f + d21))));
                    sumE[mt][half] += v0 + v1;
                    sumT[mt][half] = fmaf(v0, Rp[c], sumT[mt][half]);
                    sumT[mt][half] = fmaf(v1, Rp[c + 1], sumT[mt][half]);
                }
                if (RND && EPI != 3) { v0 = rnd_tf32(v0); v1 = rnd_tf32(v1); }
                if (EPI == 6) {   // per-head |v|^2 of rounded stored values
                    sumQ[mt][half] = fmaf(v0, v0, fmaf(v1, v1, sumQ[mt][half]));
                }
                float* cp = Cp + (size_t)r * ldc + cofs;
                if (EPI == 3) {
                    if (ok0) __stcs(cp + c, v0);
                    if (ok1) __stcs(cp + c + 1, v1);
                } else {
                    if (ok0) cp[c] = v0;
                    if (ok1) cp[c + 1] = v1;
                }
            }
        }
    }
    if (EPI == 3) {
        #pragma unroll
        for (int mt = 0; mt < 4; mt++)
            #pragma unroll
            for (int half = 0; half < 2; half++) {
                float vE = sumE[mt][half], vT = sumT[mt][half];
                vE += __shfl_down_sync(0xffffffffu, vE, 1, 4);
                vE += __shfl_down_sync(0xffffffffu, vE, 2, 4);
                vT += __shfl_down_sync(0xffffffffu, vT, 1, 4);
                vT += __shfl_down_sync(0xffffffffu, vT, 2, 4);
                if ((lane & 3) == 0) {
                    int r = er + mt * 16 + half * 8;
                    atomicAdd(&pS1p[r], vE);
                    atomicAdd(&pS2p[r], vT);
                }
            }
    }
    if (EPI == 1) {
        #pragma unroll
        for (int mt = 0; mt < 4; mt++)
            #pragma unroll
            for (int half = 0; half < 2; half++) {
                float vQ = sumQ[mt][half];
                vQ += __shfl_down_sync(0xffffffffu, vQ, 1, 4);
                vQ += __shfl_down_sync(0xffffffffu, vQ, 2, 4);
                if ((lane & 3) == 0) {
                    int r = er + mt * 16 + half * 8;
                    atomicAdd(&pS1p[r], vQ);
                }
            }
    }
    if (EPI == 6) {
        // accumulate per-(token, head) |v|^2; each warp's cols sit in one head
        int ghead = (bnb + warpn * 32) >> 6;
        float* hp = pS1 + (size_t)blockIdx.z * ((size_t)BH * N);
        #pragma unroll
        for (int mt = 0; mt < 4; mt++)
            #pragma unroll
            for (int half = 0; half < 2; half++) {
                float vQ = sumQ[mt][half];
                vQ += __shfl_down_sync(0xffffffffu, vQ, 1, 4);
                vQ += __shfl_down_sync(0xffffffffu, vQ, 2, 4);
                if ((lane & 3) == 0) {
                    int r = er + mt * 16 + half * 8;
                    int b_ = r >> 10, j_ = r & 1023;
                    atomicAdd(&hp[((size_t)b_ * H + ghead) * N + j_], vQ);
                }
            }
    }
}

// ---- finish per-head times from accumulated |v|^2 (no bulk reads) ----------
__global__ void head_time2() {
    int idx = blockIdx.x * 256 + threadIdx.x;
    if (idx >= BH * N) return;
    g_qt[idx] = sqrtf(1.f + g_hts[idx]);
    g_kt[idx] = sqrtf(1.f + g_hts[BH * N + idx]);
    int bh = idx >> 10, i = idx & 1023;
    g_vT[(size_t)bh * 80 * N + i] = rnd_tf32(sqrtf(1.f + g_hts[2 * BH * N + idx]));
}

// ------------------ V transpose to [bh][80][N] (rows 1..64) -----------------
__global__ void vT_kernel() {
    __shared__ float tile[32][33];
    int i0 = blockIdx.x << 5, d0 = blockIdx.y << 5, b = blockIdx.z;
    int tx = threadIdx.x, ty = threadIdx.y;
    const float* vsp = g_qkv + (size_t)2 * BN * DS;
    #pragma unroll
    for (int r = 0; r < 4; r++)
        tile[ty + 8 * r][tx] = vsp[(size_t)(b * N + i0 + ty + 8 * r) * DS + d0 + tx];
    __syncthreads();
    #pragma unroll
    for (int r = 0; r < 4; r++) {
        int dg = d0 + ty + 8 * r;
        int h = dg >> 6, dd = dg & 63;
        g_vT[((size_t)(b * H + h) * 80 + 1 + dd) * N + i0 + tx] = tile[tx][ty + 8 * r];
    }
}

// ----------------------- small finishers ------------------------------------
__global__ void hidt_kernel() {
    int idx = blockIdx.x * 256 + threadIdx.x;
    if (idx < BN) g_hidt[idx] = sqrtf(1.f + g_hsq[idx]);
}
__global__ void atnt_kernel() {
    int idx = blockIdx.x * 256 + threadIdx.x;
    if (idx < BN) g_atnt[idx] = sqrtf(g_cts[idx] - 11.f);
}

// --------------------------- final add_time ---------------------------------
__global__ void final_time_kernel(float* __restrict__ out) {
    __shared__ float sh[33];
    int bn = blockIdx.x, tid = threadIdx.x;
    float* p = out + (size_t)bn * 769;
    float s = 0.f;
    #pragma unroll
    for (int r = 0; r < 3; r++) {
        float v = p[1 + tid + r * 256];
        s = fmaf(v, v, s);
    }
    s = block_reduce_sum(s, sh);
    if (tid == 0) p[0] = sqrtf(1.f + s);
}

// ----------------------------------------------------------------------------
extern "C" void kernel_launch(void* const* d_in, const int* in_sizes, int n_in,
                              void* d_out, int out_size) {
    const float* x      = (const float*)d_in[0];
    const float* gamma1 = (const float*)d_in[1];
    const float* beta1  = (const float*)d_in[2];
    const float* Wq     = (const float*)d_in[3];
    const float* Wk     = (const float*)d_in[4];
    const float* Wv     = (const float*)d_in[5];
    const float* Wo     = (const float*)d_in[6];
    const float* gamma2 = (const float*)d_in[7];
    const float* beta2  = (const float*)d_in[8];
    const float* W1     = (const float*)d_in[9];
    const float* W2     = (const float*)d_in[10];
    float* out = (float*)d_out;

    float *h1s, *h1t, *qkv, *qt, *kt, *vT, *lt, *rsE, *st, *hts, *cts;
    float *atns, *atnt, *out1, *zs, *zt, *hid, *hsq, *hidt;
    float *wqkv, *wqkvt, *wos, *wot, *w1s, *w1t, *w2s, *w2t;
    cudaGetSymbolAddress((void**)&h1s,  g_h1s);  cudaGetSymbolAddress((void**)&h1t,  g_h1t);
    cudaGetSymbolAddress((void**)&qkv,  g_qkv);
    cudaGetSymbolAddress((void**)&qt,   g_qt);   cudaGetSymbolAddress((void**)&kt,   g_kt);
    cudaGetSymbolAddress((void**)&vT,   g_vT);   cudaGetSymbolAddress((void**)&lt,   g_lt);
    cudaGetSymbolAddress((void**)&rsE,  g_rsE);  cudaGetSymbolAddress((void**)&st,   g_st);
    cudaGetSymbolAddress((void**)&hts,  g_hts);  cudaGetSymbolAddress((void**)&cts,  g_cts);
    cudaGetSymbolAddress((void**)&atns, g_atns); cudaGetSymbolAddress((void**)&atnt, g_atnt);
    cudaGetSymbolAddress((void**)&out1, g_out1);
    cudaGetSymbolAddress((void**)&zs,   g_zs);   cudaGetSymbolAddress((void**)&zt,   g_zt);
    cudaGetSymbolAddress((void**)&hid,  g_hid);  cudaGetSymbolAddress((void**)&hsq,  g_hsq);
    cudaGetSymbolAddress((void**)&hidt, g_hidt);
    cudaGetSymbolAddress((void**)&wqkv, g_wqkv); cudaGetSymbolAddress((void**)&wqkvt, g_wqkvt);
    cudaGetSymbolAddress((void**)&wos,  g_wos);  cudaGetSymbolAddress((void**)&wot,  g_wot);
    cudaGetSymbolAddress((void**)&w1s,  g_w1s);  cudaGetSymbolAddress((void**)&w1t,  g_w1t);
    cudaGetSymbolAddress((void**)&w2s,  g_w2s);  cudaGetSymbolAddress((void**)&w2t,  g_w2t);

    constexpr int SMB128 = 65536;   // 4 stages * 16KB
    constexpr int SMB64  = 49152;   // 4 stages * 12KB
    cudaFuncSetAttribute(mma_gemm<6, 2, true,  true,  128>, cudaFuncAttributeMaxDynamicSharedMemorySize, SMB128);
    cudaFuncSetAttribute(mma_gemm<3, 1, false, true,  128>, cudaFuncAttributeMaxDynamicSharedMemorySize, SMB128);
    cudaFuncSetAttribute(mma_gemm<5, 2, false, false, 64>,  cudaFuncAttributeMaxDynamicSharedMemorySize, SMB64);
    cudaFuncSetAttribute(mma_gemm<2, 0, true,  false, 128>, cudaFuncAttributeMaxDynamicSharedMemorySize, SMB128);
    cudaFuncSetAttribute(mma_gemm<1, 0, true,  true,  128>, cudaFuncAttributeMaxDynamicSharedMemorySize, SMB128);

    dim3 t1(256);
    const float* qs  = qkv;
    const float* ksp = qkv + (size_t)BN * DS;

    // 0) weight prep + accumulator zero
    prep_w<<<(768 * 768 + 255) / 256, t1>>>(Wq, wqkv,                 wqkvt,        768, 768, 768, 769);
    prep_w<<<(768 * 768 + 255) / 256, t1>>>(Wk, wqkv + 768 * 768,     wqkvt + 768,  768, 768, 768, 769);
    prep_w<<<(768 * 768 + 255) / 256, t1>>>(Wv, wqkv + 2 * 768 * 768, wqkvt + 1536, 768, 768, 768, 769);
    prep_w<<<(768 * 768 + 255) / 256, t1>>>(Wo, wos, wot, 768, 768, 768, 769);
    prep_w<<<(3071 * 768 + 255) / 256, t1>>>(W1, w1s, w1t, 3071, 768, 768, 769);
    prep_w<<<(768 * 3072 + 255) / 256, t1>>>(W2, w2s, w2t, 768, 3072, 3071, 3072);
    zero_acc<<<(3 * BH * N + 255) / 256, t1>>>();

    // 1) LN1
    ln_kernel<<<BN, t1>>>(x, 769, 1, gamma1, beta1, h1s, h1t);

    // 2) QKV — batched, with fused per-head |v|^2 (EPI6)
    mma_gemm<6, 2, true, true, 128><<<dim3(6, 64, 3), t1, SMB128>>>(
        h1s, 768, 0, wqkv, 768, (size_t)768 * 768, qkv, 768, 0, (size_t)BN * DS,
        nullptr, 0, 0, h1t, 0, wqkvt, 768, hts, nullptr, 768, 768);
    head_time2<<<(BH * N + 255) / 256, t1>>>();
    vT_kernel<<<dim3(32, 24, 8), dim3(32, 8)>>>();

    // 3) E=exp(logits) + fused rowsum/time-dot; av + normalize + concat (EPI5)
    mma_gemm<3, 1, false, true, 128><<<dim3(8, 8, BH), t1, SMB128>>>(
        ksp, 768, 0, qs, 768, 0, lt, N, 0, (size_t)N * N,
        vT, 80 * N, 0, kt, 0, qt, 0, rsE, st, N, HD);
    mma_gemm<5, 2, false, false, 64><<<dim3(1, 8, BH), t1, SMB64>>>(
        lt, N, (size_t)N * N, vT + N, N, (size_t)80 * N, atns, 0, 0, 0,
        nullptr, 0, 0, rsE, N, nullptr, 0, cts, st, 64, N);
    atnt_kernel<<<(BN + 255) / 256, t1>>>();

    // 5) Wo + residual(x)
    mma_gemm<2, 0, true, false, 128><<<dim3(6, 64), t1, SMB128>>>(
        atns, 768, 0, wos, 768, 0, out1, 768, 0, 0,
        x, 769, 1, atnt, 0, wot, 0, nullptr, nullptr, 768, 768);

    // 6) LN2
    ln_kernel<<<BN, t1>>>(out1, 768, 0, gamma2, beta2, zs, zt);

    // 7) FFN up (fast gelu + fused |v|^2 atomics), then hidt
    mma_gemm<1, 0, true, true, 128><<<dim3(24, 64), t1, SMB128>>>(
        zs, 768, 0, w1s, 768, 0, hid, M_, 0, 0,
        nullptr, 0, 0, zt, 0, w1t, 0, hsq, nullptr, 3071, 768);
    hidt_kernel<<<(BN + 255) / 256, t1>>>();

    // 8) FFN down + residual(out1) -> d_out space cols
    mma_gemm<2, 0, true, false, 128><<<dim3(6, 64), t1, SMB128>>>(
        hid, M_, 0, w2s, M_, 0, out, 769, 1, 0,
        out1, 768, 0, hidt, 0, w2t, 0, nullptr, nullptr, 768, M_);

    // 9) final add_time
    final_time_kernel<<<BN, t1>>>(out);
}

// round 14
// speedup vs baseline: 3.3616x; 1.5656x over previous
#include <cuda_runtime.h>
#include <cuda_fp16.h>
#include <math.h>
#include <stdint.h>

// ---------------------------------------------------------------------------
// LorentzTransformerEncoder  (B=8, N=1024, D=769, H=12, hd=64, M=3072)
// R14 = R13 with the MMA datapath switched tf32-m16n8k8 -> fp16-m16n8k16
//       (same 11-bit mantissa, 2x throughput, half the smem/DRAM traffic).
//       Byte-level smem layout and lane addressing unchanged.
// ---------------------------------------------------------------------------

constexpr int B  = 8;
constexpr int N  = 1024;
constexpr int DS = 768;
constexpr int H  = 12;
constexpr int HD = 64;
constexpr int M_ = 3072;
constexpr int BN = B * N;   // 8192
constexpr int BH = B * H;   // 96

// ------------------------------- scratch -----------------------------------
__device__ __half g_h1s [(size_t)BN * DS];
__device__ float  g_h1t [BN];
__device__ __half g_qkv [(size_t)3 * BN * DS];
__device__ float  g_qt  [BH * N];
__device__ float  g_kt  [BH * N];
__device__ __half g_vT  [(size_t)BH * 80 * N];  // row 0 time, rows 1..64 space^T
__device__ __half g_lt  [(size_t)BH * N * N];   // E = exp(logit), fp16
__device__ float  g_rsE [BH * N];
__device__ float  g_st  [BH * N];
__device__ float  g_hts [3 * BH * N];
__device__ float  g_cts [BN];
__device__ __half g_atns[(size_t)BN * DS];
__device__ float  g_atnt[BN];
__device__ float  g_out1[(size_t)BN * DS];
__device__ __half g_zs  [(size_t)BN * DS];
__device__ float  g_zt  [BN];
__device__ __half g_hid [(size_t)BN * M_];      // col 3071 stays 0
__device__ float  g_hsq [BN];
__device__ float  g_hidt[BN];
// fp16 weights (space part, k-major, aligned) + fp32 time columns
__device__ __half g_wqkv [(size_t)3 * 768 * 768];
__device__ float  g_wqkvt[3 * 768];
__device__ __half g_wos [768 * 768];  __device__ float g_wot [768];
__device__ __half g_w1s [3071 * 768]; __device__ float g_w1t [3071];
__device__ __half g_w2s [768 * 3072]; __device__ float g_w2t [768];

// ----------------------------- helpers --------------------------------------
__device__ __forceinline__ void ldsm4(uint32_t& r0, uint32_t& r1, uint32_t& r2,
                                      uint32_t& r3, uint32_t addr) {
    asm volatile("ldmatrix.sync.aligned.m8n8.x4.shared.b16 {%0,%1,%2,%3},[%4];"
                 : "=r"(r0), "=r"(r1), "=r"(r2), "=r"(r3) : "r"(addr));
}
__device__ __forceinline__ void mma_f16(float* c, const uint32_t* a, const uint32_t* b) {
    asm volatile("mma.sync.aligned.m16n8k16.row.col.f32.f16.f16.f32 "
                 "{%0,%1,%2,%3},{%4,%5,%6,%7},{%8,%9},{%0,%1,%2,%3};"
                 : "+f"(c[0]), "+f"(c[1]), "+f"(c[2]), "+f"(c[3])
                 : "r"(a[0]), "r"(a[1]), "r"(a[2]), "r"(a[3]), "r"(b[0]), "r"(b[1]));
}
#define CP16(d, s) \
    asm volatile("cp.async.cg.shared.global [%0],[%1],16;" :: "r"(d), "l"(s))
#define CP_COMMIT() asm volatile("cp.async.commit_group;" ::: "memory")
#define CP_WAIT2()  asm volatile("cp.async.wait_group 2;" ::: "memory")
#define CP_WAIT0()  asm volatile("cp.async.wait_group 0;" ::: "memory")

__device__ __forceinline__ float fast_tanh(float a) {
    float e2 = __expf(2.f * a);
    return __fdividef(e2 - 1.f, e2 + 1.f);
}

// one pipeline stage; k0 in HALF elements (stage covers k32)
#define ISSUE_STAGE(slot, k0)                                    \
    do {                                                         \
        uint32_t sa_ = sbase + (slot) * STG + dOff;              \
        CP16(sa_,         aSrc  + (k0));                         \
        CP16(sa_ + 4096,  aSrc2 + (k0));                         \
        CP16(sa_ + 8192,  bSrc1 + (k0));                         \
        if (NT == 128) { CP16(sa_ + 12288, bSrc2 + (k0)); }      \
        CP_COMMIT();                                             \
    } while (0)

__device__ __forceinline__ float block_reduce_sum(float v, float* sh) {
    int tid = threadIdx.x, lane = tid & 31, wid = tid >> 5;
    #pragma unroll
    for (int o = 16; o > 0; o >>= 1) v += __shfl_down_sync(0xffffffffu, v, o);
    __syncthreads();
    if (lane == 0) sh[wid] = v;
    __syncthreads();
    if (tid == 0) {
        float s = 0.f;
        #pragma unroll
        for (int w = 0; w < 8; w++) s += sh[w];
        sh[32] = s;
    }
    __syncthreads();
    return sh[32];
}

// ------------------------ weight prep (fp16 + split time) -------------------
__global__ void prep_w(const float* __restrict__ W, __half* __restrict__ Ws,
                       float* __restrict__ Wt, int rows, int cols, int kcols, int sld) {
    int idx = blockIdx.x * 256 + threadIdx.x;
    if (idx >= rows * cols) return;
    int n = idx / cols, k = idx - n * cols;
    float v = (k < kcols) ? W[(size_t)(n + 1) * sld + k + 1] : 0.f;
    Ws[idx] = __float2half_rn(v);
    if (k == 0) Wt[n] = W[(size_t)(n + 1) * sld];
}

// ------------------ zero the atomic accumulators (per launch) ---------------
__global__ void zero_acc() {
    int idx = blockIdx.x * 256 + threadIdx.x;
    if (idx < BH * N) { g_rsE[idx] = 0.f; g_st[idx] = 0.f; }
    if (idx < 3 * BH * N) g_hts[idx] = 0.f;
    if (idx < BN) { g_hsq[idx] = 0.f; g_cts[idx] = 0.f; }
}

// ------------------------- Lorentz layernorm --------------------------------
__global__ void ln_kernel(const float* __restrict__ X, int ldx, int xofs,
                          const float* __restrict__ gamma,
                          const float* __restrict__ beta,
                          __half* __restrict__ Ys, float* __restrict__ Yt) {
    __shared__ float sh[33];
    int bn = blockIdx.x, tid = threadIdx.x;
    const float* x = X + (size_t)bn * ldx + xofs;
    float v[3], s = 0.f;
    #pragma unroll
    for (int i = 0; i < 3; i++) { v[i] = x[tid + i * 256]; s += v[i]; }
    s = block_reduce_sum(s, sh);
    float mu = s * (1.f / 768.f);
    float s2 = 0.f;
    #pragma unroll
    for (int i = 0; i < 3; i++) { float dd = v[i] - mu; s2 += dd * dd; }
    s2 = block_reduce_sum(s2, sh);
    float rstd = rsqrtf(s2 * (1.f / 768.f) + 1e-5f);
    float t2 = 0.f;
    __half* ys = Ys + (size_t)bn * DS;
    #pragma unroll
    for (int i = 0; i < 3; i++) {
        int d = tid + i * 256;
        float yy = gamma[d] * (v[i] - mu) * rstd + beta[d];
        ys[d] = __float2half_rn(yy);
        t2 += yy * yy;
    }
    t2 = block_reduce_sum(t2, sh);
    if (tid == 0) Yt[bn] = sqrtf(1.f + t2);
}

// ------------------------------- fp16 GEMM ----------------------------------
// C[m][n] = sum_k A[m][k] * Bw[n][k]  (+ rank1 tA[m]*tB[n] if RK1, fp32)
// EPI: 1 gelu(+hsq, half C), 2 +R (float C), 3 exp-logit(+rowsum/time, half C),
//      5 av+normalize+concat (half C), 6 qkv(+per-head |v|^2, half C)
// BM : 0 none, 1 head-slice, 2 flat batch.  NT: 128 or 64.
// 128xNT tile, K%32==0 for KT>=3 (logits KT=2 uses in-bounds garbage prefetch),
// 4-stage cp.async (stage = k32), 256 thr, 8 warps (2m x 4n).
template<int EPI, int BM, bool RK1, int NT>
__global__ void __launch_bounds__(256, 2)
mma_gemm(const __half* __restrict__ A, int lda, size_t aBatch,
         const __half* __restrict__ Bw, int ldb, size_t bBatch,
         void* __restrict__ Cv, int ldc, int cofs, size_t cBatch,
         const void* __restrict__ R, int ldr, int rofs,
         const float* __restrict__ tA, size_t tABat,
         const float* __restrict__ tB, size_t tBBat,
         float* __restrict__ pS1, float* __restrict__ pS2,
         int Nn, int Kk) {
    constexpr int STG = (NT == 128) ? 16384 : 12288;
    constexpr int NTILES = NT / 32;
    extern __shared__ float dsm[];
    uint32_t sbase = (uint32_t)__cvta_generic_to_shared(dsm);

    int tid = threadIdx.x;
    int lane = tid & 31, wid = tid >> 5;
    int warpm = wid >> 2, warpn = wid & 3;
    int bm = blockIdx.y << 7, bnb = blockIdx.x * NT;

    const __half* Ab = A;
    const __half* Bb = Bw;
    const float* tAp = tA;
    const float* tBp = tB;
    const __half* RpH = (const __half*)R;
    float* pS1p = pS1;
    float* pS2p = pS2;
    char* Cp = (char*)Cv;
    if (BM == 1) {
        int bz = blockIdx.z;
        int b = bz / H, h = bz % H;
        Ab += (size_t)b * N * lda + h * HD;
        Bb += (size_t)b * N * ldb + h * HD;
        tAp = tA + (size_t)bz * N;
        tBp = tB + (size_t)bz * N;
        Cp += (size_t)bz * cBatch * 2;       // half C
        if (EPI == 3) {
            RpH = (const __half*)R + (size_t)bz * ldr;   // vt row (ldr=80*N)
            pS1p = pS1 + (size_t)bz * N;
            pS2p = pS2 + (size_t)bz * N;
        }
    }
    if (BM == 2) {
        int bz = blockIdx.z;
        Ab += (size_t)bz * aBatch;
        Bb += (size_t)bz * bBatch;
        Cp += (size_t)bz * cBatch * ((EPI == 2) ? 4 : 2);
        tAp = tA + (size_t)bz * tABat;
        tBp = tB + (size_t)bz * tBBat;
    }

    // ---- loader constants (byte layout identical to tf32 version) ----
    int lrow = tid >> 2, lch = tid & 3;
    uint32_t dOff = lrow * 64 + ((lch ^ ((lrow >> 1) & 3)) << 4);
    const __half* aSrc  = Ab + (size_t)(bm + lrow) * lda + lch * 8;
    const __half* aSrc2 = aSrc + (size_t)64 * lda;
    int brow1 = bnb + lrow, brow2 = brow1 + 64;
    int cb1 = (brow1 < Nn) ? brow1 : Nn - 1;
    int cb2 = (brow2 < Nn) ? brow2 : Nn - 1;
    const __half* bSrc1 = Bb + (size_t)cb1 * ldb + lch * 8;
    const __half* bSrc2 = Bb + (size_t)cb2 * ldb + lch * 8;

    // ---- ldmatrix lane addressing (same bytes; chunks now = k8 halves) ----
    int lrowA = (lane & 7) + ((lane >> 3) & 1) * 8;
    int hiA   = lane >> 4;
    int swA   = (lrowA >> 1) & 3;
    int lrowB = (lane & 7) + ((lane >> 4) & 1) * 8;
    int hiB   = (lane >> 3) & 1;
    int swB   = (lrowB >> 1) & 3;
    uint32_t aOff[2], bOff[2];
    #pragma unroll
    for (int ks = 0; ks < 2; ks++) {
        aOff[ks] = (warpm * 64 + lrowA) * 64 + (((2 * ks + hiA) ^ swA) << 4);
        bOff[ks] = 8192 + (warpn * (NT / 4) + lrowB) * 64 + (((2 * ks + hiB) ^ swB) << 4);
    }

    float acc[4][NTILES][4];
    #pragma unroll
    for (int i = 0; i < 4; i++)
        #pragma unroll
        for (int j = 0; j < NTILES; j++)
            #pragma unroll
            for (int r = 0; r < 4; r++) acc[i][j][r] = 0.f;

    int KT = Kk >> 5;                 // k32 per stage

    ISSUE_STAGE(0, 0);
    ISSUE_STAGE(1, 32);
    ISSUE_STAGE(2, 64);

    for (int kt = 0; kt < KT; kt++) {
        CP_WAIT2();
        __syncthreads();
        int st = kt & 3;
        uint32_t sb = sbase + st * STG;
        #pragma unroll
        for (int ks = 0; ks < 2; ks++) {   // two k16 mma steps per stage
            uint32_t af[4][4];
            uint32_t bf[NTILES][2];
            #pragma unroll
            for (int mt = 0; mt < 4; mt++)
                ldsm4(af[mt][0], af[mt][1], af[mt][2], af[mt][3],
                      sb + aOff[ks] + mt * 1024);
            #pragma unroll
            for (int np = 0; np < NTILES / 2; np++)
                ldsm4(bf[2 * np][0], bf[2 * np][1], bf[2 * np + 1][0], bf[2 * np + 1][1],
                      sb + bOff[ks] + np * 1024);
            #pragma unroll
            for (int mt = 0; mt < 4; mt++)
                #pragma unroll
                for (int nt = 0; nt < NTILES; nt++)
                    mma_f16(acc[mt][nt], af[mt], bf[nt]);
        }
        int nk = kt + 3;
        if (nk < KT) { ISSUE_STAGE(nk & 3, nk << 5); }
        else CP_COMMIT();
    }

    // ------------------------------ epilogue --------------------------------
    int er = bm + warpm * 64 + (lane >> 2);
    int ec0 = bnb + warpn * (NT / 4) + 2 * (lane & 3);

    if (EPI == 5) {
        CP_WAIT0();
        __syncthreads();
        float* hs = dsm;
        if (tid < 128) hs[tid] = 0.f;
        __syncthreads();
        int bz = blockIdx.z;
        int b = bz / H, h = bz % H;
        #pragma unroll
        for (int mt = 0; mt < 4; mt++)
            #pragma unroll
            for (int half_ = 0; half_ < 2; half_++) {
                int r = er + mt * 16 + half_ * 8;
                float sc = __fdividef(1.f, tAp[r]);
                float ss = 0.f;
                #pragma unroll
                for (int nt = 0; nt < NTILES; nt++) {
                    float v0 = acc[mt][nt][2 * half_] * sc;
                    float v1 = acc[mt][nt][2 * half_ + 1] * sc;
                    acc[mt][nt][2 * half_] = v0;
                    acc[mt][nt][2 * half_ + 1] = v1;
                    ss = fmaf(v0, v0, fmaf(v1, v1, ss));
                }
                ss += __shfl_down_sync(0xffffffffu, ss, 1, 4);
                ss += __shfl_down_sync(0xffffffffu, ss, 2, 4);
                if ((lane & 3) == 0) atomicAdd(&hs[r - bm], ss);
            }
        __syncthreads();
        #pragma unroll
        for (int mt = 0; mt < 4; mt++)
            #pragma unroll
            for (int half_ = 0; half_ < 2; half_++) {
                int r = er + mt * 16 + half_ * 8;
                float sc = __fdividef(1.f, tAp[r]);
                float stt = pS2[(size_t)blockIdx.z * N + r] * sc;
                float inv = rsqrtf(fmaxf(stt * stt - hs[r - bm], 1e-8f));
                __half* op = (__half*)Cv + (size_t)(b * N + r) * 768 + h * 64;
                #pragma unroll
                for (int nt = 0; nt < NTILES; nt++) {
                    int c = ec0 + nt * 8;
                    __half2 hv = __halves2half2(
                        __float2half_rn(acc[mt][nt][2 * half_] * inv),
                        __float2half_rn(acc[mt][nt][2 * half_ + 1] * inv));
                    *(__half2*)(op + c) = hv;
                }
                if (warpn == 0 && (lane & 3) == 0) {
                    float ct = stt * inv;
                    atomicAdd(&pS1[b * N + r], ct * ct);
                }
            }
        return;
    }

    float sumE[4][2], sumT[4][2], sumQ[4][2];
    if (EPI == 3 || EPI == 1 || EPI == 6) {
        #pragma unroll
        for (int i = 0; i < 4; i++)
            #pragma unroll
            for (int j = 0; j < 2; j++) { sumE[i][j] = 0.f; sumT[i][j] = 0.f; sumQ[i][j] = 0.f; }
    }
    #pragma unroll
    for (int mt = 0; mt < 4; mt++) {
        #pragma unroll
        for (int nt = 0; nt < NTILES; nt++) {
            #pragma unroll
            for (int half_ = 0; half_ < 2; half_++) {
                int r = er + mt * 16 + half_ * 8;
                int c = ec0 + nt * 8;
                bool ok0 = c < Nn, ok1 = (c + 1) < Nn;
                float v0 = acc[mt][nt][2 * half_];
                float v1 = acc[mt][nt][2 * half_ + 1];
                if (RK1) {
                    float ta = tAp[r];
                    if (ok0) v0 += ta * tBp[c];
                    if (ok1) v1 += ta * tBp[c + 1];
                }
                if (EPI == 1) {
                    float t0 = fast_tanh(0.7978845608028654f * (v0 + 0.044715f * v0 * v0 * v0));
                    v0 = 0.5f * v0 * (1.f + t0);
                    float t1 = fast_tanh(0.7978845608028654f * (v1 + 0.044715f * v1 * v1 * v1));
                    v1 = 0.5f * v1 * (1.f + t1);
                    if (ok0) sumQ[mt][half_] = fmaf(v0, v0, sumQ[mt][half_]);
                    if (ok1) sumQ[mt][half_] = fmaf(v1, v1, sumQ[mt][half_]);
                    __half* cph = (__half*)Cp + (size_t)r * ldc + cofs;
                    if (ok0) cph[c] = __float2half_rn(v0);
                    if (ok1) cph[c + 1] = __float2half_rn(v1);
                }
                if (EPI == 2) {
                    const float* rp = (const float*)R + (size_t)r * ldr + rofs;
                    if (ok0) v0 += rp[c];
                    if (ok1) v1 += rp[c + 1];
                    float* cpf = (float*)Cp + (size_t)r * ldc + cofs;
                    if (ok0) cpf[c] = v0;
                    if (ok1) cpf[c + 1] = v1;
                }
                if (EPI == 3) {
                    float kt_ = tAp[r];
                    float d20 = fmaxf(2.f * (kt_ * tBp[c] - v0 - 1.f), 1e-8f);
                    float d21 = fmaxf(2.f * (kt_ * tBp[c + 1] - v1 - 1.f), 1e-8f);
                    __half h0 = __float2half_rn(__expf(__fdividef(1.f, 1.f + __logf(1.f + d20))));
                    __half h1 = __float2half_rn(__expf(__fdividef(1.f, 1.f + __logf(1.f + d21))));
                    float e0 = __half2float(h0), e1 = __half2float(h1);
                    sumE[mt][half_] += e0 + e1;
                    sumT[mt][half_] = fmaf(e0, __half2float(RpH[c]), sumT[mt][half_]);
                    sumT[mt][half_] = fmaf(e1, __half2float(RpH[c + 1]), sumT[mt][half_]);
                    __half* cph = (__half*)Cp + (size_t)r * ldc + cofs;
                    __stcs((__half2*)(cph + c), __halves2half2(h0, h1));
                }
                if (EPI == 6) {
                    __half h0 = __float2half_rn(v0), h1 = __float2half_rn(v1);
                    float r0 = __half2float(h0), r1 = __half2float(h1);
                    sumQ[mt][half_] = fmaf(r0, r0, fmaf(r1, r1, sumQ[mt][half_]));
                    __half* cph = (__half*)Cp + (size_t)r * ldc + cofs;
                    *(__half2*)(cph + c) = __halves2half2(h0, h1);
                }
            }
        }
    }
    if (EPI == 3) {
        #pragma unroll
        for (int mt = 0; mt < 4; mt++)
            #pragma unroll
            for (int half_ = 0; half_ < 2; half_++) {
                float vE = sumE[mt][half_], vT = sumT[mt][half_];
                vE += __shfl_down_sync(0xffffffffu, vE, 1, 4);
                vE += __shfl_down_sync(0xffffffffu, vE, 2, 4);
                vT += __shfl_down_sync(0xffffffffu, vT, 1, 4);
                vT += __shfl_down_sync(0xffffffffu, vT, 2, 4);
                if ((lane & 3) == 0) {
                    int r = er + mt * 16 + half_ * 8;
                    atomicAdd(&pS1p[r], vE);
                    atomicAdd(&pS2p[r], vT);
                }
            }
    }
    if (EPI == 1) {
        #pragma unroll
        for (int mt = 0; mt < 4; mt++)
            #pragma unroll
            for (int half_ = 0; half_ < 2; half_++) {
                float vQ = sumQ[mt][half_];
                vQ += __shfl_down_sync(0xffffffffu, vQ, 1, 4);
                vQ += __shfl_down_sync(0xffffffffu, vQ, 2, 4);
                if ((lane & 3) == 0) {
                    int r = er + mt * 16 + half_ * 8;
                    atomicAdd(&pS1p[r], vQ);
                }
            }
    }
    if (EPI == 6) {
        int ghead = (bnb + warpn * 32) >> 6;
        float* hp = pS1 + (size_t)blockIdx.z * ((size_t)BH * N);
        #pragma unroll
        for (int mt = 0; mt < 4; mt++)
            #pragma unroll
            for (int half_ = 0; half_ < 2; half_++) {
                float vQ = sumQ[mt][half_];
                vQ += __shfl_down_sync(0xffffffffu, vQ, 1, 4);
                vQ += __shfl_down_sync(0xffffffffu, vQ, 2, 4);
                if ((lane & 3) == 0) {
                    int r = er + mt * 16 + half_ * 8;
                    int b_ = r >> 10, j_ = r & 1023;
                    atomicAdd(&hp[((size_t)b_ * H + ghead) * N + j_], vQ);
                }
            }
    }
}

// ---- finish per-head times from accumulated |v|^2 --------------------------
__global__ void head_time2() {
    int idx = blockIdx.x * 256 + threadIdx.x;
    if (idx >= BH * N) return;
    g_qt[idx] = sqrtf(1.f + g_hts[idx]);
    g_kt[idx] = sqrtf(1.f + g_hts[BH * N + idx]);
    int bh = idx >> 10, i = idx & 1023;
    g_vT[(size_t)bh * 80 * N + i] = __float2half_rn(sqrtf(1.f + g_hts[2 * BH * N + idx]));
}

// ------------------ V transpose to [bh][80][N] (rows 1..64) -----------------
__global__ void vT_kernel() {
    __shared__ float tile[32][33];
    int i0 = blockIdx.x << 5, d0 = blockIdx.y << 5, b = blockIdx.z;
    int tx = threadIdx.x, ty = threadIdx.y;
    const __half* vsp = g_qkv + (size_t)2 * BN * DS;
    #pragma unroll
    for (int r = 0; r < 4; r++)
        tile[ty + 8 * r][tx] = __half2float(vsp[(size_t)(b * N + i0 + ty + 8 * r) * DS + d0 + tx]);
    __syncthreads();
    #pragma unroll
    for (int r = 0; r < 4; r++) {
        int dg = d0 + ty + 8 * r;
        int h = dg >> 6, dd = dg & 63;
        g_vT[((size_t)(b * H + h) * 80 + 1 + dd) * N + i0 + tx] =
            __float2half_rn(tile[tx][ty + 8 * r]);
    }
}

// ----------------------- small finishers ------------------------------------
__global__ void hidt_kernel() {
    int idx = blockIdx.x * 256 + threadIdx.x;
    if (idx < BN) g_hidt[idx] = sqrtf(1.f + g_hsq[idx]);
}
__global__ void atnt_kernel() {
    int idx = blockIdx.x * 256 + threadIdx.x;
    if (idx < BN) g_atnt[idx] = sqrtf(g_cts[idx] - 11.f);
}

// --------------------------- final add_time ---------------------------------
__global__ void final_time_kernel(float* __restrict__ out) {
    __shared__ float sh[33];
    int bn = blockIdx.x, tid = threadIdx.x;
    float* p = out + (size_t)bn * 769;
    float s = 0.f;
    #pragma unroll
    for (int r = 0; r < 3; r++) {
        float v = p[1 + tid + r * 256];
        s = fmaf(v, v, s);
    }
    s = block_reduce_sum(s, sh);
    if (tid == 0) p[0] = sqrtf(1.f + s);
}

// ----------------------------------------------------------------------------
extern "C" void kernel_launch(void* const* d_in, const int* in_sizes, int n_in,
                              void* d_out, int out_size) {
    const float* x      = (const float*)d_in[0];
    const float* gamma1 = (const float*)d_in[1];
    const float* beta1  = (const float*)d_in[2];
    const float* Wq     = (const float*)d_in[3];
    const float* Wk     = (const float*)d_in[4];
    const float* Wv     = (const float*)d_in[5];
    const float* Wo     = (const float*)d_in[6];
    const float* gamma2 = (const float*)d_in[7];
    const float* beta2  = (const float*)d_in[8];
    const float* W1     = (const float*)d_in[9];
    const float* W2     = (const float*)d_in[10];
    float* out = (float*)d_out;

    __half *h1s, *qkv, *vT, *lt, *atns, *zs, *hid, *wqkv, *wos, *w1s, *w2s;
    float *h1t, *qt, *kt, *rsE, *st, *hts, *cts, *atnt, *out1, *zt, *hsq, *hidt;
    float *wqkvt, *wot, *w1t, *w2t;
    cudaGetSymbolAddress((void**)&h1s,  g_h1s);  cudaGetSymbolAddress((void**)&h1t,  g_h1t);
    cudaGetSymbolAddress((void**)&qkv,  g_qkv);
    cudaGetSymbolAddress((void**)&qt,   g_qt);   cudaGetSymbolAddress((void**)&kt,   g_kt);
    cudaGetSymbolAddress((void**)&vT,   g_vT);   cudaGetSymbolAddress((void**)&lt,   g_lt);
    cudaGetSymbolAddress((void**)&rsE,  g_rsE);  cudaGetSymbolAddress((void**)&st,   g_st);
    cudaGetSymbolAddress((void**)&hts,  g_hts);  cudaGetSymbolAddress((void**)&cts,  g_cts);
    cudaGetSymbolAddress((void**)&atns, g_atns); cudaGetSymbolAddress((void**)&atnt, g_atnt);
    cudaGetSymbolAddress((void**)&out1, g_out1);
    cudaGetSymbolAddress((void**)&zs,   g_zs);   cudaGetSymbolAddress((void**)&zt,   g_zt);
    cudaGetSymbolAddress((void**)&hid,  g_hid);  cudaGetSymbolAddress((void**)&hsq,  g_hsq);
    cudaGetSymbolAddress((void**)&hidt, g_hidt);
    cudaGetSymbolAddress((void**)&wqkv, g_wqkv); cudaGetSymbolAddress((void**)&wqkvt, g_wqkvt);
    cudaGetSymbolAddress((void**)&wos,  g_wos);  cudaGetSymbolAddress((void**)&wot,  g_wot);
    cudaGetSymbolAddress((void**)&w1s,  g_w1s);  cudaGetSymbolAddress((void**)&w1t,  g_w1t);
    cudaGetSymbolAddress((void**)&w2s,  g_w2s);  cudaGetSymbolAddress((void**)&w2t,  g_w2t);

    constexpr int SMB128 = 65536;
    constexpr int SMB64  = 49152;
    cudaFuncSetAttribute(mma_gemm<6, 2, true,  128>, cudaFuncAttributeMaxDynamicSharedMemorySize, SMB128);
    cudaFuncSetAttribute(mma_gemm<3, 1, false, 128>, cudaFuncAttributeMaxDynamicSharedMemorySize, SMB128);
    cudaFuncSetAttribute(mma_gemm<5, 2, false, 64>,  cudaFuncAttributeMaxDynamicSharedMemorySize, SMB64);
    cudaFuncSetAttribute(mma_gemm<2, 0, true,  128>, cudaFuncAttributeMaxDynamicSharedMemorySize, SMB128);
    cudaFuncSetAttribute(mma_gemm<1, 0, true,  128>, cudaFuncAttributeMaxDynamicSharedMemorySize, SMB128);

    dim3 t1(256);
    const __half* qs  = qkv;
    const __half* ksp = qkv + (size_t)BN * DS;

    // 0) weight prep + accumulator zero
    prep_w<<<(768 * 768 + 255) / 256, t1>>>(Wq, wqkv,                 wqkvt,        768, 768, 768, 769);
    prep_w<<<(768 * 768 + 255) / 256, t1>>>(Wk, wqkv + 768 * 768,     wqkvt + 768,  768, 768, 768, 769);
    prep_w<<<(768 * 768 + 255) / 256, t1>>>(Wv, wqkv + 2 * 768 * 768, wqkvt + 1536, 768, 768, 768, 769);
    prep_w<<<(768 * 768 + 255) / 256, t1>>>(Wo, wos, wot, 768, 768, 768, 769);
    prep_w<<<(3071 * 768 + 255) / 256, t1>>>(W1, w1s, w1t, 3071, 768, 768, 769);
    prep_w<<<(768 * 3072 + 255) / 256, t1>>>(W2, w2s, w2t, 768, 3072, 3071, 3072);
    zero_acc<<<(3 * BH * N + 255) / 256, t1>>>();

    // 1) LN1
    ln_kernel<<<BN, t1>>>(x, 769, 1, gamma1, beta1, h1s, h1t);

    // 2) QKV — batched, fused per-head |v|^2 (EPI6)
    mma_gemm<6, 2, true, 128><<<dim3(6, 64, 3), t1, SMB128>>>(
        h1s, 768, 0, wqkv, 768, (size_t)768 * 768, qkv, 768, 0, (size_t)BN * DS,
        nullptr, 0, 0, h1t, 0, wqkvt, 768, hts, nullptr, 768, 768);
    head_time2<<<(BH * N + 255) / 256, t1>>>();
    vT_kernel<<<dim3(32, 24, 8), dim3(32, 8)>>>();

    // 3) E=exp(logits) + fused rowsum/time-dot; av + normalize + concat (EPI5)
    mma_gemm<3, 1, false, 128><<<dim3(8, 8, BH), t1, SMB128>>>(
        ksp, 768, 0, qs, 768, 0, lt, N, 0, (size_t)N * N,
        vT, 80 * N, 0, kt, 0, qt, 0, rsE, st, N, HD);
    mma_gemm<5, 2, false, 64><<<dim3(1, 8, BH), t1, SMB64>>>(
        lt, N, (size_t)N * N, vT + N, N, (size_t)80 * N, atns, 0, 0, 0,
        nullptr, 0, 0, rsE, N, nullptr, 0, cts, st, 64, N);
    atnt_kernel<<<(BN + 255) / 256, t1>>>();

    // 5) Wo + residual(x)
    mma_gemm<2, 0, true, 128><<<dim3(6, 64), t1, SMB128>>>(
        atns, 768, 0, wos, 768, 0, out1, 768, 0, 0,
        x, 769, 1, atnt, 0, wot, 0, nullptr, nullptr, 768, 768);

    // 6) LN2
    ln_kernel<<<BN, t1>>>(out1, 768, 0, gamma2, beta2, zs, zt);

    // 7) FFN up (fast gelu + fused |v|^2), then hidt
    mma_gemm<1, 0, true, 128><<<dim3(24, 64), t1, SMB128>>>(
        zs, 768, 0, w1s, 768, 0, hid, M_, 0, 0,
        nullptr, 0, 0, zt, 0, w1t, 0, hsq, nullptr, 3071, 768);
    hidt_kernel<<<(BN + 255) / 256, t1>>>();

    // 8) FFN down + residual(out1) -> d_out space cols
    mma_gemm<2, 0, true, 128><<<dim3(6, 64), t1, SMB128>>>(
        hid, M_, 0, w2s, M_, 0, out, 769, 1, 0,
        out1, 768, 0, hidt, 0, w2t, 0, nullptr, nullptr, 768, M_);

    // 9) final add_time
    final_time_kernel<<<BN, t1>>>(out);
}

// round 15
// speedup vs baseline: 3.4175x; 1.0167x over previous
#include <cuda_runtime.h>
#include <cuda_fp16.h>
#include <math.h>
#include <stdint.h>

// ---------------------------------------------------------------------------
// LorentzTransformerEncoder  (B=8, N=1024, D=769, H=12, hd=64, M=3072)
// R15 = R14 + single fused prep_all kernel (6x prep_w + zero_acc -> 1 launch).
//       fp16 m16n8k16 MMA datapath unchanged.
// ---------------------------------------------------------------------------

constexpr int B  = 8;
constexpr int N  = 1024;
constexpr int DS = 768;
constexpr int H  = 12;
constexpr int HD = 64;
constexpr int M_ = 3072;
constexpr int BN = B * N;   // 8192
constexpr int BH = B * H;   // 96

// ------------------------------- scratch -----------------------------------
__device__ __half g_h1s [(size_t)BN * DS];
__device__ float  g_h1t [BN];
__device__ __half g_qkv [(size_t)3 * BN * DS];
__device__ float  g_qt  [BH * N];
__device__ float  g_kt  [BH * N];
__device__ __half g_vT  [(size_t)BH * 80 * N];  // row 0 time, rows 1..64 space^T
__device__ __half g_lt  [(size_t)BH * N * N];   // E = exp(logit), fp16
__device__ float  g_rsE [BH * N];
__device__ float  g_st  [BH * N];
__device__ float  g_hts [3 * BH * N];
__device__ float  g_cts [BN];
__device__ __half g_atns[(size_t)BN * DS];
__device__ float  g_atnt[BN];
__device__ float  g_out1[(size_t)BN * DS];
__device__ __half g_zs  [(size_t)BN * DS];
__device__ float  g_zt  [BN];
__device__ __half g_hid [(size_t)BN * M_];      // col 3071 stays 0
__device__ float  g_hsq [BN];
__device__ float  g_hidt[BN];
// fp16 weights (space part, k-major, aligned) + fp32 time columns
__device__ __half g_wqkv [(size_t)3 * 768 * 768];
__device__ float  g_wqkvt[3 * 768];
__device__ __half g_wos [768 * 768];  __device__ float g_wot [768];
__device__ __half g_w1s [3071 * 768]; __device__ float g_w1t [3071];
__device__ __half g_w2s [768 * 3072]; __device__ float g_w2t [768];

// ----------------------------- helpers --------------------------------------
__device__ __forceinline__ void ldsm4(uint32_t& r0, uint32_t& r1, uint32_t& r2,
                                      uint32_t& r3, uint32_t addr) {
    asm volatile("ldmatrix.sync.aligned.m8n8.x4.shared.b16 {%0,%1,%2,%3},[%4];"
                 : "=r"(r0), "=r"(r1), "=r"(r2), "=r"(r3) : "r"(addr));
}
__device__ __forceinline__ void mma_f16(float* c, const uint32_t* a, const uint32_t* b) {
    asm volatile("mma.sync.aligned.m16n8k16.row.col.f32.f16.f16.f32 "
                 "{%0,%1,%2,%3},{%4,%5,%6,%7},{%8,%9},{%0,%1,%2,%3};"
                 : "+f"(c[0]), "+f"(c[1]), "+f"(c[2]), "+f"(c[3])
                 : "r"(a[0]), "r"(a[1]), "r"(a[2]), "r"(a[3]), "r"(b[0]), "r"(b[1]));
}
#define CP16(d, s) \
    asm volatile("cp.async.cg.shared.global [%0],[%1],16;" :: "r"(d), "l"(s))
#define CP_COMMIT() asm volatile("cp.async.commit_group;" ::: "memory")
#define CP_WAIT2()  asm volatile("cp.async.wait_group 2;" ::: "memory")
#define CP_WAIT0()  asm volatile("cp.async.wait_group 0;" ::: "memory")

__device__ __forceinline__ float fast_tanh(float a) {
    float e2 = __expf(2.f * a);
    return __fdividef(e2 - 1.f, e2 + 1.f);
}

// one pipeline stage; k0 in HALF elements (stage covers k32)
#define ISSUE_STAGE(slot, k0)                                    \
    do {                                                         \
        uint32_t sa_ = sbase + (slot) * STG + dOff;              \
        CP16(sa_,         aSrc  + (k0));                         \
        CP16(sa_ + 4096,  aSrc2 + (k0));                         \
        CP16(sa_ + 8192,  bSrc1 + (k0));                         \
        if (NT == 128) { CP16(sa_ + 12288, bSrc2 + (k0)); }      \
        CP_COMMIT();                                             \
    } while (0)

__device__ __forceinline__ float block_reduce_sum(float v, float* sh) {
    int tid = threadIdx.x, lane = tid & 31, wid = tid >> 5;
    #pragma unroll
    for (int o = 16; o > 0; o >>= 1) v += __shfl_down_sync(0xffffffffu, v, o);
    __syncthreads();
    if (lane == 0) sh[wid] = v;
    __syncthreads();
    if (tid == 0) {
        float s = 0.f;
        #pragma unroll
        for (int w = 0; w < 8; w++) s += sh[w];
        sh[32] = s;
    }
    __syncthreads();
    return sh[32];
}

// -------- fused prep: all weights (fp16 + time split) + accumulator zero ----
// index ranges (elements):
//   [0, 1769472)          Wq|Wk|Wv  (3 x 768x768, sld 769)
//   [1769472, 2359296)    Wo        (768x768,  sld 769)
//   [2359296, 4717824)    W1        (3071x768, sld 769)
//   [4717824, 7077120)    W2        (768x3072, kcols 3071, sld 3072)
__global__ void prep_all(const float* __restrict__ Wq, const float* __restrict__ Wk,
                         const float* __restrict__ Wv, const float* __restrict__ Wo,
                         const float* __restrict__ W1, const float* __restrict__ W2) {
    int idx = blockIdx.x * 256 + threadIdx.x;
    // accumulator zeroing (disjoint from prep logic, same launch)
    if (idx < 3 * BH * N) g_hts[idx] = 0.f;
    if (idx < BH * N) { g_rsE[idx] = 0.f; g_st[idx] = 0.f; }
    if (idx < BN) { g_hsq[idx] = 0.f; g_cts[idx] = 0.f; }

    if (idx < 1769472) {
        int which = idx / 589824;
        int rem = idx - which * 589824;
        int n = rem / 768, k = rem - n * 768;
        const float* W = (which == 0) ? Wq : (which == 1) ? Wk : Wv;
        g_wqkv[idx] = __float2half_rn(W[(size_t)(n + 1) * 769 + k + 1]);
        if (k == 0) g_wqkvt[which * 768 + n] = W[(size_t)(n + 1) * 769];
    } else if (idx < 2359296) {
        int rem = idx - 1769472;
        int n = rem / 768, k = rem - n * 768;
        g_wos[rem] = __float2half_rn(Wo[(size_t)(n + 1) * 769 + k + 1]);
        if (k == 0) g_wot[n] = Wo[(size_t)(n + 1) * 769];
    } else if (idx < 4717824) {
        int rem = idx - 2359296;
        int n = rem / 768, k = rem - n * 768;
        g_w1s[rem] = __float2half_rn(W1[(size_t)(n + 1) * 769 + k + 1]);
        if (k == 0) g_w1t[n] = W1[(size_t)(n + 1) * 769];
    } else if (idx < 7077120) {
        int rem = idx - 4717824;
        int n = rem / 3072, k = rem - n * 3072;
        float v = (k < 3071) ? W2[(size_t)(n + 1) * 3072 + k + 1] : 0.f;
        g_w2s[rem] = __float2half_rn(v);
        if (k == 0) g_w2t[n] = W2[(size_t)(n + 1) * 3072];
    }
}

// ------------------------- Lorentz layernorm --------------------------------
__global__ void ln_kernel(const float* __restrict__ X, int ldx, int xofs,
                          const float* __restrict__ gamma,
                          const float* __restrict__ beta,
                          __half* __restrict__ Ys, float* __restrict__ Yt) {
    __shared__ float sh[33];
    int bn = blockIdx.x, tid = threadIdx.x;
    const float* x = X + (size_t)bn * ldx + xofs;
    float v[3], s = 0.f;
    #pragma unroll
    for (int i = 0; i < 3; i++) { v[i] = x[tid + i * 256]; s += v[i]; }
    s = block_reduce_sum(s, sh);
    float mu = s * (1.f / 768.f);
    float s2 = 0.f;
    #pragma unroll
    for (int i = 0; i < 3; i++) { float dd = v[i] - mu; s2 += dd * dd; }
    s2 = block_reduce_sum(s2, sh);
    float rstd = rsqrtf(s2 * (1.f / 768.f) + 1e-5f);
    float t2 = 0.f;
    __half* ys = Ys + (size_t)bn * DS;
    #pragma unroll
    for (int i = 0; i < 3; i++) {
        int d = tid + i * 256;
        float yy = gamma[d] * (v[i] - mu) * rstd + beta[d];
        ys[d] = __float2half_rn(yy);
        t2 += yy * yy;
    }
    t2 = block_reduce_sum(t2, sh);
    if (tid == 0) Yt[bn] = sqrtf(1.f + t2);
}

// ------------------------------- fp16 GEMM ----------------------------------
// C[m][n] = sum_k A[m][k] * Bw[n][k]  (+ rank1 tA[m]*tB[n] if RK1, fp32)
// EPI: 1 gelu(+hsq, half C), 2 +R (float C), 3 exp-logit(+rowsum/time, half C),
//      5 av+normalize+concat (half C), 6 qkv(+per-head |v|^2, half C)
// BM : 0 none, 1 head-slice, 2 flat batch.  NT: 128 or 64.
template<int EPI, int BM, bool RK1, int NT>
__global__ void __launch_bounds__(256, 2)
mma_gemm(const __half* __restrict__ A, int lda, size_t aBatch,
         const __half* __restrict__ Bw, int ldb, size_t bBatch,
         void* __restrict__ Cv, int ldc, int cofs, size_t cBatch,
         const void* __restrict__ R, int ldr, int rofs,
         const float* __restrict__ tA, size_t tABat,
         const float* __restrict__ tB, size_t tBBat,
         float* __restrict__ pS1, float* __restrict__ pS2,
         int Nn, int Kk) {
    constexpr int STG = (NT == 128) ? 16384 : 12288;
    constexpr int NTILES = NT / 32;
    extern __shared__ float dsm[];
    uint32_t sbase = (uint32_t)__cvta_generic_to_shared(dsm);

    int tid = threadIdx.x;
    int lane = tid & 31, wid = tid >> 5;
    int warpm = wid >> 2, warpn = wid & 3;
    int bm = blockIdx.y << 7, bnb = blockIdx.x * NT;

    const __half* Ab = A;
    const __half* Bb = Bw;
    const float* tAp = tA;
    const float* tBp = tB;
    const __half* RpH = (const __half*)R;
    float* pS1p = pS1;
    float* pS2p = pS2;
    char* Cp = (char*)Cv;
    if (BM == 1) {
        int bz = blockIdx.z;
        int b = bz / H, h = bz % H;
        Ab += (size_t)b * N * lda + h * HD;
        Bb += (size_t)b * N * ldb + h * HD;
        tAp = tA + (size_t)bz * N;
        tBp = tB + (size_t)bz * N;
        Cp += (size_t)bz * cBatch * 2;
        if (EPI == 3) {
            RpH = (const __half*)R + (size_t)bz * ldr;
            pS1p = pS1 + (size_t)bz * N;
            pS2p = pS2 + (size_t)bz * N;
        }
    }
    if (BM == 2) {
        int bz = blockIdx.z;
        Ab += (size_t)bz * aBatch;
        Bb += (size_t)bz * bBatch;
        Cp += (size_t)bz * cBatch * ((EPI == 2) ? 4 : 2);
        tAp = tA + (size_t)bz * tABat;
        tBp = tB + (size_t)bz * tBBat;
    }

    // ---- loader constants ----
    int lrow = tid >> 2, lch = tid & 3;
    uint32_t dOff = lrow * 64 + ((lch ^ ((lrow >> 1) & 3)) << 4);
    const __half* aSrc  = Ab + (size_t)(bm + lrow) * lda + lch * 8;
    const __half* aSrc2 = aSrc + (size_t)64 * lda;
    int brow1 = bnb + lrow, brow2 = brow1 + 64;
    int cb1 = (brow1 < Nn) ? brow1 : Nn - 1;
    int cb2 = (brow2 < Nn) ? brow2 : Nn - 1;
    const __half* bSrc1 = Bb + (size_t)cb1 * ldb + lch * 8;
    const __half* bSrc2 = Bb + (size_t)cb2 * ldb + lch * 8;

    // ---- ldmatrix lane addressing ----
    int lrowA = (lane & 7) + ((lane >> 3) & 1) * 8;
    int hiA   = lane >> 4;
    int swA   = (lrowA >> 1) & 3;
    int lrowB = (lane & 7) + ((lane >> 4) & 1) * 8;
    int hiB   = (lane >> 3) & 1;
    int swB   = (lrowB >> 1) & 3;
    uint32_t aOff[2], bOff[2];
    #pragma unroll
    for (int ks = 0; ks < 2; ks++) {
        aOff[ks] = (warpm * 64 + lrowA) * 64 + (((2 * ks + hiA) ^ swA) << 4);
        bOff[ks] = 8192 + (warpn * (NT / 4) + lrowB) * 64 + (((2 * ks + hiB) ^ swB) << 4);
    }

    float acc[4][NTILES][4];
    #pragma unroll
    for (int i = 0; i < 4; i++)
        #pragma unroll
        for (int j = 0; j < NTILES; j++)
            #pragma unroll
            for (int r = 0; r < 4; r++) acc[i][j][r] = 0.f;

    int KT = Kk >> 5;

    ISSUE_STAGE(0, 0);
    ISSUE_STAGE(1, 32);
    ISSUE_STAGE(2, 64);

    for (int kt = 0; kt < KT; kt++) {
        CP_WAIT2();
        __syncthreads();
        int st = kt & 3;
        uint32_t sb = sbase + st * STG;
        #pragma unroll
        for (int ks = 0; ks < 2; ks++) {
            uint32_t af[4][4];
            uint32_t bf[NTILES][2];
            #pragma unroll
            for (int mt = 0; mt < 4; mt++)
                ldsm4(af[mt][0], af[mt][1], af[mt][2], af[mt][3],
                      sb + aOff[ks] + mt * 1024);
            #pragma unroll
            for (int np = 0; np < NTILES / 2; np++)
                ldsm4(bf[2 * np][0], bf[2 * np][1], bf[2 * np + 1][0], bf[2 * np + 1][1],
                      sb + bOff[ks] + np * 1024);
            #pragma unroll
            for (int mt = 0; mt < 4; mt++)
                #pragma unroll
                for (int nt = 0; nt < NTILES; nt++)
                    mma_f16(acc[mt][nt], af[mt], bf[nt]);
        }
        int nk = kt + 3;
        if (nk < KT) { ISSUE_STAGE(nk & 3, nk << 5); }
        else CP_COMMIT();
    }

    // ------------------------------ epilogue --------------------------------
    int er = bm + warpm * 64 + (lane >> 2);
    int ec0 = bnb + warpn * (NT / 4) + 2 * (lane & 3);

    if (EPI == 5) {
        CP_WAIT0();
        __syncthreads();
        float* hs = dsm;
        if (tid < 128) hs[tid] = 0.f;
        __syncthreads();
        int bz = blockIdx.z;
        int b = bz / H, h = bz % H;
        #pragma unroll
        for (int mt = 0; mt < 4; mt++)
            #pragma unroll
            for (int half_ = 0; half_ < 2; half_++) {
                int r = er + mt * 16 + half_ * 8;
                float sc = __fdividef(1.f, tAp[r]);
                float ss = 0.f;
                #pragma unroll
                for (int nt = 0; nt < NTILES; nt++) {
                    float v0 = acc[mt][nt][2 * half_] * sc;
                    float v1 = acc[mt][nt][2 * half_ + 1] * sc;
                    acc[mt][nt][2 * half_] = v0;
                    acc[mt][nt][2 * half_ + 1] = v1;
                    ss = fmaf(v0, v0, fmaf(v1, v1, ss));
                }
                ss += __shfl_down_sync(0xffffffffu, ss, 1, 4);
                ss += __shfl_down_sync(0xffffffffu, ss, 2, 4);
                if ((lane & 3) == 0) atomicAdd(&hs[r - bm], ss);
            }
        __syncthreads();
        #pragma unroll
        for (int mt = 0; mt < 4; mt++)
            #pragma unroll
            for (int half_ = 0; half_ < 2; half_++) {
                int r = er + mt * 16 + half_ * 8;
                float sc = __fdividef(1.f, tAp[r]);
                float stt = pS2[(size_t)blockIdx.z * N + r] * sc;
                float inv = rsqrtf(fmaxf(stt * stt - hs[r - bm], 1e-8f));
                __half* op = (__half*)Cv + (size_t)(b * N + r) * 768 + h * 64;
                #pragma unroll
                for (int nt = 0; nt < NTILES; nt++) {
                    int c = ec0 + nt * 8;
                    __half2 hv = __halves2half2(
                        __float2half_rn(acc[mt][nt][2 * half_] * inv),
                        __float2half_rn(acc[mt][nt][2 * half_ + 1] * inv));
                    *(__half2*)(op + c) = hv;
                }
                if (warpn == 0 && (lane & 3) == 0) {
                    float ct = stt * inv;
                    atomicAdd(&pS1[b * N + r], ct * ct);
                }
            }
        return;
    }

    float sumE[4][2], sumT[4][2], sumQ[4][2];
    if (EPI == 3 || EPI == 1 || EPI == 6) {
        #pragma unroll
        for (int i = 0; i < 4; i++)
            #pragma unroll
            for (int j = 0; j < 2; j++) { sumE[i][j] = 0.f; sumT[i][j] = 0.f; sumQ[i][j] = 0.f; }
    }
    #pragma unroll
    for (int mt = 0; mt < 4; mt++) {
        #pragma unroll
        for (int nt = 0; nt < NTILES; nt++) {
            #pragma unroll
            for (int half_ = 0; half_ < 2; half_++) {
                int r = er + mt * 16 + half_ * 8;
                int c = ec0 + nt * 8;
                bool ok0 = c < Nn, ok1 = (c + 1) < Nn;
                float v0 = acc[mt][nt][2 * half_];
                float v1 = acc[mt][nt][2 * half_ + 1];
                if (RK1) {
                    float ta = tAp[r];
                    if (ok0) v0 += ta * tBp[c];
                    if (ok1) v1 += ta * tBp[c + 1];
                }
                if (EPI == 1) {
                    float t0 = fast_tanh(0.7978845608028654f * (v0 + 0.044715f * v0 * v0 * v0));
                    v0 = 0.5f * v0 * (1.f + t0);
                    float t1 = fast_tanh(0.7978845608028654f * (v1 + 0.044715f * v1 * v1 * v1));
                    v1 = 0.5f * v1 * (1.f + t1);
                    if (ok0) sumQ[mt][half_] = fmaf(v0, v0, sumQ[mt][half_]);
                    if (ok1) sumQ[mt][half_] = fmaf(v1, v1, sumQ[mt][half_]);
                    __half* cph = (__half*)Cp + (size_t)r * ldc + cofs;
                    if (ok0) cph[c] = __float2half_rn(v0);
                    if (ok1) cph[c + 1] = __float2half_rn(v1);
                }
                if (EPI == 2) {
                    const float* rp = (const float*)R + (size_t)r * ldr + rofs;
                    if (ok0) v0 += rp[c];
                    if (ok1) v1 += rp[c + 1];
                    float* cpf = (float*)Cp + (size_t)r * ldc + cofs;
                    if (ok0) cpf[c] = v0;
                    if (ok1) cpf[c + 1] = v1;
                }
                if (EPI == 3) {
                    float kt_ = tAp[r];
                    float d20 = fmaxf(2.f * (kt_ * tBp[c] - v0 - 1.f), 1e-8f);
                    float d21 = fmaxf(2.f * (kt_ * tBp[c + 1] - v1 - 1.f), 1e-8f);
                    __half h0 = __float2half_rn(__expf(__fdividef(1.f, 1.f + __logf(1.f + d20))));
                    __half h1 = __float2half_rn(__expf(__fdividef(1.f, 1.f + __logf(1.f + d21))));
                    float e0 = __half2float(h0), e1 = __half2float(h1);
                    sumE[mt][half_] += e0 + e1;
                    sumT[mt][half_] = fmaf(e0, __half2float(RpH[c]), sumT[mt][half_]);
                    sumT[mt][half_] = fmaf(e1, __half2float(RpH[c + 1]), sumT[mt][half_]);
                    __half* cph = (__half*)Cp + (size_t)r * ldc + cofs;
                    __stcs((__half2*)(cph + c), __halves2half2(h0, h1));
                }
                if (EPI == 6) {
                    __half h0 = __float2half_rn(v0), h1 = __float2half_rn(v1);
                    float r0 = __half2float(h0), r1 = __half2float(h1);
                    sumQ[mt][half_] = fmaf(r0, r0, fmaf(r1, r1, sumQ[mt][half_]));
                    __half* cph = (__half*)Cp + (size_t)r * ldc + cofs;
                    *(__half2*)(cph + c) = __halves2half2(h0, h1);
                }
            }
        }
    }
    if (EPI == 3) {
        #pragma unroll
        for (int mt = 0; mt < 4; mt++)
            #pragma unroll
            for (int half_ = 0; half_ < 2; half_++) {
                float vE = sumE[mt][half_], vT = sumT[mt][half_];
                vE += __shfl_down_sync(0xffffffffu, vE, 1, 4);
                vE += __shfl_down_sync(0xffffffffu, vE, 2, 4);
                vT += __shfl_down_sync(0xffffffffu, vT, 1, 4);
                vT += __shfl_down_sync(0xffffffffu, vT, 2, 4);
                if ((lane & 3) == 0) {
                    int r = er + mt * 16 + half_ * 8;
                    atomicAdd(&pS1p[r], vE);
                    atomicAdd(&pS2p[r], vT);
                }
            }
    }
    if (EPI == 1) {
        #pragma unroll
        for (int mt = 0; mt < 4; mt++)
            #pragma unroll
            for (int half_ = 0; half_ < 2; half_++) {
                float vQ = sumQ[mt][half_];
                vQ += __shfl_down_sync(0xffffffffu, vQ, 1, 4);
                vQ += __shfl_down_sync(0xffffffffu, vQ, 2, 4);
                if ((lane & 3) == 0) {
                    int r = er + mt * 16 + half_ * 8;
                    atomicAdd(&pS1p[r], vQ);
                }
            }
    }
    if (EPI == 6) {
        int ghead = (bnb + warpn * 32) >> 6;
        float* hp = pS1 + (size_t)blockIdx.z * ((size_t)BH * N);
        #pragma unroll
        for (int mt = 0; mt < 4; mt++)
            #pragma unroll
            for (int half_ = 0; half_ < 2; half_++) {
                float vQ = sumQ[mt][half_];
                vQ += __shfl_down_sync(0xffffffffu, vQ, 1, 4);
                vQ += __shfl_down_sync(0xffffffffu, vQ, 2, 4);
                if ((lane & 3) == 0) {
                    int r = er + mt * 16 + half_ * 8;
                    int b_ = r >> 10, j_ = r & 1023;
                    atomicAdd(&hp[((size_t)b_ * H + ghead) * N + j_], vQ);
                }
            }
    }
}

// ---- finish per-head times from accumulated |v|^2 --------------------------
__global__ void head_time2() {
    int idx = blockIdx.x * 256 + threadIdx.x;
    if (idx >= BH * N) return;
    g_qt[idx] = sqrtf(1.f + g_hts[idx]);
    g_kt[idx] = sqrtf(1.f + g_hts[BH * N + idx]);
    int bh = idx >> 10, i = idx & 1023;
    g_vT[(size_t)bh * 80 * N + i] = __float2half_rn(sqrtf(1.f + g_hts[2 * BH * N + idx]));
}

// ------------------ V transpose to [bh][80][N] (rows 1..64) -----------------
__global__ void vT_kernel() {
    __shared__ float tile[32][33];
    int i0 = blockIdx.x << 5, d0 = blockIdx.y << 5, b = blockIdx.z;
    int tx = threadIdx.x, ty = threadIdx.y;
    const __half* vsp = g_qkv + (size_t)2 * BN * DS;
    #pragma unroll
    for (int r = 0; r < 4; r++)
        tile[ty + 8 * r][tx] = __half2float(vsp[(size_t)(b * N + i0 + ty + 8 * r) * DS + d0 + tx]);
    __syncthreads();
    #pragma unroll
    for (int r = 0; r < 4; r++) {
        int dg = d0 + ty + 8 * r;
        int h = dg >> 6, dd = dg & 63;
        g_vT[((size_t)(b * H + h) * 80 + 1 + dd) * N + i0 + tx] =
            __float2half_rn(tile[tx][ty + 8 * r]);
    }
}

// ----------------------- small finishers ------------------------------------
__global__ void hidt_kernel() {
    int idx = blockIdx.x * 256 + threadIdx.x;
    if (idx < BN) g_hidt[idx] = sqrtf(1.f + g_hsq[idx]);
}
__global__ void atnt_kernel() {
    int idx = blockIdx.x * 256 + threadIdx.x;
    if (idx < BN) g_atnt[idx] = sqrtf(g_cts[idx] - 11.f);
}

// --------------------------- final add_time ---------------------------------
__global__ void final_time_kernel(float* __restrict__ out) {
    __shared__ float sh[33];
    int bn = blockIdx.x, tid = threadIdx.x;
    float* p = out + (size_t)bn * 769;
    float s = 0.f;
    #pragma unroll
    for (int r = 0; r < 3; r++) {
        float v = p[1 + tid + r * 256];
        s = fmaf(v, v, s);
    }
    s = block_reduce_sum(s, sh);
    if (tid == 0) p[0] = sqrtf(1.f + s);
}

// ----------------------------------------------------------------------------
extern "C" void kernel_launch(void* const* d_in, const int* in_sizes, int n_in,
                              void* d_out, int out_size) {
    const float* x      = (const float*)d_in[0];
    const float* gamma1 = (const float*)d_in[1];
    const float* beta1  = (const float*)d_in[2];
    const float* Wq     = (const float*)d_in[3];
    const float* Wk     = (const float*)d_in[4];
    const float* Wv     = (const float*)d_in[5];
    const float* Wo     = (const float*)d_in[6];
    const float* gamma2 = (const float*)d_in[7];
    const float* beta2  = (const float*)d_in[8];
    const float* W1     = (const float*)d_in[9];
    const float* W2     = (const float*)d_in[10];
    float* out = (float*)d_out;

    __half *h1s, *qkv, *vT, *lt, *atns, *zs, *hid, *wqkv, *wos, *w1s, *w2s;
    float *h1t, *qt, *kt, *rsE, *st, *hts, *cts, *atnt, *out1, *zt, *hsq, *hidt;
    float *wqkvt, *wot, *w1t, *w2t;
    cudaGetSymbolAddress((void**)&h1s,  g_h1s);  cudaGetSymbolAddress((void**)&h1t,  g_h1t);
    cudaGetSymbolAddress((void**)&qkv,  g_qkv);
    cudaGetSymbolAddress((void**)&qt,   g_qt);   cudaGetSymbolAddress((void**)&kt,   g_kt);
    cudaGetSymbolAddress((void**)&vT,   g_vT);   cudaGetSymbolAddress((void**)&lt,   g_lt);
    cudaGetSymbolAddress((void**)&rsE,  g_rsE);  cudaGetSymbolAddress((void**)&st,   g_st);
    cudaGetSymbolAddress((void**)&hts,  g_hts);  cudaGetSymbolAddress((void**)&cts,  g_cts);
    cudaGetSymbolAddress((void**)&atns, g_atns); cudaGetSymbolAddress((void**)&atnt, g_atnt);
    cudaGetSymbolAddress((void**)&out1, g_out1);
    cudaGetSymbolAddress((void**)&zs,   g_zs);   cudaGetSymbolAddress((void**)&zt,   g_zt);
    cudaGetSymbolAddress((void**)&hid,  g_hid);  cudaGetSymbolAddress((void**)&hsq,  g_hsq);
    cudaGetSymbolAddress((void**)&hidt, g_hidt);
    cudaGetSymbolAddress((void**)&wqkv, g_wqkv); cudaGetSymbolAddress((void**)&wqkvt, g_wqkvt);
    cudaGetSymbolAddress((void**)&wos,  g_wos);  cudaGetSymbolAddress((void**)&wot,  g_wot);
    cudaGetSymbolAddress((void**)&w1s,  g_w1s);  cudaGetSymbolAddress((void**)&w1t,  g_w1t);
    cudaGetSymbolAddress((void**)&w2s,  g_w2s);  cudaGetSymbolAddress((void**)&w2t,  g_w2t);

    constexpr int SMB128 = 65536;
    constexpr int SMB64  = 49152;
    cudaFuncSetAttribute(mma_gemm<6, 2, true,  128>, cudaFuncAttributeMaxDynamicSharedMemorySize, SMB128);
    cudaFuncSetAttribute(mma_gemm<3, 1, false, 128>, cudaFuncAttributeMaxDynamicSharedMemorySize, SMB128);
    cudaFuncSetAttribute(mma_gemm<5, 2, false, 64>,  cudaFuncAttributeMaxDynamicSharedMemorySize, SMB64);
    cudaFuncSetAttribute(mma_gemm<2, 0, true,  128>, cudaFuncAttributeMaxDynamicSharedMemorySize, SMB128);
    cudaFuncSetAttribute(mma_gemm<1, 0, true,  128>, cudaFuncAttributeMaxDynamicSharedMemorySize, SMB128);

    dim3 t1(256);
    const __half* qs  = qkv;
    const __half* ksp = qkv + (size_t)BN * DS;

    // 0) fused weight prep + accumulator zero (single launch)
    prep_all<<<(7077120 + 255) / 256, t1>>>(Wq, Wk, Wv, Wo, W1, W2);

    // 1) LN1
    ln_kernel<<<BN, t1>>>(x, 769, 1, gamma1, beta1, h1s, h1t);

    // 2) QKV — batched, fused per-head |v|^2 (EPI6)
    mma_gemm<6, 2, true, 128><<<dim3(6, 64, 3), t1, SMB128>>>(
        h1s, 768, 0, wqkv, 768, (size_t)768 * 768, qkv, 768, 0, (size_t)BN * DS,
        nullptr, 0, 0, h1t, 0, wqkvt, 768, hts, nullptr, 768, 768);
    head_time2<<<(BH * N + 255) / 256, t1>>>();
    vT_kernel<<<dim3(32, 24, 8), dim3(32, 8)>>>();

    // 3) E=exp(logits) + fused rowsum/time-dot; av + normalize + concat (EPI5)
    mma_gemm<3, 1, false, 128><<<dim3(8, 8, BH), t1, SMB128>>>(
        ksp, 768, 0, qs, 768, 0, lt, N, 0, (size_t)N * N,
        vT, 80 * N, 0, kt, 0, qt, 0, rsE, st, N, HD);
    mma_gemm<5, 2, false, 64><<<dim3(1, 8, BH), t1, SMB64>>>(
        lt, N, (size_t)N * N, vT + N, N, (size_t)80 * N, atns, 0, 0, 0,
        nullptr, 0, 0, rsE, N, nullptr, 0, cts, st, 64, N);
    atnt_kernel<<<(BN + 255) / 256, t1>>>();

    // 5) Wo + residual(x)
    mma_gemm<2, 0, true, 128><<<dim3(6, 64), t1, SMB128>>>(
        atns, 768, 0, wos, 768, 0, out1, 768, 0, 0,
        x, 769, 1, atnt, 0, wot, 0, nullptr, nullptr, 768, 768);

    // 6) LN2
    ln_kernel<<<BN, t1>>>(out1, 768, 0, gamma2, beta2, zs, zt);

    // 7) FFN up (fast gelu + fused |v|^2), then hidt
    mma_gemm<1, 0, true, 128><<<dim3(24, 64), t1, SMB128>>>(
        zs, 768, 0, w1s, 768, 0, hid, M_, 0, 0,
        nullptr, 0, 0, zt, 0, w1t, 0, hsq, nullptr, 3071, 768);
    hidt_kernel<<<(BN + 255) / 256, t1>>>();

    // 8) FFN down + residual(out1) -> d_out space cols
    mma_gemm<2, 0, true, 128><<<dim3(6, 64), t1, SMB128>>>(
        hid, M_, 0, w2s, M_, 0, out, 769, 1, 0,
        out1, 768, 0, hidt, 0, w2t, 0, nullptr, nullptr, 768, M_);

    // 9) final add_time
    final_time_kernel<<<BN, t1>>>(out);
}

// round 16
// speedup vs baseline: 3.4718x; 1.0159x over previous
#include <cuda_runtime.h>
#include <cuda_fp16.h>
#include <math.h>
#include <stdint.h>

// ---------------------------------------------------------------------------
// LorentzTransformerEncoder  (B=8, N=1024, D=769, H=12, hd=64, M=3072)
// R16 = R15 + fused flash-style attention kernel (logits + softmax sums + av
//       + hyperboloid normalize + concat in ONE kernel; E never hits DRAM).
// ---------------------------------------------------------------------------

constexpr int B  = 8;
constexpr int N  = 1024;
constexpr int DS = 768;
constexpr int H  = 12;
constexpr int M_ = 3072;
constexpr int BN = B * N;   // 8192
constexpr int BH = B * H;   // 96

// ------------------------------- scratch -----------------------------------
__device__ __half g_h1s [(size_t)BN * DS];
__device__ float  g_h1t [BN];
__device__ __half g_qkv [(size_t)3 * BN * DS];
__device__ float  g_qt  [BH * N];
__device__ float  g_kt  [BH * N];
__device__ __half g_vT  [(size_t)BH * 80 * N];  // row 0 time, rows 1..64 space^T
__device__ float  g_hts [3 * BH * N];
__device__ float  g_cts [BN];
__device__ __half g_atns[(size_t)BN * DS];
__device__ float  g_atnt[BN];
__device__ float  g_out1[(size_t)BN * DS];
__device__ __half g_zs  [(size_t)BN * DS];
__device__ float  g_zt  [BN];
__device__ __half g_hid [(size_t)BN * M_];      // col 3071 stays 0
__device__ float  g_hsq [BN];
__device__ float  g_hidt[BN];
// fp16 weights (space part, k-major, aligned) + fp32 time columns
__device__ __half g_wqkv [(size_t)3 * 768 * 768];
__device__ float  g_wqkvt[3 * 768];
__device__ __half g_wos [768 * 768];  __device__ float g_wot [768];
__device__ __half g_w1s [3071 * 768]; __device__ float g_w1t [3071];
__device__ __half g_w2s [768 * 3072]; __device__ float g_w2t [768];

// ----------------------------- helpers --------------------------------------
__device__ __forceinline__ void ldsm4(uint32_t& r0, uint32_t& r1, uint32_t& r2,
                                      uint32_t& r3, uint32_t addr) {
    asm volatile("ldmatrix.sync.aligned.m8n8.x4.shared.b16 {%0,%1,%2,%3},[%4];"
                 : "=r"(r0), "=r"(r1), "=r"(r2), "=r"(r3) : "r"(addr));
}
__device__ __forceinline__ void mma_f16(float* c, const uint32_t* a, const uint32_t* b) {
    asm volatile("mma.sync.aligned.m16n8k16.row.col.f32.f16.f16.f32 "
                 "{%0,%1,%2,%3},{%4,%5,%6,%7},{%8,%9},{%0,%1,%2,%3};"
                 : "+f"(c[0]), "+f"(c[1]), "+f"(c[2]), "+f"(c[3])
                 : "r"(a[0]), "r"(a[1]), "r"(a[2]), "r"(a[3]), "r"(b[0]), "r"(b[1]));
}
#define CP16(d, s) \
    asm volatile("cp.async.cg.shared.global [%0],[%1],16;" :: "r"(d), "l"(s))
#define CP_COMMIT() asm volatile("cp.async.commit_group;" ::: "memory")
#define CP_WAIT2()  asm volatile("cp.async.wait_group 2;" ::: "memory")
#define CP_WAIT1()  asm volatile("cp.async.wait_group 1;" ::: "memory")

__device__ __forceinline__ float fast_tanh(float a) {
    float e2 = __expf(2.f * a);
    return __fdividef(e2 - 1.f, e2 + 1.f);
}

// one pipeline stage; k0 in HALF elements (stage covers k32)
#define ISSUE_STAGE(slot, k0)                                    \
    do {                                                         \
        uint32_t sa_ = sbase + (slot) * 16384 + dOff;            \
        CP16(sa_,         aSrc  + (k0));                         \
        CP16(sa_ + 4096,  aSrc2 + (k0));                         \
        CP16(sa_ + 8192,  bSrc1 + (k0));                         \
        CP16(sa_ + 12288, bSrc2 + (k0));                         \
        CP_COMMIT();                                             \
    } while (0)

__device__ __forceinline__ float block_reduce_sum(float v, float* sh) {
    int tid = threadIdx.x, lane = tid & 31, wid = tid >> 5;
    #pragma unroll
    for (int o = 16; o > 0; o >>= 1) v += __shfl_down_sync(0xffffffffu, v, o);
    __syncthreads();
    if (lane == 0) sh[wid] = v;
    __syncthreads();
    if (tid == 0) {
        float s = 0.f;
        #pragma unroll
        for (int w = 0; w < 8; w++) s += sh[w];
        sh[32] = s;
    }
    __syncthreads();
    return sh[32];
}

// -------- fused prep: all weights (fp16 + time split) + accumulator zero ----
__global__ void prep_all(const float* __restrict__ Wq, const float* __restrict__ Wk,
                         const float* __restrict__ Wv, const float* __restrict__ Wo,
                         const float* __restrict__ W1, const float* __restrict__ W2) {
    int idx = blockIdx.x * 256 + threadIdx.x;
    if (idx < 3 * BH * N) g_hts[idx] = 0.f;
    if (idx < BN) { g_hsq[idx] = 0.f; g_cts[idx] = 0.f; }

    if (idx < 1769472) {
        int which = idx / 589824;
        int rem = idx - which * 589824;
        int n = rem / 768, k = rem - n * 768;
        const float* W = (which == 0) ? Wq : (which == 1) ? Wk : Wv;
        g_wqkv[idx] = __float2half_rn(W[(size_t)(n + 1) * 769 + k + 1]);
        if (k == 0) g_wqkvt[which * 768 + n] = W[(size_t)(n + 1) * 769];
    } else if (idx < 2359296) {
        int rem = idx - 1769472;
        int n = rem / 768, k = rem - n * 768;
        g_wos[rem] = __float2half_rn(Wo[(size_t)(n + 1) * 769 + k + 1]);
        if (k == 0) g_wot[n] = Wo[(size_t)(n + 1) * 769];
    } else if (idx < 4717824) {
        int rem = idx - 2359296;
        int n = rem / 768, k = rem - n * 768;
        g_w1s[rem] = __float2half_rn(W1[(size_t)(n + 1) * 769 + k + 1]);
        if (k == 0) g_w1t[n] = W1[(size_t)(n + 1) * 769];
    } else if (idx < 7077120) {
        int rem = idx - 4717824;
        int n = rem / 3072, k = rem - n * 3072;
        float v = (k < 3071) ? W2[(size_t)(n + 1) * 3072 + k + 1] : 0.f;
        g_w2s[rem] = __float2half_rn(v);
        if (k == 0) g_w2t[n] = W2[(size_t)(n + 1) * 3072];
    }
}

// ------------------------- Lorentz layernorm --------------------------------
__global__ void ln_kernel(const float* __restrict__ X, int ldx, int xofs,
                          const float* __restrict__ gamma,
                          const float* __restrict__ beta,
                          __half* __restrict__ Ys, float* __restrict__ Yt) {
    __shared__ float sh[33];
    int bn = blockIdx.x, tid = threadIdx.x;
    const float* x = X + (size_t)bn * ldx + xofs;
    float v[3], s = 0.f;
    #pragma unroll
    for (int i = 0; i < 3; i++) { v[i] = x[tid + i * 256]; s += v[i]; }
    s = block_reduce_sum(s, sh);
    float mu = s * (1.f / 768.f);
    float s2 = 0.f;
    #pragma unroll
    for (int i = 0; i < 3; i++) { float dd = v[i] - mu; s2 += dd * dd; }
    s2 = block_reduce_sum(s2, sh);
    float rstd = rsqrtf(s2 * (1.f / 768.f) + 1e-5f);
    float t2 = 0.f;
    __half* ys = Ys + (size_t)bn * DS;
    #pragma unroll
    for (int i = 0; i < 3; i++) {
        int d = tid + i * 256;
        float yy = gamma[d] * (v[i] - mu) * rstd + beta[d];
        ys[d] = __float2half_rn(yy);
        t2 += yy * yy;
    }
    t2 = block_reduce_sum(t2, sh);
    if (tid == 0) Yt[bn] = sqrtf(1.f + t2);
}

// ------------------------------- fp16 GEMM ----------------------------------
// EPI: 1 gelu(+hsq, half C), 2 +R (float C), 6 qkv(+per-head |v|^2, half C)
template<int EPI, int BM, int NTAIL>
__global__ void __launch_bounds__(256, 2)
mma_gemm(const __half* __restrict__ A, int lda, size_t aBatch,
         const __half* __restrict__ Bw, int ldb, size_t bBatch,
         void* __restrict__ Cv, int ldc, int cofs, size_t cBatch,
         const float* __restrict__ R, int ldr, int rofs,
         const float* __restrict__ tA, size_t tABat,
         const float* __restrict__ tB, size_t tBBat,
         float* __restrict__ pS1,
         int Nn, int Kk) {
    extern __shared__ float dsm[];
    uint32_t sbase = (uint32_t)__cvta_generic_to_shared(dsm);

    int tid = threadIdx.x;
    int lane = tid & 31, wid = tid >> 5;
    int warpm = wid >> 2, warpn = wid & 3;
    int bm = blockIdx.y << 7, bnb = blockIdx.x << 7;

    const __half* Ab = A;
    const __half* Bb = Bw;
    const float* tAp = tA;
    const float* tBp = tB;
    char* Cp = (char*)Cv;
    if (BM == 2) {
        int bz = blockIdx.z;
        Ab += (size_t)bz * aBatch;
        Bb += (size_t)bz * bBatch;
        Cp += (size_t)bz * cBatch * ((EPI == 2) ? 4 : 2);
        tAp = tA + (size_t)bz * tABat;
        tBp = tB + (size_t)bz * tBBat;
    }

    int lrow = tid >> 2, lch = tid & 3;
    uint32_t dOff = lrow * 64 + ((lch ^ ((lrow >> 1) & 3)) << 4);
    const __half* aSrc  = Ab + (size_t)(bm + lrow) * lda + lch * 8;
    const __half* aSrc2 = aSrc + (size_t)64 * lda;
    int brow1 = bnb + lrow, brow2 = brow1 + 64;
    int cb1 = (brow1 < Nn) ? brow1 : Nn - 1;
    int cb2 = (brow2 < Nn) ? brow2 : Nn - 1;
    const __half* bSrc1 = Bb + (size_t)cb1 * ldb + lch * 8;
    const __half* bSrc2 = Bb + (size_t)cb2 * ldb + lch * 8;

    int lrowA = (lane & 7) + ((lane >> 3) & 1) * 8;
    int hiA   = lane >> 4;
    int swA   = (lrowA >> 1) & 3;
    int lrowB = (lane & 7) + ((lane >> 4) & 1) * 8;
    int hiB   = (lane >> 3) & 1;
    int swB   = (lrowB >> 1) & 3;
    uint32_t aOff[2], bOff[2];
    #pragma unroll
    for (int ks = 0; ks < 2; ks++) {
        aOff[ks] = (warpm * 64 + lrowA) * 64 + (((2 * ks + hiA) ^ swA) << 4);
        bOff[ks] = 8192 + (warpn * 32 + lrowB) * 64 + (((2 * ks + hiB) ^ swB) << 4);
    }

    float acc[4][4][4];
    #pragma unroll
    for (int i = 0; i < 4; i++)
        #pragma unroll
        for (int j = 0; j < 4; j++)
            #pragma unroll
            for (int r = 0; r < 4; r++) acc[i][j][r] = 0.f;

    int KT = Kk >> 5;

    ISSUE_STAGE(0, 0);
    ISSUE_STAGE(1, 32);
    ISSUE_STAGE(2, 64);

    for (int kt = 0; kt < KT; kt++) {
        CP_WAIT2();
        __syncthreads();
        int st = kt & 3;
        uint32_t sb = sbase + st * 16384;
        #pragma unroll
        for (int ks = 0; ks < 2; ks++) {
            uint32_t af[4][4];
            uint32_t bf[4][2];
            #pragma unroll
            for (int mt = 0; mt < 4; mt++)
                ldsm4(af[mt][0], af[mt][1], af[mt][2], af[mt][3],
                      sb + aOff[ks] + mt * 1024);
            #pragma unroll
            for (int np = 0; np < 2; np++)
                ldsm4(bf[2 * np][0], bf[2 * np][1], bf[2 * np + 1][0], bf[2 * np + 1][1],
                      sb + bOff[ks] + np * 1024);
            #pragma unroll
            for (int mt = 0; mt < 4; mt++)
                #pragma unroll
                for (int nt = 0; nt < 4; nt++)
                    mma_f16(acc[mt][nt], af[mt], bf[nt]);
        }
        int nk = kt + 3;
        if (nk < KT) { ISSUE_STAGE(nk & 3, nk << 5); }
        else CP_COMMIT();
    }

    // ------------------------------ epilogue --------------------------------
    int er = bm + warpm * 64 + (lane >> 2);
    int ec0 = bnb + warpn * 32 + 2 * (lane & 3);
    float sumQ[4][2];
    if (EPI == 1 || EPI == 6) {
        #pragma unroll
        for (int i = 0; i < 4; i++)
            #pragma unroll
            for (int j = 0; j < 2; j++) sumQ[i][j] = 0.f;
    }
    #pragma unroll
    for (int mt = 0; mt < 4; mt++) {
        #pragma unroll
        for (int nt = 0; nt < 4; nt++) {
            #pragma unroll
            for (int half_ = 0; half_ < 2; half_++) {
                int r = er + mt * 16 + half_ * 8;
                int c = ec0 + nt * 8;
                bool ok0 = !NTAIL || c < Nn;
                bool ok1 = !NTAIL || (c + 1) < Nn;
                float v0 = acc[mt][nt][2 * half_];
                float v1 = acc[mt][nt][2 * half_ + 1];
                float ta = tAp[r];
                if (ok0) v0 += ta * tBp[c];
                if (ok1) v1 += ta * tBp[c + 1];
                if (EPI == 1) {
                    float t0 = fast_tanh(0.7978845608028654f * (v0 + 0.044715f * v0 * v0 * v0));
                    v0 = 0.5f * v0 * (1.f + t0);
                    float t1 = fast_tanh(0.7978845608028654f * (v1 + 0.044715f * v1 * v1 * v1));
                    v1 = 0.5f * v1 * (1.f + t1);
                    if (ok0) sumQ[mt][half_] = fmaf(v0, v0, sumQ[mt][half_]);
                    if (ok1) sumQ[mt][half_] = fmaf(v1, v1, sumQ[mt][half_]);
                    __half* cph = (__half*)Cp + (size_t)r * ldc + cofs;
                    if (ok0) cph[c] = __float2half_rn(v0);
                    if (ok1) cph[c + 1] = __float2half_rn(v1);
                }
                if (EPI == 2) {
                    const float* rp = R + (size_t)r * ldr + rofs;
                    v0 += rp[c];
                    v1 += rp[c + 1];
                    float* cpf = (float*)Cp + (size_t)r * ldc + cofs;
                    cpf[c] = v0;
                    cpf[c + 1] = v1;
                }
                if (EPI == 6) {
                    __half h0 = __float2half_rn(v0), h1 = __float2half_rn(v1);
                    float r0 = __half2float(h0), r1 = __half2float(h1);
                    sumQ[mt][half_] = fmaf(r0, r0, fmaf(r1, r1, sumQ[mt][half_]));
                    __half* cph = (__half*)Cp + (size_t)r * ldc + cofs;
                    *(__half2*)(cph + c) = __halves2half2(h0, h1);
                }
            }
        }
    }
    if (EPI == 1) {
        #pragma unroll
        for (int mt = 0; mt < 4; mt++)
            #pragma unroll
            for (int half_ = 0; half_ < 2; half_++) {
                float vQ = sumQ[mt][half_];
                vQ += __shfl_down_sync(0xffffffffu, vQ, 1, 4);
                vQ += __shfl_down_sync(0xffffffffu, vQ, 2, 4);
                if ((lane & 3) == 0) {
                    int r = er + mt * 16 + half_ * 8;
                    atomicAdd(&pS1[r], vQ);
                }
            }
    }
    if (EPI == 6) {
        int ghead = (bnb + warpn * 32) >> 6;
        float* hp = pS1 + (size_t)blockIdx.z * ((size_t)BH * N);
        #pragma unroll
        for (int mt = 0; mt < 4; mt++)
            #pragma unroll
            for (int half_ = 0; half_ < 2; half_++) {
                float vQ = sumQ[mt][half_];
                vQ += __shfl_down_sync(0xffffffffu, vQ, 1, 4);
                vQ += __shfl_down_sync(0xffffffffu, vQ, 2, 4);
                if ((lane & 3) == 0) {
                    int r = er + mt * 16 + half_ * 8;
                    int b_ = r >> 10, j_ = r & 1023;
                    atomicAdd(&hp[((size_t)b_ * H + ghead) * N + j_], vQ);
                }
            }
    }
}

// --------------------- fused flash-style attention ---------------------------
// grid (8 j-tiles, BH).  smem layout (bytes):
//   K tile:   0      + kb*8192        (2 x 8KB,  128 rows x k32)
//   Q bufs:   16384  + buf*16384 + kb*8192
//   vT bufs:  49152  + buf*16384 + ib*4096   (64 rows x k32 per block)
//   E tiles:  81920  + ib*8192        (4 x 8KB)     [reused as float red arrays]
__global__ void __launch_bounds__(256, 1) fused_attn() {
    extern __shared__ char fsm[];
    uint32_t sbase = (uint32_t)__cvta_generic_to_shared(fsm);
    int tid = threadIdx.x;
    int lane = tid & 31, wid = tid >> 5;
    int warpm = wid >> 2, warpn = wid & 3;
    int bh = blockIdx.y, b = bh / H, h = bh % H;
    int j0 = blockIdx.x << 7;

    const __half* Kg = g_qkv + (size_t)BN * DS;   // ksp
    const __half* Qg = g_qkv;
    const float* ktp = g_kt + (size_t)bh * N + j0;
    const float* qtp0 = g_qt + (size_t)bh * N;
    const __half* vtp0 = g_vT + (size_t)bh * 80 * N;   // row 0 = times

    int lrow = tid >> 2, lch = tid & 3;
    uint32_t dOff = lrow * 64 + ((lch ^ ((lrow >> 1) & 3)) << 4);

    // --- issue K (once) + Q/vT for iter 0 as group 0 ---
    #pragma unroll
    for (int kb = 0; kb < 2; kb++) {
        const __half* ks_ = Kg + (size_t)(b * N + j0 + lrow) * 768 + h * 64 + kb * 32 + lch * 8;
        CP16(sbase + kb * 8192 + dOff, ks_);
        CP16(sbase + kb * 8192 + dOff + 4096, ks_ + (size_t)64 * 768);
    }
    #define ISSUE_QV(buf, i0_)                                                        \
        do {                                                                          \
            uint32_t qb_ = sbase + 16384 + (buf) * 16384;                             \
            uint32_t vb_ = sbase + 49152 + (buf) * 16384;                             \
            _Pragma("unroll")                                                         \
            for (int kb = 0; kb < 2; kb++) {                                          \
                const __half* qsrc = Qg + (size_t)(b * N + (i0_) + lrow) * 768        \
                                     + h * 64 + kb * 32 + lch * 8;                    \
                CP16(qb_ + kb * 8192 + dOff, qsrc);                                   \
                CP16(qb_ + kb * 8192 + dOff + 4096, qsrc + (size_t)64 * 768);         \
            }                                                                         \
            _Pragma("unroll")                                                         \
            for (int ib = 0; ib < 4; ib++) {                                          \
                const __half* vsrc = vtp0 + (size_t)(1 + lrow) * N + (i0_)            \
                                     + ib * 32 + lch * 8;                             \
                CP16(vb_ + ib * 4096 + dOff, vsrc);                                   \
            }                                                                         \
            CP_COMMIT();                                                              \
        } while (0)
    ISSUE_QV(0, 0);        // completes group 0 (with K)
    ISSUE_QV(1, 128);      // group 1

    // --- fragment addressing ---
    int lrowA = (lane & 7) + ((lane >> 3) & 1) * 8;
    int hiA   = lane >> 4;
    int swA   = (lrowA >> 1) & 3;
    int lrowB = (lane & 7) + ((lane >> 4) & 1) * 8;
    int hiB   = (lane >> 3) & 1;
    int swB   = (lrowB >> 1) & 3;
    uint32_t aOff[2], bOffQ[2], bOffV[2];
    #pragma unroll
    for (int ks = 0; ks < 2; ks++) {
        aOff[ks]  = (warpm * 64 + lrowA) * 64 + (((2 * ks + hiA) ^ swA) << 4);
        bOffQ[ks] = (warpn * 32 + lrowB) * 64 + (((2 * ks + hiB) ^ swB) << 4);
        bOffV[ks] = (warpn * 16 + lrowB) * 64 + (((2 * ks + hiB) ^ swB) << 4);
    }

    float Oacc[4][2][4];
    #pragma unroll
    for (int i = 0; i < 4; i++)
        #pragma unroll
        for (int j = 0; j < 2; j++)
            #pragma unroll
            for (int r = 0; r < 4; r++) Oacc[i][j][r] = 0.f;
    float sumE[4][2], sumT[4][2];
    #pragma unroll
    for (int i = 0; i < 4; i++)
        #pragma unroll
        for (int j = 0; j < 2; j++) { sumE[i][j] = 0.f; sumT[i][j] = 0.f; }

    int rloc = warpm * 64 + (lane >> 2);
    int cloc = warpn * 32 + 2 * (lane & 3);
    int rsw = 0;   // placeholder

    for (int it = 0; it < 8; it++) {
        int i0 = it << 7;
        CP_WAIT1();
        __syncthreads();
        uint32_t qb = sbase + 16384 + (it & 1) * 16384;
        uint32_t vb = sbase + 49152 + (it & 1) * 16384;

        // ---- stage 1: E = K @ Q^T  (K=64) ----
        float Eacc[4][4][4];
        #pragma unroll
        for (int i = 0; i < 4; i++)
            #pragma unroll
            for (int j = 0; j < 4; j++)
                #pragma unroll
                for (int r = 0; r < 4; r++) Eacc[i][j][r] = 0.f;
        #pragma unroll
        for (int kb = 0; kb < 2; kb++) {
            #pragma unroll
            for (int ks = 0; ks < 2; ks++) {
                uint32_t af[4][4];
                uint32_t bf[4][2];
                #pragma unroll
                for (int mt = 0; mt < 4; mt++)
                    ldsm4(af[mt][0], af[mt][1], af[mt][2], af[mt][3],
                          sbase + kb * 8192 + aOff[ks] + mt * 1024);
                #pragma unroll
                for (int np = 0; np < 2; np++)
                    ldsm4(bf[2 * np][0], bf[2 * np][1], bf[2 * np + 1][0], bf[2 * np + 1][1],
                          qb + kb * 8192 + bOffQ[ks] + np * 1024);
                #pragma unroll
                for (int mt = 0; mt < 4; mt++)
                    #pragma unroll
                    for (int nt = 0; nt < 4; nt++)
                        mma_f16(Eacc[mt][nt], af[mt], bf[nt]);
            }
        }

        // ---- logit epilogue: e = exp(1/(1+log(1+d2))), write E-smem ----
        const float* qtp = qtp0 + i0;
        const __half* vtp = vtp0 + i0;
        #pragma unroll
        for (int mt = 0; mt < 4; mt++) {
            #pragma unroll
            for (int half_ = 0; half_ < 2; half_++) {
                int r = rloc + mt * 16 + half_ * 8;
                float kt_ = ktp[r];
                int rx = (r >> 1) & 3;
                #pragma unroll
                for (int nt = 0; nt < 4; nt++) {
                    int c = cloc + nt * 8;
                    float d20 = fmaxf(2.f * (kt_ * qtp[c] - Eacc[mt][nt][2 * half_] - 1.f), 1e-8f);
                    float d21 = fmaxf(2.f * (kt_ * qtp[c + 1] - Eacc[mt][nt][2 * half_ + 1] - 1.f), 1e-8f);
                    __half h0 = __float2half_rn(__expf(__fdividef(1.f, 1.f + __logf(1.f + d20))));
                    __half h1 = __float2half_rn(__expf(__fdividef(1.f, 1.f + __logf(1.f + d21))));
                    float e0 = __half2float(h0), e1 = __half2float(h1);
                    sumE[mt][half_] += e0 + e1;
                    sumT[mt][half_] = fmaf(e0, __half2float(vtp[c]), sumT[mt][half_]);
                    sumT[mt][half_] = fmaf(e1, __half2float(vtp[c + 1]), sumT[mt][half_]);
                    int ib = c >> 5, cc = c & 31;
                    uint32_t eaddr = sbase + 81920 + ib * 8192 + r * 64
                                   + ((((cc >> 3) ^ rx)) << 4) + (cc & 7) * 2;
                    *(__half2*)(fsm + (eaddr - sbase)) = __halves2half2(h0, h1);
                }
            }
        }
        __syncthreads();

        // ---- stage 2: O += E @ vT^T  (K = 128 i-values) ----
        #pragma unroll
        for (int ib = 0; ib < 4; ib++) {
            #pragma unroll
            for (int ks = 0; ks < 2; ks++) {
                uint32_t af[4][4];
                uint32_t bf[2][2];
                #pragma unroll
                for (int mt = 0; mt < 4; mt++)
                    ldsm4(af[mt][0], af[mt][1], af[mt][2], af[mt][3],
                          sbase + 81920 + ib * 8192 + aOff[ks] + mt * 1024);
                ldsm4(bf[0][0], bf[0][1], bf[1][0], bf[1][1],
                      vb + ib * 4096 + bOffV[ks]);
                #pragma unroll
                for (int mt = 0; mt < 4; mt++)
                    #pragma unroll
                    for (int nt = 0; nt < 2; nt++)
                        mma_f16(Oacc[mt][nt], af[mt], bf[nt]);
            }
        }
        __syncthreads();

        if (it + 2 < 8) { ISSUE_QV(it & 1, (it + 2) << 7); }
        else CP_COMMIT();
    }
    (void)rsw;

    // ---- final: CTA-local softmax sums -> normalize -> concat write ----
    float* red = (float*)(fsm + 81920);   // [0..127] sumE, [128..255] sumT, [256..383] ss
    if (tid < 128) { red[tid] = 0.f; red[128 + tid] = 0.f; red[256 + tid] = 0.f; }
    __syncthreads();
    #pragma unroll
    for (int mt = 0; mt < 4; mt++)
        #pragma unroll
        for (int half_ = 0; half_ < 2; half_++) {
            float vE = sumE[mt][half_], vT = sumT[mt][half_];
            vE += __shfl_down_sync(0xffffffffu, vE, 1, 4);
            vE += __shfl_down_sync(0xffffffffu, vE, 2, 4);
            vT += __shfl_down_sync(0xffffffffu, vT, 1, 4);
            vT += __shfl_down_sync(0xffffffffu, vT, 2, 4);
            if ((lane & 3) == 0) {
                int r = rloc + mt * 16 + half_ * 8;
                atomicAdd(&red[r], vE);
                atomicAdd(&red[128 + r], vT);
            }
        }
    __syncthreads();
    #pragma unroll
    for (int mt = 0; mt < 4; mt++)
        #pragma unroll
        for (int half_ = 0; half_ < 2; half_++) {
            int r = rloc + mt * 16 + half_ * 8;
            float sc = __fdividef(1.f, red[r]);
            float ss = 0.f;
            #pragma unroll
            for (int nt = 0; nt < 2; nt++) {
                float v0 = Oacc[mt][nt][2 * half_] * sc;
                float v1 = Oacc[mt][nt][2 * half_ + 1] * sc;
                Oacc[mt][nt][2 * half_] = v0;
                Oacc[mt][nt][2 * half_ + 1] = v1;
                ss = fmaf(v0, v0, fmaf(v1, v1, ss));
            }
            ss += __shfl_down_sync(0xffffffffu, ss, 1, 4);
            ss += __shfl_down_sync(0xffffffffu, ss, 2, 4);
            if ((lane & 3) == 0) atomicAdd(&red[256 + r], ss);
        }
    __syncthreads();
    int c2base = warpn * 16 + 2 * (lane & 3);
    #pragma unroll
    for (int mt = 0; mt < 4; mt++)
        #pragma unroll
        for (int half_ = 0; half_ < 2; half_++) {
            int r = rloc + mt * 16 + half_ * 8;
            float sc = __fdividef(1.f, red[r]);
            float stt = red[128 + r] * sc;
            float inv = rsqrtf(fmaxf(stt * stt - red[256 + r], 1e-8f));
            __half* op = g_atns + (size_t)(b * N + j0 + r) * 768 + h * 64;
            #pragma unroll
            for (int nt = 0; nt < 2; nt++) {
                int c = c2base + nt * 8;
                *(__half2*)(op + c) = __halves2half2(
                    __float2half_rn(Oacc[mt][nt][2 * half_] * inv),
                    __float2half_rn(Oacc[mt][nt][2 * half_ + 1] * inv));
            }
            if (warpn == 0 && (lane & 3) == 0) {
                float ct = stt * inv;
                atomicAdd(&g_cts[b * N + j0 + r], ct * ct);
            }
        }
}

// ---- finish per-head times from accumulated |v|^2 --------------------------
__global__ void head_time2() {
    int idx = blockIdx.x * 256 + threadIdx.x;
    if (idx >= BH * N) return;
    g_qt[idx] = sqrtf(1.f + g_hts[idx]);
    g_kt[idx] = sqrtf(1.f + g_hts[BH * N + idx]);
    int bh = idx >> 10, i = idx & 1023;
    g_vT[(size_t)bh * 80 * N + i] = __float2half_rn(sqrtf(1.f + g_hts[2 * BH * N + idx]));
}

// ------------------ V transpose to [bh][80][N] (rows 1..64) -----------------
__global__ void vT_kernel() {
    __shared__ float tile[32][33];
    int i0 = blockIdx.x << 5, d0 = blockIdx.y << 5, b = blockIdx.z;
    int tx = threadIdx.x, ty = threadIdx.y;
    const __half* vsp = g_qkv + (size_t)2 * BN * DS;
    #pragma unroll
    for (int r = 0; r < 4; r++)
        tile[ty + 8 * r][tx] = __half2float(vsp[(size_t)(b * N + i0 + ty + 8 * r) * DS + d0 + tx]);
    __syncthreads();
    #pragma unroll
    for (int r = 0; r < 4; r++) {
        int dg = d0 + ty + 8 * r;
        int h = dg >> 6, dd = dg & 63;
        g_vT[((size_t)(b * H + h) * 80 + 1 + dd) * N + i0 + tx] =
            __float2half_rn(tile[tx][ty + 8 * r]);
    }
}

// ----------------------- small finishers ------------------------------------
__global__ void hidt_kernel() {
    int idx = blockIdx.x * 256 + threadIdx.x;
    if (idx < BN) g_hidt[idx] = sqrtf(1.f + g_hsq[idx]);
}
__global__ void atnt_kernel() {
    int idx = blockIdx.x * 256 + threadIdx.x;
    if (idx < BN) g_atnt[idx] = sqrtf(g_cts[idx] - 11.f);
}

// --------------------------- final add_time ---------------------------------
__global__ void final_time_kernel(float* __restrict__ out) {
    __shared__ float sh[33];
    int bn = blockIdx.x, tid = threadIdx.x;
    float* p = out + (size_t)bn * 769;
    float s = 0.f;
    #pragma unroll
    for (int r = 0; r < 3; r++) {
        float v = p[1 + tid + r * 256];
        s = fmaf(v, v, s);
    }
    s = block_reduce_sum(s, sh);
    if (tid == 0) p[0] = sqrtf(1.f + s);
}

// ----------------------------------------------------------------------------
extern "C" void kernel_launch(void* const* d_in, const int* in_sizes, int n_in,
                              void* d_out, int out_size) {
    const float* x      = (const float*)d_in[0];
    const float* gamma1 = (const float*)d_in[1];
    const float* beta1  = (const float*)d_in[2];
    const float* Wq     = (const float*)d_in[3];
    const float* Wk     = (const float*)d_in[4];
    const float* Wv     = (const float*)d_in[5];
    const float* Wo     = (const float*)d_in[6];
    const float* gamma2 = (const float*)d_in[7];
    const float* beta2  = (const float*)d_in[8];
    const float* W1     = (const float*)d_in[9];
    const float* W2     = (const float*)d_in[10];
    float* out = (float*)d_out;

    __half *h1s, *qkv, *atns, *zs, *hid, *wqkv, *wos, *w1s, *w2s;
    float *h1t, *hts, *atnt, *out1, *zt, *hsq, *hidt;
    float *wqkvt, *wot, *w1t, *w2t;
    cudaGetSymbolAddress((void**)&h1s,  g_h1s);  cudaGetSymbolAddress((void**)&h1t,  g_h1t);
    cudaGetSymbolAddress((void**)&qkv,  g_qkv);
    cudaGetSymbolAddress((void**)&hts,  g_hts);
    cudaGetSymbolAddress((void**)&atns, g_atns); cudaGetSymbolAddress((void**)&atnt, g_atnt);
    cudaGetSymbolAddress((void**)&out1, g_out1);
    cudaGetSymbolAddress((void**)&zs,   g_zs);   cudaGetSymbolAddress((void**)&zt,   g_zt);
    cudaGetSymbolAddress((void**)&hid,  g_hid);  cudaGetSymbolAddress((void**)&hsq,  g_hsq);
    cudaGetSymbolAddress((void**)&hidt, g_hidt);
    cudaGetSymbolAddress((void**)&wqkv, g_wqkv); cudaGetSymbolAddress((void**)&wqkvt, g_wqkvt);
    cudaGetSymbolAddress((void**)&wos,  g_wos);  cudaGetSymbolAddress((void**)&wot,  g_wot);
    cudaGetSymbolAddress((void**)&w1s,  g_w1s);  cudaGetSymbolAddress((void**)&w1t,  g_w1t);
    cudaGetSymbolAddress((void**)&w2s,  g_w2s);  cudaGetSymbolAddress((void**)&w2t,  g_w2t);

    constexpr int SMB = 65536;
    constexpr int SMF = 114688;   // fused attention
    cudaFuncSetAttribute(mma_gemm<6, 2, 0>, cudaFuncAttributeMaxDynamicSharedMemorySize, SMB);
    cudaFuncSetAttribute(mma_gemm<2, 0, 0>, cudaFuncAttributeMaxDynamicSharedMemorySize, SMB);
    cudaFuncSetAttribute(mma_gemm<1, 0, 1>, cudaFuncAttributeMaxDynamicSharedMemorySize, SMB);
    cudaFuncSetAttribute(fused_attn, cudaFuncAttributeMaxDynamicSharedMemorySize, SMF);

    dim3 t1(256);

    // 0) fused weight prep + accumulator zero
    prep_all<<<(7077120 + 255) / 256, t1>>>(Wq, Wk, Wv, Wo, W1, W2);

    // 1) LN1
    ln_kernel<<<BN, t1>>>(x, 769, 1, gamma1, beta1, h1s, h1t);

    // 2) QKV — batched, fused per-head |v|^2
    mma_gemm<6, 2, 0><<<dim3(6, 64, 3), t1, SMB>>>(
        h1s, 768, 0, wqkv, 768, (size_t)768 * 768, qkv, 768, 0, (size_t)BN * DS,
        nullptr, 0, 0, h1t, 0, wqkvt, 768, hts, 768, 768);
    head_time2<<<(BH * N + 255) / 256, t1>>>();
    vT_kernel<<<dim3(32, 24, 8), dim3(32, 8)>>>();

    // 3) fused attention (logits + sums + av + normalize + concat)
    fused_attn<<<dim3(8, BH), t1, SMF>>>();
    atnt_kernel<<<(BN + 255) / 256, t1>>>();

    // 5) Wo + residual(x)
    mma_gemm<2, 0, 0><<<dim3(6, 64), t1, SMB>>>(
        atns, 768, 0, wos, 768, 0, out1, 768, 0, 0,
        x, 769, 1, atnt, 0, wot, 0, nullptr, 768, 768);

    // 6) LN2
    ln_kernel<<<BN, t1>>>(out1, 768, 0, gamma2, beta2, zs, zt);

    // 7) FFN up (fast gelu + fused |v|^2), then hidt
    mma_gemm<1, 0, 1><<<dim3(24, 64), t1, SMB>>>(
        zs, 768, 0, w1s, 768, 0, hid, M_, 0, 0,
        nullptr, 0, 0, zt, 0, w1t, 0, hsq, 3071, 768);
    hidt_kernel<<<(BN + 255) / 256, t1>>>();

    // 8) FFN down + residual(out1) -> d_out space cols
    mma_gemm<2, 0, 0><<<dim3(6, 64), t1, SMB>>>(
        hid, M_, 0, w2s, M_, 0, out, 769, 1, 0,
        out1, 768, 0, hidt, 0, w2t, 0, nullptr, 768, M_);

    // 9) final add_time
    final_time_kernel<<<BN, t1>>>(out);
}